// round 3
// baseline (speedup 1.0000x reference)
#include <cuda_runtime.h>
#include <cuda_bf16.h>
#include <cstdint>
#include <math.h>

// Problem constants
#define BATCH 8
#define SEQ   1024
#define HID   768
#define NHEAD 12
#define DHEAD 64
#define ROWS  (BATCH*SEQ)          // 8192
#define FF    (2*HID)              // 1536
#define NQKV  (3*HID)              // 2304

// ---------------- scratch (device globals; no allocations allowed) ----------
__device__ float g_qkv[ROWS*NQKV];   // q | k | v  per row
__device__ float g_ctx[ROWS*HID];
__device__ float g_x  [ROWS*HID];
__device__ float g_ff1[ROWS*FF];
__device__ float g_ff2[ROWS*HID];
__device__ float g_bqkv[NQKV];

__device__ __nv_bfloat16 g_ah[ROWS*FF];      // split activations (reused per stage)
__device__ __nv_bfloat16 g_al[ROWS*FF];
__device__ __nv_bfloat16 g_wqkvh[NQKV*HID];  // W^T split, rows = N, K-major
__device__ __nv_bfloat16 g_wqkvl[NQKV*HID];
__device__ __nv_bfloat16 g_w1h[FF*HID];
__device__ __nv_bfloat16 g_w1l[FF*HID];
__device__ __nv_bfloat16 g_w2h[HID*FF];
__device__ __nv_bfloat16 g_w2l[HID*FF];

// ---------------- PTX helpers (sm_80-era only; no 'a'-features) -------------
__device__ __forceinline__ uint32_t smem_u32(const void* p) {
    uint32_t a;
    asm("{ .reg .u64 t; cvta.to.shared.u64 t, %1; cvt.u32.u64 %0, t; }"
        : "=r"(a) : "l"(p));
    return a;
}

__device__ __forceinline__ void cp16(uint32_t dst, const void* src) {
    asm volatile("cp.async.cg.shared.global [%0], [%1], 16;"
                 :: "r"(dst), "l"(src));
}
#define CP_COMMIT() asm volatile("cp.async.commit_group;" ::: "memory")
#define CP_WAIT(n)  asm volatile("cp.async.wait_group %0;" :: "n"(n) : "memory")

__device__ __forceinline__ void ldsm4(uint32_t& r0, uint32_t& r1,
                                      uint32_t& r2, uint32_t& r3, uint32_t addr) {
    asm volatile("ldmatrix.sync.aligned.m8n8.x4.shared.b16 {%0,%1,%2,%3}, [%4];"
                 : "=r"(r0), "=r"(r1), "=r"(r2), "=r"(r3) : "r"(addr));
}

__device__ __forceinline__ void mma_bf16(float* c, const uint32_t* a, const uint32_t* b) {
    asm volatile("mma.sync.aligned.m16n8k16.row.col.f32.bf16.bf16.f32 "
                 "{%0,%1,%2,%3}, {%4,%5,%6,%7}, {%8,%9}, {%0,%1,%2,%3};"
                 : "+f"(c[0]), "+f"(c[1]), "+f"(c[2]), "+f"(c[3])
                 : "r"(a[0]), "r"(a[1]), "r"(a[2]), "r"(a[3]),
                   "r"(b[0]), "r"(b[1]));
}

// ---------------- prep kernels ----------------------------------------------
__global__ void prep_bias(const float* __restrict__ bq, const float* __restrict__ bk,
                          const float* __restrict__ bv) {
    int i = blockIdx.x * blockDim.x + threadIdx.x;
    if (i < HID) {
        g_bqkv[i]         = bq[i];
        g_bqkv[i + HID]   = bk[i];
        g_bqkv[i + 2*HID] = bv[i];
    }
}

// W[K,N] fp32 -> out[N,K] bf16 hi/lo (transpose + split)
__global__ void __launch_bounds__(256)
transpose_split(const float* __restrict__ W, __nv_bfloat16* __restrict__ oh,
                __nv_bfloat16* __restrict__ ol, int K, int N) {
    __shared__ float t[32][33];
    const int tx = threadIdx.x, ty = threadIdx.y;
    const int n0 = blockIdx.x * 32, k0 = blockIdx.y * 32;
#pragma unroll
    for (int i = 0; i < 4; i++)
        t[ty + 8*i][tx] = W[(size_t)(k0 + ty + 8*i) * N + n0 + tx];
    __syncthreads();
#pragma unroll
    for (int i = 0; i < 4; i++) {
        float v = t[tx][ty + 8*i];
        __nv_bfloat16 h = __float2bfloat16(v);
        __nv_bfloat16 l = __float2bfloat16(v - __bfloat162float(h));
        size_t idx = (size_t)(n0 + ty + 8*i) * K + k0 + tx;
        oh[idx] = h;
        ol[idx] = l;
    }
}

// fp32 -> bf16 hi/lo elementwise split
__global__ void __launch_bounds__(256)
convert_split(const float* __restrict__ in, __nv_bfloat16* __restrict__ oh,
              __nv_bfloat16* __restrict__ ol, int n4) {
    for (int i = blockIdx.x * blockDim.x + threadIdx.x; i < n4;
         i += gridDim.x * blockDim.x) {
        float4 a = ((const float4*)in)[i];
        __nv_bfloat16 h0 = __float2bfloat16(a.x);
        __nv_bfloat16 h1 = __float2bfloat16(a.y);
        __nv_bfloat16 h2 = __float2bfloat16(a.z);
        __nv_bfloat16 h3 = __float2bfloat16(a.w);
        __nv_bfloat162 hp0; hp0.x = h0; hp0.y = h1;
        __nv_bfloat162 hp1; hp1.x = h2; hp1.y = h3;
        ((__nv_bfloat162*)oh)[2*i]   = hp0;
        ((__nv_bfloat162*)oh)[2*i+1] = hp1;
        __nv_bfloat162 lp0, lp1;
        lp0.x = __float2bfloat16(a.x - __bfloat162float(h0));
        lp0.y = __float2bfloat16(a.y - __bfloat162float(h1));
        lp1.x = __float2bfloat16(a.z - __bfloat162float(h2));
        lp1.y = __float2bfloat16(a.w - __bfloat162float(h3));
        ((__nv_bfloat162*)ol)[2*i]   = lp0;
        ((__nv_bfloat162*)ol)[2*i+1] = lp1;
    }
}

// ---------------- mma.sync bf16-split GEMM -----------------------------------
// C[M,N] = (Ah+Al)(Bh+Bl)^T + bias. 128x128 tile / CTA, K-step 32, 3-phase
// split chain: Ah*Bh, Ah*Bl, Al*Bh (al*bl dropped, ~2^-16 rel).
// B is pre-transposed: rows = N, K-major (so both operands ldmatrix non-trans).
#define ASTRIDE 40                           // halves per smem row (80 B, conflict-free)
#define SMSTAGE (128 * ASTRIDE * 2)          // bytes per stage (10240)

__global__ void __launch_bounds__(256, 1)
gemm_mma(const __nv_bfloat16* __restrict__ Ah, const __nv_bfloat16* __restrict__ Al,
         const __nv_bfloat16* __restrict__ Bh, const __nv_bfloat16* __restrict__ Bl,
         const float* __restrict__ bias, float* __restrict__ C,
         int N, int K, int relu)
{
    __shared__ __align__(16) __nv_bfloat16 smA[2 * 128 * ASTRIDE];
    __shared__ __align__(16) __nv_bfloat16 smB[2 * 128 * ASTRIDE];

    const int tid  = threadIdx.x;
    const int wid  = tid >> 5, lane = tid & 31;
    const int warp_m = wid >> 2;          // 0..1 (64 rows each)
    const int warp_n = wid & 3;           // 0..3 (32 cols each)
    const int m0 = blockIdx.y << 7;
    const int n0 = blockIdx.x << 7;

    const uint32_t sA = smem_u32(smA);
    const uint32_t sB = smem_u32(smB);

    // gmem->smem mapping: thread -> (row = tid>>1, 32B chunk = (tid&1)*32B)
    const int lrow = tid >> 1;
    const int lcolh = (tid & 1) * 16;     // halves

    const int kb = K >> 5;                // 32-wide K blocks per phase
    const int NB = 3 * kb;

    float c[4][4][4];
#pragma unroll
    for (int i = 0; i < 4; i++)
#pragma unroll
        for (int j = 0; j < 4; j++)
#pragma unroll
            for (int r = 0; r < 4; r++) c[i][j][r] = 0.f;

    // ldmatrix lane addressing (same for A and B tiles)
    const int rowoff = ((lane >> 3) & 1) * 8 + (lane & 7);
    const int coloff = ((lane >> 4) & 1) * 8;   // halves

    // stage-issue helper (macro-ish lambda)
    auto issue = [&](int blk, int stage) {
        int phase = blk / kb;
        int kk = blk - phase * kb;
        const __nv_bfloat16* As = (phase == 2) ? Al : Ah;
        const __nv_bfloat16* Bs = (phase == 1) ? Bl : Bh;
        const __nv_bfloat16* ga = As + (size_t)(m0 + lrow) * K + kk * 32 + lcolh;
        const __nv_bfloat16* gb = Bs + (size_t)(n0 + lrow) * K + kk * 32 + lcolh;
        uint32_t da = sA + stage * SMSTAGE + (lrow * ASTRIDE + lcolh) * 2;
        uint32_t db = sB + stage * SMSTAGE + (lrow * ASTRIDE + lcolh) * 2;
        cp16(da,      ga);
        cp16(da + 16, ga + 8);
        cp16(db,      gb);
        cp16(db + 16, gb + 8);
        CP_COMMIT();
    };

    issue(0, 0);

    for (int blk = 0; blk < NB; blk++) {
        const int stage = blk & 1;
        if (blk + 1 < NB) {
            issue(blk + 1, (blk + 1) & 1);
            CP_WAIT(1);
        } else {
            CP_WAIT(0);
        }
        __syncthreads();

        const uint32_t a0 = sA + stage * SMSTAGE;
        const uint32_t b0 = sB + stage * SMSTAGE;
#pragma unroll
        for (int kh = 0; kh < 2; kh++) {
            uint32_t af[4][4];
#pragma unroll
            for (int t = 0; t < 4; t++) {
                uint32_t addr = a0 + ((warp_m * 64 + t * 16 + rowoff) * ASTRIDE
                                      + kh * 16 + coloff) * 2;
                ldsm4(af[t][0], af[t][1], af[t][2], af[t][3], addr);
            }
            uint32_t bf[4][2];
#pragma unroll
            for (int p = 0; p < 2; p++) {
                uint32_t r0, r1, r2, r3;
                uint32_t addr = b0 + ((warp_n * 32 + p * 16 + rowoff) * ASTRIDE
                                      + kh * 16 + coloff) * 2;
                ldsm4(r0, r1, r2, r3, addr);
                bf[2*p][0]   = r0; bf[2*p][1]   = r2;
                bf[2*p+1][0] = r1; bf[2*p+1][1] = r3;
            }
#pragma unroll
            for (int i = 0; i < 4; i++)
#pragma unroll
                for (int j = 0; j < 4; j++)
                    mma_bf16(c[i][j], af[i], bf[j]);
        }
        __syncthreads();
    }

    // epilogue: bias (+relu) and direct fp32 stores
#pragma unroll
    for (int i = 0; i < 4; i++) {
#pragma unroll
        for (int j = 0; j < 4; j++) {
            int grow = m0 + warp_m * 64 + i * 16 + (lane >> 2);
            int gcol = n0 + warp_n * 32 + j * 8 + (lane & 3) * 2;
            float b0v = bias[gcol], b1v = bias[gcol + 1];
            float v0 = c[i][j][0] + b0v;
            float v1 = c[i][j][1] + b1v;
            float v2 = c[i][j][2] + b0v;
            float v3 = c[i][j][3] + b1v;
            if (relu) {
                v0 = fmaxf(v0, 0.f); v1 = fmaxf(v1, 0.f);
                v2 = fmaxf(v2, 0.f); v3 = fmaxf(v3, 0.f);
            }
            *(float2*)(C + (size_t)grow * N + gcol)       = make_float2(v0, v1);
            *(float2*)(C + (size_t)(grow + 8) * N + gcol) = make_float2(v2, v3);
        }
    }
}

// ---------------- flash attention with post-softmax mask --------------------
#define AS 68   // padded smem row stride (floats)

__global__ void __launch_bounds__(256)
attn_kernel(const float* __restrict__ wm)
{
    extern __shared__ float sm[];
    float* qst = sm;               // [d][r] transposed, 64 x AS
    float* kst = sm + 64 * AS;     // [d][k] transposed
    float* vs  = sm + 2 * 64 * AS; // [k][d]
    float* sct = sm + 3 * 64 * AS; // [k][r]  probs transposed

    const int tid = threadIdx.x;
    const int qt = blockIdx.x, h = blockIdx.y, b = blockIdx.z;
    const int q0 = qt * 64;
    const int tr = tid >> 4, tc = tid & 15;

    const int lr = tid & 63;
    const int ld = (tid >> 6) << 4;
    const int vr = tid >> 2;
    const int vd = (tid & 3) << 4;

    {
        const float* qg = g_qkv + ((size_t)(b * SEQ + q0 + lr)) * NQKV + h * DHEAD + ld;
#pragma unroll
        for (int u = 0; u < 4; u++) {
            float4 t = *(const float4*)(qg + 4 * u);
            int d = ld + 4 * u;
            qst[(d + 0) * AS + lr] = t.x * 0.125f;
            qst[(d + 1) * AS + lr] = t.y * 0.125f;
            qst[(d + 2) * AS + lr] = t.z * 0.125f;
            qst[(d + 3) * AS + lr] = t.w * 0.125f;
        }
    }

    float m[4], l[4], acc[4][4];
#pragma unroll
    for (int i = 0; i < 4; i++) {
        m[i] = -1e30f; l[i] = 0.f;
#pragma unroll
        for (int j = 0; j < 4; j++) acc[i][j] = 0.f;
    }

    for (int kt = 0; kt < 16; ++kt) {
        const int kb = kt * 64;
        {
            const float* kg = g_qkv + ((size_t)(b * SEQ + kb + lr)) * NQKV + HID + h * DHEAD + ld;
#pragma unroll
            for (int u = 0; u < 4; u++) {
                float4 t = *(const float4*)(kg + 4 * u);
                int d = ld + 4 * u;
                kst[(d + 0) * AS + lr] = t.x;
                kst[(d + 1) * AS + lr] = t.y;
                kst[(d + 2) * AS + lr] = t.z;
                kst[(d + 3) * AS + lr] = t.w;
            }
            const float* vg = g_qkv + ((size_t)(b * SEQ + kb + vr)) * NQKV + 2 * HID + h * DHEAD + vd;
#pragma unroll
            for (int u = 0; u < 4; u++)
                *(float4*)(vs + vr * AS + vd + 4 * u) = *(const float4*)(vg + 4 * u);
        }
        __syncthreads();

        float s[4][4];
#pragma unroll
        for (int i = 0; i < 4; i++)
#pragma unroll
            for (int j = 0; j < 4; j++) s[i][j] = 0.f;

#pragma unroll 8
        for (int d = 0; d < 64; ++d) {
            float4 qv = *(const float4*)(qst + d * AS + 4 * tr);
            float4 kv = *(const float4*)(kst + d * AS + 4 * tc);
            float qa[4] = {qv.x, qv.y, qv.z, qv.w};
            float ka[4] = {kv.x, kv.y, kv.z, kv.w};
#pragma unroll
            for (int i = 0; i < 4; i++)
#pragma unroll
                for (int j = 0; j < 4; j++)
                    s[i][j] = fmaf(qa[i], ka[j], s[i][j]);
        }

        float mk[4][4];
#pragma unroll
        for (int i = 0; i < 4; i++) {
            float4 t = *(const float4*)(wm + ((size_t)b * SEQ + (q0 + 4 * tr + i)) * SEQ + kb + 4 * tc);
            mk[i][0] = t.x; mk[i][1] = t.y; mk[i][2] = t.z; mk[i][3] = t.w;
        }

#pragma unroll
        for (int i = 0; i < 4; i++) {
            float mx = fmaxf(fmaxf(s[i][0], s[i][1]), fmaxf(s[i][2], s[i][3]));
#pragma unroll
            for (int o = 8; o; o >>= 1)
                mx = fmaxf(mx, __shfl_xor_sync(0xffffffffu, mx, o));
            float mn = fmaxf(m[i], mx);
            float f  = __expf(m[i] - mn);
            float e0 = __expf(s[i][0] - mn);
            float e1 = __expf(s[i][1] - mn);
            float e2 = __expf(s[i][2] - mn);
            float e3 = __expf(s[i][3] - mn);
            float ls = e0 + e1 + e2 + e3;
#pragma unroll
            for (int o = 8; o; o >>= 1)
                ls += __shfl_xor_sync(0xffffffffu, ls, o);
            l[i] = l[i] * f + ls;
            m[i] = mn;
#pragma unroll
            for (int j = 0; j < 4; j++) acc[i][j] *= f;
            s[i][0] = e0 * mk[i][0];
            s[i][1] = e1 * mk[i][1];
            s[i][2] = e2 * mk[i][2];
            s[i][3] = e3 * mk[i][3];
        }

#pragma unroll
        for (int j = 0; j < 4; j++) {
            float4 col = make_float4(s[0][j], s[1][j], s[2][j], s[3][j]);
            *(float4*)(sct + (4 * tc + j) * AS + 4 * tr) = col;
        }
        __syncthreads();

#pragma unroll 8
        for (int kk = 0; kk < 64; ++kk) {
            float4 p = *(const float4*)(sct + kk * AS + 4 * tr);
            float4 v = *(const float4*)(vs  + kk * AS + 4 * tc);
            float pa[4] = {p.x, p.y, p.z, p.w};
            float va[4] = {v.x, v.y, v.z, v.w};
#pragma unroll
            for (int i = 0; i < 4; i++)
#pragma unroll
                for (int j = 0; j < 4; j++)
                    acc[i][j] = fmaf(pa[i], va[j], acc[i][j]);
        }
        __syncthreads();
    }

#pragma unroll
    for (int i = 0; i < 4; i++) {
        float inv = 1.0f / l[i];
        float4 o = make_float4(acc[i][0] * inv, acc[i][1] * inv,
                               acc[i][2] * inv, acc[i][3] * inv);
        *(float4*)(g_ctx + ((size_t)(b * SEQ + q0 + 4 * tr + i)) * HID + h * DHEAD + 4 * tc) = o;
    }
}

// ---------------- fused residual-add + LayerNorm (two-pass) -----------------
__device__ __forceinline__ void addln_body(const float* __restrict__ A, int sA,
                                           const float* __restrict__ Bv, int sB,
                                           const float* __restrict__ g,
                                           const float* __restrict__ be,
                                           float* __restrict__ out)
{
    const int row = blockIdx.x;
    const int tid = threadIdx.x;
    __shared__ float red[8];
    __shared__ float s_mu, s_rs;

    float4 v4 = make_float4(0.f, 0.f, 0.f, 0.f);
    float ls = 0.f;
    if (tid < 192) {
        float4 av = ((const float4*)(A  + (size_t)row * sA))[tid];
        float4 bv = ((const float4*)(Bv + (size_t)row * sB))[tid];
        v4 = make_float4(av.x + bv.x, av.y + bv.y, av.z + bv.z, av.w + bv.w);
        ls = v4.x + v4.y + v4.z + v4.w;
    }
    int lane = tid & 31, wid = tid >> 5;
#pragma unroll
    for (int o = 16; o; o >>= 1) ls += __shfl_xor_sync(0xffffffffu, ls, o);
    if (lane == 0) red[wid] = ls;
    __syncthreads();
    if (tid == 0) {
        float t = 0.f;
#pragma unroll
        for (int i = 0; i < 8; i++) t += red[i];
        s_mu = t * (1.0f / HID);
    }
    __syncthreads();
    float mu = s_mu;

    float4 dx = make_float4(v4.x - mu, v4.y - mu, v4.z - mu, v4.w - mu);
    float lv = 0.f;
    if (tid < 192)
        lv = dx.x * dx.x + dx.y * dx.y + dx.z * dx.z + dx.w * dx.w;
#pragma unroll
    for (int o = 16; o; o >>= 1) lv += __shfl_xor_sync(0xffffffffu, lv, o);
    __syncthreads();
    if (lane == 0) red[wid] = lv;
    __syncthreads();
    if (tid == 0) {
        float t = 0.f;
#pragma unroll
        for (int i = 0; i < 8; i++) t += red[i];
        s_rs = rsqrtf(t * (1.0f / HID) + 1e-5f);
    }
    __syncthreads();
    float rs = s_rs;

    if (tid < 192) {
        float4 g4  = ((const float4*)g)[tid];
        float4 be4 = ((const float4*)be)[tid];
        float4 o = make_float4(dx.x * rs * g4.x + be4.x,
                               dx.y * rs * g4.y + be4.y,
                               dx.z * rs * g4.z + be4.z,
                               dx.w * rs * g4.w + be4.w);
        ((float4*)(out + (size_t)row * HID))[tid] = o;
    }
}

__global__ void __launch_bounds__(256)
ln1_kernel(const float* __restrict__ g, const float* __restrict__ be)
{
    addln_body(g_ctx, HID, g_qkv, NQKV, g, be, g_x);  // x = LN(ctx + q_mixed)
}

__global__ void __launch_bounds__(256)
ln2_kernel(const float* __restrict__ g, const float* __restrict__ be,
           float* __restrict__ out)
{
    addln_body(g_x, HID, g_ff2, HID, g, be, out);     // out = LN(x + ff)
}

// ---------------- launch -----------------------------------------------------
extern "C" void kernel_launch(void* const* d_in, const int* in_sizes, int n_in,
                              void* d_out, int out_size)
{
    const float* x1  = (const float*)d_in[0];
    const float* wm  = (const float*)d_in[1];
    const float* Wq  = (const float*)d_in[2];
    const float* bq  = (const float*)d_in[3];
    const float* Wk  = (const float*)d_in[4];
    const float* bk  = (const float*)d_in[5];
    const float* Wv  = (const float*)d_in[6];
    const float* bv  = (const float*)d_in[7];
    const float* g1  = (const float*)d_in[8];
    const float* be1 = (const float*)d_in[9];
    const float* g2  = (const float*)d_in[10];
    const float* be2 = (const float*)d_in[11];
    const float* W1  = (const float*)d_in[12];
    const float* b1  = (const float*)d_in[13];
    const float* W2  = (const float*)d_in[14];
    const float* b2  = (const float*)d_in[15];
    float* out = (float*)d_out;

    // resolve device-global scratch addresses (no allocation, capture-safe)
    void *p_ah, *p_al, *p_wqh, *p_wql, *p_w1h, *p_w1l, *p_w2h, *p_w2l;
    void *p_qkv, *p_bqkv, *p_x, *p_ff1, *p_ff2;
    cudaGetSymbolAddress(&p_ah, g_ah);     cudaGetSymbolAddress(&p_al, g_al);
    cudaGetSymbolAddress(&p_wqh, g_wqkvh); cudaGetSymbolAddress(&p_wql, g_wqkvl);
    cudaGetSymbolAddress(&p_w1h, g_w1h);   cudaGetSymbolAddress(&p_w1l, g_w1l);
    cudaGetSymbolAddress(&p_w2h, g_w2h);   cudaGetSymbolAddress(&p_w2l, g_w2l);
    cudaGetSymbolAddress(&p_qkv, g_qkv);   cudaGetSymbolAddress(&p_bqkv, g_bqkv);
    cudaGetSymbolAddress(&p_x, g_x);       cudaGetSymbolAddress(&p_ff1, g_ff1);
    cudaGetSymbolAddress(&p_ff2, g_ff2);

    __nv_bfloat16* ah  = (__nv_bfloat16*)p_ah;
    __nv_bfloat16* al  = (__nv_bfloat16*)p_al;
    __nv_bfloat16* wqh = (__nv_bfloat16*)p_wqh;
    __nv_bfloat16* wql = (__nv_bfloat16*)p_wql;
    __nv_bfloat16* w1h = (__nv_bfloat16*)p_w1h;
    __nv_bfloat16* w1l = (__nv_bfloat16*)p_w1l;
    __nv_bfloat16* w2h = (__nv_bfloat16*)p_w2h;
    __nv_bfloat16* w2l = (__nv_bfloat16*)p_w2l;
    float* qkv  = (float*)p_qkv;
    float* bqkv = (float*)p_bqkv;
    float* xbuf = (float*)p_x;
    float* ff1  = (float*)p_ff1;
    float* ff2  = (float*)p_ff2;

    const int ATTN_SMEM = 4 * 64 * AS * (int)sizeof(float);  // 69632 B
    cudaFuncSetAttribute(attn_kernel,
                         cudaFuncAttributeMaxDynamicSharedMemorySize, ATTN_SMEM);

    dim3 tb(32, 8);

    // weight prep: transpose + bf16 split
    prep_bias<<<3, 256>>>(bq, bk, bv);
    transpose_split<<<dim3(HID/32, HID/32), tb>>>(Wq, wqh,             wql,             HID, HID);
    transpose_split<<<dim3(HID/32, HID/32), tb>>>(Wk, wqh + HID*HID,   wql + HID*HID,   HID, HID);
    transpose_split<<<dim3(HID/32, HID/32), tb>>>(Wv, wqh + 2*HID*HID, wql + 2*HID*HID, HID, HID);
    transpose_split<<<dim3(FF/32,  HID/32), tb>>>(W1, w1h, w1l, HID, FF);
    transpose_split<<<dim3(HID/32, FF/32),  tb>>>(W2, w2h, w2l, FF, HID);

    // 1. fused QKV: [8192,768] x [768,2304]^T -> g_qkv
    convert_split<<<2048, 256>>>(x1, ah, al, ROWS * HID / 4);
    gemm_mma<<<dim3(NQKV/128, ROWS/128), 256>>>(ah, al, wqh, wql, bqkv, qkv, NQKV, HID, 0);

    // 2. flash attention with post-softmax mask
    attn_kernel<<<dim3(SEQ/64, NHEAD, BATCH), 256, ATTN_SMEM>>>(wm);

    // 3. x = LN(ctx + q_mixed)
    ln1_kernel<<<ROWS, 256>>>(g1, be1);

    // 4. ff1 = relu(x @ W1 + b1)
    convert_split<<<2048, 256>>>(xbuf, ah, al, ROWS * HID / 4);
    gemm_mma<<<dim3(FF/128, ROWS/128), 256>>>(ah, al, w1h, w1l, b1, ff1, FF, HID, 1);

    // 5. ff2 = ff1 @ W2 + b2
    convert_split<<<4096, 256>>>(ff1, ah, al, ROWS * FF / 4);
    gemm_mma<<<dim3(HID/128, ROWS/128), 256>>>(ah, al, w2h, w2l, b2, ff2, HID, FF, 0);

    // 6. out = LN(x + ff2)
    ln2_kernel<<<ROWS, 256>>>(g2, be2, out);
}

// round 5
// speedup vs baseline: 1.7129x; 1.7129x over previous
#include <cuda_runtime.h>
#include <cuda_bf16.h>
#include <cstdint>
#include <math.h>

// Problem constants
#define BATCH 8
#define SEQ   1024
#define HID   768
#define NHEAD 12
#define DHEAD 64
#define ROWS  (BATCH*SEQ)          // 8192
#define FF    (2*HID)              // 1536
#define NQKV  (3*HID)              // 2304

// ---------------- scratch (device globals; no allocations allowed) ----------
__device__ float g_qkv[ROWS*NQKV];   // q | k | v  per row
__device__ float g_ctx[ROWS*HID];
__device__ float g_x  [ROWS*HID];
__device__ float g_ff2[ROWS*HID];
__device__ float g_bqkv[NQKV];

__device__ __nv_bfloat16 g_ah[ROWS*HID];     // x1 / x splits (GEMM A inputs)
__device__ __nv_bfloat16 g_al[ROWS*HID];
__device__ __nv_bfloat16 g_fh[ROWS*FF];      // ff1 splits (separate! no aliasing)
__device__ __nv_bfloat16 g_fl[ROWS*FF];
__device__ __nv_bfloat16 g_wqkvh[NQKV*HID];  // W^T split, rows = N, K-major
__device__ __nv_bfloat16 g_wqkvl[NQKV*HID];
__device__ __nv_bfloat16 g_w1h[FF*HID];
__device__ __nv_bfloat16 g_w1l[FF*HID];
__device__ __nv_bfloat16 g_w2h[HID*FF];
__device__ __nv_bfloat16 g_w2l[HID*FF];

// ---------------- PTX helpers (sm_80-era only; no 'a'-features) -------------
__device__ __forceinline__ uint32_t smem_u32(const void* p) {
    uint32_t a;
    asm("{ .reg .u64 t; cvta.to.shared.u64 t, %1; cvt.u32.u64 %0, t; }"
        : "=r"(a) : "l"(p));
    return a;
}

__device__ __forceinline__ void cp16(uint32_t dst, const void* src) {
    asm volatile("cp.async.cg.shared.global [%0], [%1], 16;"
                 :: "r"(dst), "l"(src));
}
#define CP_COMMIT() asm volatile("cp.async.commit_group;" ::: "memory")
#define CP_WAIT(n)  asm volatile("cp.async.wait_group %0;" :: "n"(n) : "memory")

__device__ __forceinline__ void ldsm4(uint32_t& r0, uint32_t& r1,
                                      uint32_t& r2, uint32_t& r3, uint32_t addr) {
    asm volatile("ldmatrix.sync.aligned.m8n8.x4.shared.b16 {%0,%1,%2,%3}, [%4];"
                 : "=r"(r0), "=r"(r1), "=r"(r2), "=r"(r3) : "r"(addr));
}

__device__ __forceinline__ void mma_bf16(float* c, const uint32_t* a, const uint32_t* b) {
    asm volatile("mma.sync.aligned.m16n8k16.row.col.f32.bf16.bf16.f32 "
                 "{%0,%1,%2,%3}, {%4,%5,%6,%7}, {%8,%9}, {%0,%1,%2,%3};"
                 : "+f"(c[0]), "+f"(c[1]), "+f"(c[2]), "+f"(c[3])
                 : "r"(a[0]), "r"(a[1]), "r"(a[2]), "r"(a[3]),
                   "r"(b[0]), "r"(b[1]));
}

// ---------------- prep kernels ----------------------------------------------
__global__ void prep_bias(const float* __restrict__ bq, const float* __restrict__ bk,
                          const float* __restrict__ bv) {
    int i = blockIdx.x * blockDim.x + threadIdx.x;
    if (i < HID) {
        g_bqkv[i]         = bq[i];
        g_bqkv[i + HID]   = bk[i];
        g_bqkv[i + 2*HID] = bv[i];
    }
}

// W[K,N] fp32 -> out[N,K] bf16 hi/lo (transpose + split)
__device__ __forceinline__ void tsp_body(const float* __restrict__ W,
                                         __nv_bfloat16* __restrict__ oh,
                                         __nv_bfloat16* __restrict__ ol,
                                         int K, int N) {
    __shared__ float t[32][33];
    const int tx = threadIdx.x, ty = threadIdx.y;
    const int n0 = blockIdx.x * 32, k0 = blockIdx.y * 32;
#pragma unroll
    for (int i = 0; i < 4; i++)
        t[ty + 8*i][tx] = W[(size_t)(k0 + ty + 8*i) * N + n0 + tx];
    __syncthreads();
#pragma unroll
    for (int i = 0; i < 4; i++) {
        float v = t[tx][ty + 8*i];
        __nv_bfloat16 h = __float2bfloat16(v);
        __nv_bfloat16 l = __float2bfloat16(v - __bfloat162float(h));
        size_t idx = (size_t)(n0 + ty + 8*i) * K + k0 + tx;
        oh[idx] = h;
        ol[idx] = l;
    }
}

__global__ void __launch_bounds__(256)
transpose_split(const float* __restrict__ W, __nv_bfloat16* __restrict__ oh,
                __nv_bfloat16* __restrict__ ol, int K, int N) {
    tsp_body(W, oh, ol, K, N);
}

// fused Q/K/V weight transpose: z selects projection
__global__ void __launch_bounds__(256)
transpose_qkv(const float* __restrict__ Wq, const float* __restrict__ Wk,
              const float* __restrict__ Wv) {
    const float* W = (blockIdx.z == 0) ? Wq : (blockIdx.z == 1) ? Wk : Wv;
    tsp_body(W, g_wqkvh + (size_t)blockIdx.z * HID * HID,
                g_wqkvl + (size_t)blockIdx.z * HID * HID, HID, HID);
}

// fp32 -> bf16 hi/lo elementwise split
__global__ void __launch_bounds__(256)
convert_split(const float* __restrict__ in, __nv_bfloat16* __restrict__ oh,
              __nv_bfloat16* __restrict__ ol, int n4) {
    for (int i = blockIdx.x * blockDim.x + threadIdx.x; i < n4;
         i += gridDim.x * blockDim.x) {
        float4 a = ((const float4*)in)[i];
        __nv_bfloat16 h0 = __float2bfloat16(a.x);
        __nv_bfloat16 h1 = __float2bfloat16(a.y);
        __nv_bfloat16 h2 = __float2bfloat16(a.z);
        __nv_bfloat16 h3 = __float2bfloat16(a.w);
        __nv_bfloat162 hp0; hp0.x = h0; hp0.y = h1;
        __nv_bfloat162 hp1; hp1.x = h2; hp1.y = h3;
        ((__nv_bfloat162*)oh)[2*i]   = hp0;
        ((__nv_bfloat162*)oh)[2*i+1] = hp1;
        __nv_bfloat162 lp0, lp1;
        lp0.x = __float2bfloat16(a.x - __bfloat162float(h0));
        lp0.y = __float2bfloat16(a.y - __bfloat162float(h1));
        lp1.x = __float2bfloat16(a.z - __bfloat162float(h2));
        lp1.y = __float2bfloat16(a.w - __bfloat162float(h3));
        ((__nv_bfloat162*)ol)[2*i]   = lp0;
        ((__nv_bfloat162*)ol)[2*i+1] = lp1;
    }
}

// ---------------- mma.sync bf16-split GEMM (4-stage cp.async ring) -----------
// C[M,N] = (Ah+Al)(Bh+Bl)^T + bias. 128x128 tile / CTA, K-step 32, 3-phase
// split chain: Ah*Bh, Ah*Bl, Al*Bh (al*bl dropped, ~2^-16 rel).
// B pre-transposed: rows = N, K-major. Output: fp32, or bf16 hi/lo split
// (split output must NOT alias the A inputs).
#define ASTR    40                           // halves per smem row (80 B)
#define STGB    (128 * ASTR * 2)             // bytes per tile per stage (10240)
#define STAGES  4
#define GEMM_SMEM (STAGES * 2 * STGB)        // 81920 B dynamic

__global__ void __launch_bounds__(256, 2)
gemm_mma(const __nv_bfloat16* __restrict__ Ah, const __nv_bfloat16* __restrict__ Al,
         const __nv_bfloat16* __restrict__ Bh, const __nv_bfloat16* __restrict__ Bl,
         const float* __restrict__ bias,
         float* __restrict__ Cf,
         __nv_bfloat16* __restrict__ Ch, __nv_bfloat16* __restrict__ Cl,
         int N, int K, int relu, int split_out)
{
    extern __shared__ __align__(16) char dsm[];
    __nv_bfloat16* smA = (__nv_bfloat16*)dsm;                    // STAGES x 128 x ASTR
    __nv_bfloat16* smB = (__nv_bfloat16*)(dsm + STAGES * STGB);

    const int tid  = threadIdx.x;
    const int wid  = tid >> 5, lane = tid & 31;
    const int warp_m = wid >> 2;          // 0..1 (64 rows each)
    const int warp_n = wid & 3;           // 0..3 (32 cols each)
    const int m0 = blockIdx.y << 7;
    const int n0 = blockIdx.x << 7;

    const uint32_t sA = smem_u32(smA);
    const uint32_t sB = smem_u32(smB);

    // gmem->smem mapping: row = tid>>1, 32B chunk = (tid&1)
    const int lrow  = tid >> 1;
    const int lcolh = (tid & 1) * 16;     // halves

    const int kb = K >> 5;                // 32-wide K blocks per phase
    const int NB = 3 * kb;

    float c[4][4][4];
#pragma unroll
    for (int i = 0; i < 4; i++)
#pragma unroll
        for (int j = 0; j < 4; j++)
#pragma unroll
            for (int r = 0; r < 4; r++) c[i][j][r] = 0.f;

    // ldmatrix lane addressing
    const int rowoff = ((lane >> 3) & 1) * 8 + (lane & 7);
    const int coloff = ((lane >> 4) & 1) * 8;   // halves

    auto issue = [&](int blk) {
        if (blk < NB) {
            int phase = blk / kb;
            int kk = blk - phase * kb;
            const __nv_bfloat16* As = (phase == 2) ? Al : Ah;
            const __nv_bfloat16* Bs = (phase == 1) ? Bl : Bh;
            const __nv_bfloat16* ga = As + (size_t)(m0 + lrow) * K + kk * 32 + lcolh;
            const __nv_bfloat16* gb = Bs + (size_t)(n0 + lrow) * K + kk * 32 + lcolh;
            int st = blk & (STAGES - 1);
            uint32_t da = sA + st * STGB + (lrow * ASTR + lcolh) * 2;
            uint32_t db = sB + st * STGB + (lrow * ASTR + lcolh) * 2;
            cp16(da,      ga);
            cp16(da + 16, ga + 8);
            cp16(db,      gb);
            cp16(db + 16, gb + 8);
        }
        CP_COMMIT();
    };

    issue(0); issue(1); issue(2);

    for (int blk = 0; blk < NB; blk++) {
        CP_WAIT(2);
        __syncthreads();

        const int stage = blk & (STAGES - 1);
        const uint32_t a0 = sA + stage * STGB;
        const uint32_t b0 = sB + stage * STGB;
#pragma unroll
        for (int kh = 0; kh < 2; kh++) {
            uint32_t af[4][4];
#pragma unroll
            for (int t = 0; t < 4; t++) {
                uint32_t addr = a0 + ((warp_m * 64 + t * 16 + rowoff) * ASTR
                                      + kh * 16 + coloff) * 2;
                ldsm4(af[t][0], af[t][1], af[t][2], af[t][3], addr);
            }
            uint32_t bf[4][2];
#pragma unroll
            for (int p = 0; p < 2; p++) {
                uint32_t r0, r1, r2, r3;
                uint32_t addr = b0 + ((warp_n * 32 + p * 16 + rowoff) * ASTR
                                      + kh * 16 + coloff) * 2;
                ldsm4(r0, r1, r2, r3, addr);
                bf[2*p][0]   = r0; bf[2*p][1]   = r2;
                bf[2*p+1][0] = r1; bf[2*p+1][1] = r3;
            }
#pragma unroll
            for (int i = 0; i < 4; i++)
#pragma unroll
                for (int j = 0; j < 4; j++)
                    mma_bf16(c[i][j], af[i], bf[j]);
        }
        issue(blk + 3);
    }

    // epilogue: bias (+relu), then fp32 or bf16-split stores
#pragma unroll
    for (int i = 0; i < 4; i++) {
#pragma unroll
        for (int j = 0; j < 4; j++) {
            int grow = m0 + warp_m * 64 + i * 16 + (lane >> 2);
            int gcol = n0 + warp_n * 32 + j * 8 + (lane & 3) * 2;
            float b0v = bias[gcol], b1v = bias[gcol + 1];
            float v0 = c[i][j][0] + b0v;
            float v1 = c[i][j][1] + b1v;
            float v2 = c[i][j][2] + b0v;
            float v3 = c[i][j][3] + b1v;
            if (relu) {
                v0 = fmaxf(v0, 0.f); v1 = fmaxf(v1, 0.f);
                v2 = fmaxf(v2, 0.f); v3 = fmaxf(v3, 0.f);
            }
            if (split_out) {
                __nv_bfloat162 h0, h1, l0, l1;
                h0.x = __float2bfloat16(v0); h0.y = __float2bfloat16(v1);
                h1.x = __float2bfloat16(v2); h1.y = __float2bfloat16(v3);
                l0.x = __float2bfloat16(v0 - __bfloat162float(h0.x));
                l0.y = __float2bfloat16(v1 - __bfloat162float(h0.y));
                l1.x = __float2bfloat16(v2 - __bfloat162float(h1.x));
                l1.y = __float2bfloat16(v3 - __bfloat162float(h1.y));
                *(__nv_bfloat162*)(Ch + (size_t)grow * N + gcol)       = h0;
                *(__nv_bfloat162*)(Ch + (size_t)(grow + 8) * N + gcol) = h1;
                *(__nv_bfloat162*)(Cl + (size_t)grow * N + gcol)       = l0;
                *(__nv_bfloat162*)(Cl + (size_t)(grow + 8) * N + gcol) = l1;
            } else {
                *(float2*)(Cf + (size_t)grow * N + gcol)       = make_float2(v0, v1);
                *(float2*)(Cf + (size_t)(grow + 8) * N + gcol) = make_float2(v2, v3);
            }
        }
    }
}

// ---------------- flash attention with post-softmax mask --------------------
#define AS 68   // padded smem row stride (floats)

__global__ void __launch_bounds__(256)
attn_kernel(const float* __restrict__ wm)
{
    extern __shared__ float sm[];
    float* qst = sm;               // [d][r] transposed, 64 x AS
    float* kst = sm + 64 * AS;     // [d][k] transposed
    float* vs  = sm + 2 * 64 * AS; // [k][d]
    float* sct = sm + 3 * 64 * AS; // [k][r]  probs transposed

    const int tid = threadIdx.x;
    const int qt = blockIdx.x, h = blockIdx.y, b = blockIdx.z;
    const int q0 = qt * 64;
    const int tr = tid >> 4, tc = tid & 15;

    const int lr = tid & 63;
    const int ld = (tid >> 6) << 4;
    const int vr = tid >> 2;
    const int vd = (tid & 3) << 4;

    {
        const float* qg = g_qkv + ((size_t)(b * SEQ + q0 + lr)) * NQKV + h * DHEAD + ld;
#pragma unroll
        for (int u = 0; u < 4; u++) {
            float4 t = *(const float4*)(qg + 4 * u);
            int d = ld + 4 * u;
            qst[(d + 0) * AS + lr] = t.x * 0.125f;
            qst[(d + 1) * AS + lr] = t.y * 0.125f;
            qst[(d + 2) * AS + lr] = t.z * 0.125f;
            qst[(d + 3) * AS + lr] = t.w * 0.125f;
        }
    }

    float m[4], l[4], acc[4][4];
#pragma unroll
    for (int i = 0; i < 4; i++) {
        m[i] = -1e30f; l[i] = 0.f;
#pragma unroll
        for (int j = 0; j < 4; j++) acc[i][j] = 0.f;
    }

    for (int kt = 0; kt < 16; ++kt) {
        const int kb = kt * 64;
        {
            const float* kg = g_qkv + ((size_t)(b * SEQ + kb + lr)) * NQKV + HID + h * DHEAD + ld;
#pragma unroll
            for (int u = 0; u < 4; u++) {
                float4 t = *(const float4*)(kg + 4 * u);
                int d = ld + 4 * u;
                kst[(d + 0) * AS + lr] = t.x;
                kst[(d + 1) * AS + lr] = t.y;
                kst[(d + 2) * AS + lr] = t.z;
                kst[(d + 3) * AS + lr] = t.w;
            }
            const float* vg = g_qkv + ((size_t)(b * SEQ + kb + vr)) * NQKV + 2 * HID + h * DHEAD + vd;
#pragma unroll
            for (int u = 0; u < 4; u++)
                *(float4*)(vs + vr * AS + vd + 4 * u) = *(const float4*)(vg + 4 * u);
        }
        __syncthreads();

        float s[4][4];
#pragma unroll
        for (int i = 0; i < 4; i++)
#pragma unroll
            for (int j = 0; j < 4; j++) s[i][j] = 0.f;

#pragma unroll 8
        for (int d = 0; d < 64; ++d) {
            float4 qv = *(const float4*)(qst + d * AS + 4 * tr);
            float4 kv = *(const float4*)(kst + d * AS + 4 * tc);
            float qa[4] = {qv.x, qv.y, qv.z, qv.w};
            float ka[4] = {kv.x, kv.y, kv.z, kv.w};
#pragma unroll
            for (int i = 0; i < 4; i++)
#pragma unroll
                for (int j = 0; j < 4; j++)
                    s[i][j] = fmaf(qa[i], ka[j], s[i][j]);
        }

        float mk[4][4];
#pragma unroll
        for (int i = 0; i < 4; i++) {
            float4 t = *(const float4*)(wm + ((size_t)b * SEQ + (q0 + 4 * tr + i)) * SEQ + kb + 4 * tc);
            mk[i][0] = t.x; mk[i][1] = t.y; mk[i][2] = t.z; mk[i][3] = t.w;
        }

#pragma unroll
        for (int i = 0; i < 4; i++) {
            float mx = fmaxf(fmaxf(s[i][0], s[i][1]), fmaxf(s[i][2], s[i][3]));
#pragma unroll
            for (int o = 8; o; o >>= 1)
                mx = fmaxf(mx, __shfl_xor_sync(0xffffffffu, mx, o));
            float mn = fmaxf(m[i], mx);
            float f  = __expf(m[i] - mn);
            float e0 = __expf(s[i][0] - mn);
            float e1 = __expf(s[i][1] - mn);
            float e2 = __expf(s[i][2] - mn);
            float e3 = __expf(s[i][3] - mn);
            float ls = e0 + e1 + e2 + e3;
#pragma unroll
            for (int o = 8; o; o >>= 1)
                ls += __shfl_xor_sync(0xffffffffu, ls, o);
            l[i] = l[i] * f + ls;
            m[i] = mn;
#pragma unroll
            for (int j = 0; j < 4; j++) acc[i][j] *= f;
            s[i][0] = e0 * mk[i][0];
            s[i][1] = e1 * mk[i][1];
            s[i][2] = e2 * mk[i][2];
            s[i][3] = e3 * mk[i][3];
        }

#pragma unroll
        for (int j = 0; j < 4; j++) {
            float4 col = make_float4(s[0][j], s[1][j], s[2][j], s[3][j]);
            *(float4*)(sct + (4 * tc + j) * AS + 4 * tr) = col;
        }
        __syncthreads();

#pragma unroll 8
        for (int kk = 0; kk < 64; ++kk) {
            float4 p = *(const float4*)(sct + kk * AS + 4 * tr);
            float4 v = *(const float4*)(vs  + kk * AS + 4 * tc);
            float pa[4] = {p.x, p.y, p.z, p.w};
            float va[4] = {v.x, v.y, v.z, v.w};
#pragma unroll
            for (int i = 0; i < 4; i++)
#pragma unroll
                for (int j = 0; j < 4; j++)
                    acc[i][j] = fmaf(pa[i], va[j], acc[i][j]);
        }
        __syncthreads();
    }

#pragma unroll
    for (int i = 0; i < 4; i++) {
        float inv = 1.0f / l[i];
        float4 o = make_float4(acc[i][0] * inv, acc[i][1] * inv,
                               acc[i][2] * inv, acc[i][3] * inv);
        *(float4*)(g_ctx + ((size_t)(b * SEQ + q0 + 4 * tr + i)) * HID + h * DHEAD + 4 * tc) = o;
    }
}

// ---------------- fused residual-add + LayerNorm (two-pass) -----------------
// SPLIT: additionally emit bf16 hi/lo of the normalized output.
template<bool SPLIT>
__device__ __forceinline__ void addln_body(const float* __restrict__ A, int sA,
                                           const float* __restrict__ Bv, int sB,
                                           const float* __restrict__ g,
                                           const float* __restrict__ be,
                                           float* __restrict__ out,
                                           __nv_bfloat16* __restrict__ oh,
                                           __nv_bfloat16* __restrict__ ol)
{
    const int row = blockIdx.x;
    const int tid = threadIdx.x;
    __shared__ float red[8];
    __shared__ float s_mu, s_rs;

    float4 v4 = make_float4(0.f, 0.f, 0.f, 0.f);
    float ls = 0.f;
    if (tid < 192) {
        float4 av = ((const float4*)(A  + (size_t)row * sA))[tid];
        float4 bv = ((const float4*)(Bv + (size_t)row * sB))[tid];
        v4 = make_float4(av.x + bv.x, av.y + bv.y, av.z + bv.z, av.w + bv.w);
        ls = v4.x + v4.y + v4.z + v4.w;
    }
    int lane = tid & 31, wid = tid >> 5;
#pragma unroll
    for (int o = 16; o; o >>= 1) ls += __shfl_xor_sync(0xffffffffu, ls, o);
    if (lane == 0) red[wid] = ls;
    __syncthreads();
    if (tid == 0) {
        float t = 0.f;
#pragma unroll
        for (int i = 0; i < 8; i++) t += red[i];
        s_mu = t * (1.0f / HID);
    }
    __syncthreads();
    float mu = s_mu;

    float4 dx = make_float4(v4.x - mu, v4.y - mu, v4.z - mu, v4.w - mu);
    float lv = 0.f;
    if (tid < 192)
        lv = dx.x * dx.x + dx.y * dx.y + dx.z * dx.z + dx.w * dx.w;
#pragma unroll
    for (int o = 16; o; o >>= 1) lv += __shfl_xor_sync(0xffffffffu, lv, o);
    __syncthreads();
    if (lane == 0) red[wid] = lv;
    __syncthreads();
    if (tid == 0) {
        float t = 0.f;
#pragma unroll
        for (int i = 0; i < 8; i++) t += red[i];
        s_rs = rsqrtf(t * (1.0f / HID) + 1e-5f);
    }
    __syncthreads();
    float rs = s_rs;

    if (tid < 192) {
        float4 g4  = ((const float4*)g)[tid];
        float4 be4 = ((const float4*)be)[tid];
        float4 o = make_float4(dx.x * rs * g4.x + be4.x,
                               dx.y * rs * g4.y + be4.y,
                               dx.z * rs * g4.z + be4.z,
                               dx.w * rs * g4.w + be4.w);
        ((float4*)(out + (size_t)row * HID))[tid] = o;
        if (SPLIT) {
            __nv_bfloat162 h0, h1, l0, l1;
            h0.x = __float2bfloat16(o.x); h0.y = __float2bfloat16(o.y);
            h1.x = __float2bfloat16(o.z); h1.y = __float2bfloat16(o.w);
            l0.x = __float2bfloat16(o.x - __bfloat162float(h0.x));
            l0.y = __float2bfloat16(o.y - __bfloat162float(h0.y));
            l1.x = __float2bfloat16(o.z - __bfloat162float(h1.x));
            l1.y = __float2bfloat16(o.w - __bfloat162float(h1.y));
            ((__nv_bfloat162*)(oh + (size_t)row * HID))[2*tid]   = h0;
            ((__nv_bfloat162*)(oh + (size_t)row * HID))[2*tid+1] = h1;
            ((__nv_bfloat162*)(ol + (size_t)row * HID))[2*tid]   = l0;
            ((__nv_bfloat162*)(ol + (size_t)row * HID))[2*tid+1] = l1;
        }
    }
}

__global__ void __launch_bounds__(256)
ln1_kernel(const float* __restrict__ g, const float* __restrict__ be)
{
    // x = LN(ctx + q_mixed), also emit bf16 split of x for ff1
    addln_body<true>(g_ctx, HID, g_qkv, NQKV, g, be, g_x, g_ah, g_al);
}

__global__ void __launch_bounds__(256)
ln2_kernel(const float* __restrict__ g, const float* __restrict__ be,
           float* __restrict__ out)
{
    addln_body<false>(g_x, HID, g_ff2, HID, g, be, out, nullptr, nullptr);
}

// ---------------- launch -----------------------------------------------------
extern "C" void kernel_launch(void* const* d_in, const int* in_sizes, int n_in,
                              void* d_out, int out_size)
{
    const float* x1  = (const float*)d_in[0];
    const float* wm  = (const float*)d_in[1];
    const float* Wq  = (const float*)d_in[2];
    const float* bq  = (const float*)d_in[3];
    const float* Wk  = (const float*)d_in[4];
    const float* bk  = (const float*)d_in[5];
    const float* Wv  = (const float*)d_in[6];
    const float* bv  = (const float*)d_in[7];
    const float* g1  = (const float*)d_in[8];
    const float* be1 = (const float*)d_in[9];
    const float* g2  = (const float*)d_in[10];
    const float* be2 = (const float*)d_in[11];
    const float* W1  = (const float*)d_in[12];
    const float* b1  = (const float*)d_in[13];
    const float* W2  = (const float*)d_in[14];
    const float* b2  = (const float*)d_in[15];
    float* out = (float*)d_out;

    void *p_ah, *p_al, *p_fh, *p_fl, *p_w1h, *p_w1l, *p_w2h, *p_w2l;
    void *p_qkv, *p_bqkv, *p_ff2, *p_wqh, *p_wql;
    cudaGetSymbolAddress(&p_ah, g_ah);     cudaGetSymbolAddress(&p_al, g_al);
    cudaGetSymbolAddress(&p_fh, g_fh);     cudaGetSymbolAddress(&p_fl, g_fl);
    cudaGetSymbolAddress(&p_w1h, g_w1h);   cudaGetSymbolAddress(&p_w1l, g_w1l);
    cudaGetSymbolAddress(&p_w2h, g_w2h);   cudaGetSymbolAddress(&p_w2l, g_w2l);
    cudaGetSymbolAddress(&p_qkv, g_qkv);   cudaGetSymbolAddress(&p_bqkv, g_bqkv);
    cudaGetSymbolAddress(&p_ff2, g_ff2);
    cudaGetSymbolAddress(&p_wqh, g_wqkvh); cudaGetSymbolAddress(&p_wql, g_wqkvl);

    __nv_bfloat16* ah  = (__nv_bfloat16*)p_ah;
    __nv_bfloat16* al  = (__nv_bfloat16*)p_al;
    __nv_bfloat16* fh  = (__nv_bfloat16*)p_fh;
    __nv_bfloat16* fl  = (__nv_bfloat16*)p_fl;
    __nv_bfloat16* wqh = (__nv_bfloat16*)p_wqh;
    __nv_bfloat16* wql = (__nv_bfloat16*)p_wql;
    __nv_bfloat16* w1h = (__nv_bfloat16*)p_w1h;
    __nv_bfloat16* w1l = (__nv_bfloat16*)p_w1l;
    __nv_bfloat16* w2h = (__nv_bfloat16*)p_w2h;
    __nv_bfloat16* w2l = (__nv_bfloat16*)p_w2l;
    float* qkv  = (float*)p_qkv;
    float* bqkv = (float*)p_bqkv;
    float* ff2  = (float*)p_ff2;

    const int ATTN_SMEM = 4 * 64 * AS * (int)sizeof(float);  // 69632 B
    cudaFuncSetAttribute(attn_kernel,
                         cudaFuncAttributeMaxDynamicSharedMemorySize, ATTN_SMEM);
    cudaFuncSetAttribute(gemm_mma,
                         cudaFuncAttributeMaxDynamicSharedMemorySize, GEMM_SMEM);

    dim3 tb(32, 8);

    // 1..4: weight prep
    prep_bias<<<3, 256>>>(bq, bk, bv);
    transpose_qkv<<<dim3(HID/32, HID/32, 3), tb>>>(Wq, Wk, Wv);
    transpose_split<<<dim3(FF/32,  HID/32), tb>>>(W1, w1h, w1l, HID, FF);
    transpose_split<<<dim3(HID/32, FF/32),  tb>>>(W2, w2h, w2l, FF, HID);

    // 5: split x1
    convert_split<<<2048, 256>>>(x1, ah, al, ROWS * HID / 4);

    // 6: fused QKV GEMM  (ncu -s 5 -c 1 captures this launch)
    gemm_mma<<<dim3(NQKV/128, ROWS/128), 256, GEMM_SMEM>>>(
        ah, al, wqh, wql, bqkv, qkv, nullptr, nullptr, NQKV, HID, 0, 0);

    // 7: flash attention with post-softmax mask
    attn_kernel<<<dim3(SEQ/64, NHEAD, BATCH), 256, ATTN_SMEM>>>(wm);

    // 8: x = LN(ctx + q_mixed), fused bf16 split of x into g_ah/g_al
    ln1_kernel<<<ROWS, 256>>>(g1, be1);

    // 9: ff1 = relu(x @ W1 + b1) -> bf16 split into g_fh/g_fl (NO aliasing)
    gemm_mma<<<dim3(FF/128, ROWS/128), 256, GEMM_SMEM>>>(
        ah, al, w1h, w1l, b1, nullptr, fh, fl, FF, HID, 1, 1);

    // 10: ff2 = ff1 @ W2 + b2
    gemm_mma<<<dim3(HID/128, ROWS/128), 256, GEMM_SMEM>>>(
        fh, fl, w2h, w2l, b2, ff2, nullptr, nullptr, HID, FF, 0, 0);

    // 11: out = LN(x + ff2)
    ln2_kernel<<<ROWS, 256>>>(g2, be2, out);
}

// round 6
// speedup vs baseline: 2.3077x; 1.3473x over previous
#include <cuda_runtime.h>
#include <cuda_bf16.h>
#include <cstdint>
#include <math.h>

// Problem constants
#define BATCH 8
#define SEQ   1024
#define HID   768
#define NHEAD 12
#define DHEAD 64
#define ROWS  (BATCH*SEQ)          // 8192
#define FF    (2*HID)              // 1536
#define NQKV  (3*HID)              // 2304

// ---------------- scratch (device globals; no allocations allowed) ----------
__device__ float g_qkv[ROWS*NQKV];   // q | k | v  per row
__device__ float g_ctx[ROWS*HID];
__device__ float g_x  [ROWS*HID];
__device__ float g_ff2[ROWS*HID];
__device__ float g_bqkv[NQKV];

__device__ __nv_bfloat16 g_ah[ROWS*HID];     // x1 / x splits (GEMM A inputs)
__device__ __nv_bfloat16 g_al[ROWS*HID];
__device__ __nv_bfloat16 g_fh[ROWS*FF];      // ff1 splits (separate! no aliasing)
__device__ __nv_bfloat16 g_fl[ROWS*FF];
__device__ __nv_bfloat16 g_wqkvh[NQKV*HID];  // W^T split, rows = N, K-major
__device__ __nv_bfloat16 g_wqkvl[NQKV*HID];
__device__ __nv_bfloat16 g_w1h[FF*HID];
__device__ __nv_bfloat16 g_w1l[FF*HID];
__device__ __nv_bfloat16 g_w2h[HID*FF];
__device__ __nv_bfloat16 g_w2l[HID*FF];

// ---------------- PTX helpers (sm_80-era only; no 'a'-features) -------------
__device__ __forceinline__ uint32_t smem_u32(const void* p) {
    uint32_t a;
    asm("{ .reg .u64 t; cvta.to.shared.u64 t, %1; cvt.u32.u64 %0, t; }"
        : "=r"(a) : "l"(p));
    return a;
}

__device__ __forceinline__ void cp16(uint32_t dst, const void* src) {
    asm volatile("cp.async.cg.shared.global [%0], [%1], 16;"
                 :: "r"(dst), "l"(src));
}
#define CP_COMMIT() asm volatile("cp.async.commit_group;" ::: "memory")
#define CP_WAIT(n)  asm volatile("cp.async.wait_group %0;" :: "n"(n) : "memory")

__device__ __forceinline__ void ldsm4(uint32_t& r0, uint32_t& r1,
                                      uint32_t& r2, uint32_t& r3, uint32_t addr) {
    asm volatile("ldmatrix.sync.aligned.m8n8.x4.shared.b16 {%0,%1,%2,%3}, [%4];"
                 : "=r"(r0), "=r"(r1), "=r"(r2), "=r"(r3) : "r"(addr));
}

__device__ __forceinline__ void mma_bf16(float* c, const uint32_t* a, const uint32_t* b) {
    asm volatile("mma.sync.aligned.m16n8k16.row.col.f32.bf16.bf16.f32 "
                 "{%0,%1,%2,%3}, {%4,%5,%6,%7}, {%8,%9}, {%0,%1,%2,%3};"
                 : "+f"(c[0]), "+f"(c[1]), "+f"(c[2]), "+f"(c[3])
                 : "r"(a[0]), "r"(a[1]), "r"(a[2]), "r"(a[3]),
                   "r"(b[0]), "r"(b[1]));
}

// pack two fp32 into bf16x2 hi + residual-lo bf16x2
__device__ __forceinline__ void splitpack(float x, float y, uint32_t& h, uint32_t& l) {
    __nv_bfloat162 hh, ll;
    hh.x = __float2bfloat16(x); hh.y = __float2bfloat16(y);
    ll.x = __float2bfloat16(x - __bfloat162float(hh.x));
    ll.y = __float2bfloat16(y - __bfloat162float(hh.y));
    h = *(uint32_t*)&hh; l = *(uint32_t*)&ll;
}

// ---------------- prep kernels ----------------------------------------------
__global__ void prep_bias(const float* __restrict__ bq, const float* __restrict__ bk,
                          const float* __restrict__ bv) {
    int i = blockIdx.x * blockDim.x + threadIdx.x;
    if (i < HID) {
        g_bqkv[i]         = bq[i];
        g_bqkv[i + HID]   = bk[i];
        g_bqkv[i + 2*HID] = bv[i];
    }
}

// W[K,N] fp32 -> out[N,K] bf16 hi/lo (transpose + split)
__device__ __forceinline__ void tsp_body(const float* __restrict__ W,
                                         __nv_bfloat16* __restrict__ oh,
                                         __nv_bfloat16* __restrict__ ol,
                                         int K, int N) {
    __shared__ float t[32][33];
    const int tx = threadIdx.x, ty = threadIdx.y;
    const int n0 = blockIdx.x * 32, k0 = blockIdx.y * 32;
#pragma unroll
    for (int i = 0; i < 4; i++)
        t[ty + 8*i][tx] = W[(size_t)(k0 + ty + 8*i) * N + n0 + tx];
    __syncthreads();
#pragma unroll
    for (int i = 0; i < 4; i++) {
        float v = t[tx][ty + 8*i];
        __nv_bfloat16 h = __float2bfloat16(v);
        __nv_bfloat16 l = __float2bfloat16(v - __bfloat162float(h));
        size_t idx = (size_t)(n0 + ty + 8*i) * K + k0 + tx;
        oh[idx] = h;
        ol[idx] = l;
    }
}

__global__ void __launch_bounds__(256)
transpose_split(const float* __restrict__ W, __nv_bfloat16* __restrict__ oh,
                __nv_bfloat16* __restrict__ ol, int K, int N) {
    tsp_body(W, oh, ol, K, N);
}

__global__ void __launch_bounds__(256)
transpose_qkv(const float* __restrict__ Wq, const float* __restrict__ Wk,
              const float* __restrict__ Wv) {
    const float* W = (blockIdx.z == 0) ? Wq : (blockIdx.z == 1) ? Wk : Wv;
    tsp_body(W, g_wqkvh + (size_t)blockIdx.z * HID * HID,
                g_wqkvl + (size_t)blockIdx.z * HID * HID, HID, HID);
}

// fp32 -> bf16 hi/lo elementwise split
__global__ void __launch_bounds__(256)
convert_split(const float* __restrict__ in, __nv_bfloat16* __restrict__ oh,
              __nv_bfloat16* __restrict__ ol, int n4) {
    for (int i = blockIdx.x * blockDim.x + threadIdx.x; i < n4;
         i += gridDim.x * blockDim.x) {
        float4 a = ((const float4*)in)[i];
        uint32_t h0, l0, h1, l1;
        splitpack(a.x, a.y, h0, l0);
        splitpack(a.z, a.w, h1, l1);
        ((uint32_t*)oh)[2*i]   = h0;
        ((uint32_t*)oh)[2*i+1] = h1;
        ((uint32_t*)ol)[2*i]   = l0;
        ((uint32_t*)ol)[2*i+1] = l1;
    }
}

// ---------------- mma.sync bf16-split GEMM (4-stage cp.async ring) -----------
#define ASTR    40                           // halves per smem row (80 B)
#define STGB    (128 * ASTR * 2)             // bytes per tile per stage (10240)
#define STAGES  4
#define GEMM_SMEM (STAGES * 2 * STGB)        // 81920 B dynamic

__global__ void __launch_bounds__(256, 2)
gemm_mma(const __nv_bfloat16* __restrict__ Ah, const __nv_bfloat16* __restrict__ Al,
         const __nv_bfloat16* __restrict__ Bh, const __nv_bfloat16* __restrict__ Bl,
         const float* __restrict__ bias,
         float* __restrict__ Cf,
         __nv_bfloat16* __restrict__ Ch, __nv_bfloat16* __restrict__ Cl,
         int N, int K, int relu, int split_out)
{
    extern __shared__ __align__(16) char dsm[];
    __nv_bfloat16* smA = (__nv_bfloat16*)dsm;
    __nv_bfloat16* smB = (__nv_bfloat16*)(dsm + STAGES * STGB);

    const int tid  = threadIdx.x;
    const int wid  = tid >> 5, lane = tid & 31;
    const int warp_m = wid >> 2;
    const int warp_n = wid & 3;
    const int m0 = blockIdx.y << 7;
    const int n0 = blockIdx.x << 7;

    const uint32_t sA = smem_u32(smA);
    const uint32_t sB = smem_u32(smB);

    const int lrow  = tid >> 1;
    const int lcolh = (tid & 1) * 16;

    const int kb = K >> 5;
    const int NB = 3 * kb;

    float c[4][4][4];
#pragma unroll
    for (int i = 0; i < 4; i++)
#pragma unroll
        for (int j = 0; j < 4; j++)
#pragma unroll
            for (int r = 0; r < 4; r++) c[i][j][r] = 0.f;

    const int rowoff = ((lane >> 3) & 1) * 8 + (lane & 7);
    const int coloff = ((lane >> 4) & 1) * 8;

    auto issue = [&](int blk) {
        if (blk < NB) {
            int phase = blk / kb;
            int kk = blk - phase * kb;
            const __nv_bfloat16* As = (phase == 2) ? Al : Ah;
            const __nv_bfloat16* Bs = (phase == 1) ? Bl : Bh;
            const __nv_bfloat16* ga = As + (size_t)(m0 + lrow) * K + kk * 32 + lcolh;
            const __nv_bfloat16* gb = Bs + (size_t)(n0 + lrow) * K + kk * 32 + lcolh;
            int st = blk & (STAGES - 1);
            uint32_t da = sA + st * STGB + (lrow * ASTR + lcolh) * 2;
            uint32_t db = sB + st * STGB + (lrow * ASTR + lcolh) * 2;
            cp16(da,      ga);
            cp16(da + 16, ga + 8);
            cp16(db,      gb);
            cp16(db + 16, gb + 8);
        }
        CP_COMMIT();
    };

    issue(0); issue(1); issue(2);

    for (int blk = 0; blk < NB; blk++) {
        CP_WAIT(2);
        __syncthreads();

        const int stage = blk & (STAGES - 1);
        const uint32_t a0 = sA + stage * STGB;
        const uint32_t b0 = sB + stage * STGB;
#pragma unroll
        for (int kh = 0; kh < 2; kh++) {
            uint32_t af[4][4];
#pragma unroll
            for (int t = 0; t < 4; t++) {
                uint32_t addr = a0 + ((warp_m * 64 + t * 16 + rowoff) * ASTR
                                      + kh * 16 + coloff) * 2;
                ldsm4(af[t][0], af[t][1], af[t][2], af[t][3], addr);
            }
            uint32_t bf[4][2];
#pragma unroll
            for (int p = 0; p < 2; p++) {
                uint32_t r0, r1, r2, r3;
                uint32_t addr = b0 + ((warp_n * 32 + p * 16 + rowoff) * ASTR
                                      + kh * 16 + coloff) * 2;
                ldsm4(r0, r1, r2, r3, addr);
                bf[2*p][0]   = r0; bf[2*p][1]   = r2;
                bf[2*p+1][0] = r1; bf[2*p+1][1] = r3;
            }
#pragma unroll
            for (int i = 0; i < 4; i++)
#pragma unroll
                for (int j = 0; j < 4; j++)
                    mma_bf16(c[i][j], af[i], bf[j]);
        }
        issue(blk + 3);
    }

#pragma unroll
    for (int i = 0; i < 4; i++) {
#pragma unroll
        for (int j = 0; j < 4; j++) {
            int grow = m0 + warp_m * 64 + i * 16 + (lane >> 2);
            int gcol = n0 + warp_n * 32 + j * 8 + (lane & 3) * 2;
            float b0v = bias[gcol], b1v = bias[gcol + 1];
            float v0 = c[i][j][0] + b0v;
            float v1 = c[i][j][1] + b1v;
            float v2 = c[i][j][2] + b0v;
            float v3 = c[i][j][3] + b1v;
            if (relu) {
                v0 = fmaxf(v0, 0.f); v1 = fmaxf(v1, 0.f);
                v2 = fmaxf(v2, 0.f); v3 = fmaxf(v3, 0.f);
            }
            if (split_out) {
                uint32_t h0, l0, h1, l1;
                splitpack(v0, v1, h0, l0);
                splitpack(v2, v3, h1, l1);
                *(uint32_t*)(Ch + (size_t)grow * N + gcol)       = h0;
                *(uint32_t*)(Ch + (size_t)(grow + 8) * N + gcol) = h1;
                *(uint32_t*)(Cl + (size_t)grow * N + gcol)       = l0;
                *(uint32_t*)(Cl + (size_t)(grow + 8) * N + gcol) = l1;
            } else {
                *(float2*)(Cf + (size_t)grow * N + gcol)       = make_float2(v0, v1);
                *(float2*)(Cf + (size_t)(grow + 8) * N + gcol) = make_float2(v2, v3);
            }
        }
    }
}

// ---------------- tensor-core flash attention (split-bf16, post-softmax mask)
// 256 threads, 8 warps; q-tile 128 rows (16 per warp); k-tile 64.
// Q/K in smem [row][d] split hi/lo; V stored TRANSPOSED [d][kcol] split hi/lo
// so PV uses the same proven non-trans ldmatrix B pattern as the GEMM.
#define QT 128
#define KTILE 64
#define SQ 72                                  // smem stride (halves), ldsm conflict-free
#define ATTN_SMEM ((2*QT + 4*KTILE) * SQ * 2)  // 73728 B

__global__ void __launch_bounds__(256)
attn_mma(const float* __restrict__ wm)
{
    extern __shared__ __align__(16) __nv_bfloat16 am_[];
    __nv_bfloat16* qh = am_;
    __nv_bfloat16* ql = qh + QT * SQ;
    __nv_bfloat16* kh = ql + QT * SQ;
    __nv_bfloat16* kl = kh + KTILE * SQ;
    __nv_bfloat16* vh = kl + KTILE * SQ;   // [d][kcol]
    __nv_bfloat16* vl = vh + KTILE * SQ;

    const int tid = threadIdx.x, wid = tid >> 5, lane = tid & 31;
    const int b = blockIdx.z, h = blockIdx.y, q0 = blockIdx.x * QT;

    const uint32_t sqh = smem_u32(qh), sql = smem_u32(ql);
    const uint32_t skh = smem_u32(kh), skl = smem_u32(kl);
    const uint32_t svh = smem_u32(vh), svl = smem_u32(vl);

    // ---- load Q (scaled by 1/8) and split into smem ----
    {
        const int row = tid >> 1, cb = (tid & 1) * 32;
        const float* src = g_qkv + (size_t)(b * SEQ + q0 + row) * NQKV + h * DHEAD + cb;
#pragma unroll
        for (int f = 0; f < 8; f++) {
            float4 v = *(const float4*)(src + 4 * f);
            v.x *= 0.125f; v.y *= 0.125f; v.z *= 0.125f; v.w *= 0.125f;
            uint32_t h0, l0, h1, l1;
            splitpack(v.x, v.y, h0, l0);
            splitpack(v.z, v.w, h1, l1);
            int base = row * SQ + cb + 4 * f;
            *(uint32_t*)(qh + base)     = h0;
            *(uint32_t*)(qh + base + 2) = h1;
            *(uint32_t*)(ql + base)     = l0;
            *(uint32_t*)(ql + base + 2) = l1;
        }
    }

    // ---- K/V prefetch registers ----
    const int krow = tid >> 2, kcb = (tid & 3) * 16;
    float4 rk[4], rv[4];
    {
        const float* kp = g_qkv + (size_t)(b * SEQ + krow) * NQKV + HID + h * DHEAD + kcb;
#pragma unroll
        for (int f = 0; f < 4; f++) {
            rk[f] = *(const float4*)(kp + 4 * f);
            rv[f] = *(const float4*)(kp + HID + 4 * f);
        }
    }

    float m0 = -1e30f, m1 = -1e30f, l0 = 0.f, l1 = 0.f;
    float o[8][4];
#pragma unroll
    for (int j = 0; j < 8; j++)
#pragma unroll
        for (int r = 0; r < 4; r++) o[j][r] = 0.f;

    const int rowoff = ((lane >> 3) & 1) * 8 + (lane & 7);
    const int coloff = (lane >> 4) * 8;
    const int rA = q0 + wid * 16 + (lane >> 2);

    for (int kt = 0; kt < 16; kt++) {
        __syncthreads();
        // ---- stage K (row-major) and V (transposed) split into smem ----
#pragma unroll
        for (int f = 0; f < 4; f++) {
            int c = kcb + 4 * f;
            uint32_t h0, lo0, h1, lo1;
            splitpack(rk[f].x, rk[f].y, h0, lo0);
            splitpack(rk[f].z, rk[f].w, h1, lo1);
            int base = krow * SQ + c;
            *(uint32_t*)(kh + base)     = h0;
            *(uint32_t*)(kh + base + 2) = h1;
            *(uint32_t*)(kl + base)     = lo0;
            *(uint32_t*)(kl + base + 2) = lo1;
            float vv[4] = {rv[f].x, rv[f].y, rv[f].z, rv[f].w};
#pragma unroll
            for (int e = 0; e < 4; e++) {
                __nv_bfloat16 hb = __float2bfloat16(vv[e]);
                __nv_bfloat16 lb = __float2bfloat16(vv[e] - __bfloat162float(hb));
                vh[(c + e) * SQ + krow] = hb;
                vl[(c + e) * SQ + krow] = lb;
            }
        }
        __syncthreads();
        // prefetch next K/V
        if (kt < 15) {
            const float* kp = g_qkv + (size_t)(b * SEQ + (kt + 1) * KTILE + krow) * NQKV
                              + HID + h * DHEAD + kcb;
#pragma unroll
            for (int f = 0; f < 4; f++) {
                rk[f] = *(const float4*)(kp + 4 * f);
                rv[f] = *(const float4*)(kp + HID + 4 * f);
            }
        }
        // prefetch mask tile (used after QK MMAs)
        float2 mk0[8], mk1[8];
        {
            const float* mr0 = wm + ((size_t)b * SEQ + rA) * SEQ + kt * KTILE + (lane & 3) * 2;
            const float* mr1 = mr0 + 8 * SEQ;
#pragma unroll
            for (int j = 0; j < 8; j++) {
                mk0[j] = *(const float2*)(mr0 + 8 * j);
                mk1[j] = *(const float2*)(mr1 + 8 * j);
            }
        }

        // ---- QK^T scores (3-pass split) ----
        float s[8][4];
#pragma unroll
        for (int j = 0; j < 8; j++)
#pragma unroll
            for (int r = 0; r < 4; r++) s[j][r] = 0.f;

#pragma unroll
        for (int t = 0; t < 4; t++) {
            uint32_t ah[4], al4[4];
            uint32_t qaddr = sqh + ((wid * 16 + rowoff) * SQ + t * 16 + coloff) * 2;
            ldsm4(ah[0], ah[1], ah[2], ah[3], qaddr);
            ldsm4(al4[0], al4[1], al4[2], al4[3],
                  sql + ((wid * 16 + rowoff) * SQ + t * 16 + coloff) * 2);
#pragma unroll
            for (int p = 0; p < 4; p++) {
                uint32_t h0, h1, h2, h3, g0, g1, g2, g3;
                uint32_t kaddr = ((p * 16 + rowoff) * SQ + t * 16 + coloff) * 2;
                ldsm4(h0, h1, h2, h3, skh + kaddr);
                ldsm4(g0, g1, g2, g3, skl + kaddr);
                uint32_t bh0[2] = {h0, h2}, bh1[2] = {h1, h3};
                uint32_t bl0[2] = {g0, g2}, bl1[2] = {g1, g3};
                mma_bf16(s[2*p],   ah,  bh0);
                mma_bf16(s[2*p],   ah,  bl0);
                mma_bf16(s[2*p],   al4, bh0);
                mma_bf16(s[2*p+1], ah,  bh1);
                mma_bf16(s[2*p+1], ah,  bl1);
                mma_bf16(s[2*p+1], al4, bh1);
            }
        }

        // ---- online softmax (denominator UNmasked), then mask ----
        float lm0 = -1e30f, lm1 = -1e30f;
#pragma unroll
        for (int j = 0; j < 8; j++) {
            lm0 = fmaxf(lm0, fmaxf(s[j][0], s[j][1]));
            lm1 = fmaxf(lm1, fmaxf(s[j][2], s[j][3]));
        }
        lm0 = fmaxf(lm0, __shfl_xor_sync(0xffffffffu, lm0, 1));
        lm0 = fmaxf(lm0, __shfl_xor_sync(0xffffffffu, lm0, 2));
        lm1 = fmaxf(lm1, __shfl_xor_sync(0xffffffffu, lm1, 1));
        lm1 = fmaxf(lm1, __shfl_xor_sync(0xffffffffu, lm1, 2));
        float mn0 = fmaxf(m0, lm0), mn1 = fmaxf(m1, lm1);
        float f0 = __expf(m0 - mn0), f1 = __expf(m1 - mn1);
        m0 = mn0; m1 = mn1;
        float ls0 = 0.f, ls1 = 0.f;
#pragma unroll
        for (int j = 0; j < 8; j++) {
            float e0 = __expf(s[j][0] - mn0);
            float e1 = __expf(s[j][1] - mn0);
            float e2 = __expf(s[j][2] - mn1);
            float e3 = __expf(s[j][3] - mn1);
            ls0 += e0 + e1; ls1 += e2 + e3;
            s[j][0] = e0 * mk0[j].x;
            s[j][1] = e1 * mk0[j].y;
            s[j][2] = e2 * mk1[j].x;
            s[j][3] = e3 * mk1[j].y;
        }
        ls0 += __shfl_xor_sync(0xffffffffu, ls0, 1);
        ls0 += __shfl_xor_sync(0xffffffffu, ls0, 2);
        ls1 += __shfl_xor_sync(0xffffffffu, ls1, 1);
        ls1 += __shfl_xor_sync(0xffffffffu, ls1, 2);
        l0 = l0 * f0 + ls0;
        l1 = l1 * f1 + ls1;
#pragma unroll
        for (int j = 0; j < 8; j++) {
            o[j][0] *= f0; o[j][1] *= f0;
            o[j][2] *= f1; o[j][3] *= f1;
        }

        // ---- PV (3-pass split); V^T in smem -> proven non-trans B pattern ----
#pragma unroll
        for (int u = 0; u < 4; u++) {
            uint32_t pah[4], pal[4];
            splitpack(s[2*u][0],   s[2*u][1],   pah[0], pal[0]);
            splitpack(s[2*u][2],   s[2*u][3],   pah[1], pal[1]);
            splitpack(s[2*u+1][0], s[2*u+1][1], pah[2], pal[2]);
            splitpack(s[2*u+1][2], s[2*u+1][3], pah[3], pal[3]);
#pragma unroll
            for (int p = 0; p < 4; p++) {
                uint32_t h0, h1, h2, h3, g0, g1, g2, g3;
                uint32_t vaddr = ((p * 16 + rowoff) * SQ + u * 16 + coloff) * 2;
                ldsm4(h0, h1, h2, h3, svh + vaddr);
                ldsm4(g0, g1, g2, g3, svl + vaddr);
                uint32_t bh0[2] = {h0, h2}, bh1[2] = {h1, h3};
                uint32_t bl0[2] = {g0, g2}, bl1[2] = {g1, g3};
                mma_bf16(o[2*p],   pah, bh0);
                mma_bf16(o[2*p],   pah, bl0);
                mma_bf16(o[2*p],   pal, bh0);
                mma_bf16(o[2*p+1], pah, bh1);
                mma_bf16(o[2*p+1], pah, bl1);
                mma_bf16(o[2*p+1], pal, bh1);
            }
        }
    }

    // ---- epilogue: divide by unmasked denominator, store ctx ----
    float inv0 = 1.0f / l0, inv1 = 1.0f / l1;
    float* c0 = g_ctx + ((size_t)(b * SEQ) + rA) * HID + h * DHEAD + (lane & 3) * 2;
    float* c1 = c0 + 8 * HID;
#pragma unroll
    for (int j = 0; j < 8; j++) {
        *(float2*)(c0 + 8 * j) = make_float2(o[j][0] * inv0, o[j][1] * inv0);
        *(float2*)(c1 + 8 * j) = make_float2(o[j][2] * inv1, o[j][3] * inv1);
    }
}

// ---------------- fused residual-add + LayerNorm (two-pass) -----------------
template<bool SPLIT>
__device__ __forceinline__ void addln_body(const float* __restrict__ A, int sA,
                                           const float* __restrict__ Bv, int sB,
                                           const float* __restrict__ g,
                                           const float* __restrict__ be,
                                           float* __restrict__ out,
                                           __nv_bfloat16* __restrict__ oh,
                                           __nv_bfloat16* __restrict__ ol)
{
    const int row = blockIdx.x;
    const int tid = threadIdx.x;
    __shared__ float red[8];
    __shared__ float s_mu, s_rs;

    float4 v4 = make_float4(0.f, 0.f, 0.f, 0.f);
    float ls = 0.f;
    if (tid < 192) {
        float4 av = ((const float4*)(A  + (size_t)row * sA))[tid];
        float4 bv = ((const float4*)(Bv + (size_t)row * sB))[tid];
        v4 = make_float4(av.x + bv.x, av.y + bv.y, av.z + bv.z, av.w + bv.w);
        ls = v4.x + v4.y + v4.z + v4.w;
    }
    int lane = tid & 31, wid = tid >> 5;
#pragma unroll
    for (int o = 16; o; o >>= 1) ls += __shfl_xor_sync(0xffffffffu, ls, o);
    if (lane == 0) red[wid] = ls;
    __syncthreads();
    if (tid == 0) {
        float t = 0.f;
#pragma unroll
        for (int i = 0; i < 8; i++) t += red[i];
        s_mu = t * (1.0f / HID);
    }
    __syncthreads();
    float mu = s_mu;

    float4 dx = make_float4(v4.x - mu, v4.y - mu, v4.z - mu, v4.w - mu);
    float lv = 0.f;
    if (tid < 192)
        lv = dx.x * dx.x + dx.y * dx.y + dx.z * dx.z + dx.w * dx.w;
#pragma unroll
    for (int o = 16; o; o >>= 1) lv += __shfl_xor_sync(0xffffffffu, lv, o);
    __syncthreads();
    if (lane == 0) red[wid] = lv;
    __syncthreads();
    if (tid == 0) {
        float t = 0.f;
#pragma unroll
        for (int i = 0; i < 8; i++) t += red[i];
        s_rs = rsqrtf(t * (1.0f / HID) + 1e-5f);
    }
    __syncthreads();
    float rs = s_rs;

    if (tid < 192) {
        float4 g4  = ((const float4*)g)[tid];
        float4 be4 = ((const float4*)be)[tid];
        float4 o = make_float4(dx.x * rs * g4.x + be4.x,
                               dx.y * rs * g4.y + be4.y,
                               dx.z * rs * g4.z + be4.z,
                               dx.w * rs * g4.w + be4.w);
        ((float4*)(out + (size_t)row * HID))[tid] = o;
        if (SPLIT) {
            uint32_t h0, l0, h1, l1;
            splitpack(o.x, o.y, h0, l0);
            splitpack(o.z, o.w, h1, l1);
            ((uint32_t*)(oh + (size_t)row * HID))[2*tid]   = h0;
            ((uint32_t*)(oh + (size_t)row * HID))[2*tid+1] = h1;
            ((uint32_t*)(ol + (size_t)row * HID))[2*tid]   = l0;
            ((uint32_t*)(ol + (size_t)row * HID))[2*tid+1] = l1;
        }
    }
}

__global__ void __launch_bounds__(256)
ln1_kernel(const float* __restrict__ g, const float* __restrict__ be)
{
    addln_body<true>(g_ctx, HID, g_qkv, NQKV, g, be, g_x, g_ah, g_al);
}

__global__ void __launch_bounds__(256)
ln2_kernel(const float* __restrict__ g, const float* __restrict__ be,
           float* __restrict__ out)
{
    addln_body<false>(g_x, HID, g_ff2, HID, g, be, out, nullptr, nullptr);
}

// ---------------- launch -----------------------------------------------------
extern "C" void kernel_launch(void* const* d_in, const int* in_sizes, int n_in,
                              void* d_out, int out_size)
{
    const float* x1  = (const float*)d_in[0];
    const float* wm  = (const float*)d_in[1];
    const float* Wq  = (const float*)d_in[2];
    const float* bq  = (const float*)d_in[3];
    const float* Wk  = (const float*)d_in[4];
    const float* bk  = (const float*)d_in[5];
    const float* Wv  = (const float*)d_in[6];
    const float* bv  = (const float*)d_in[7];
    const float* g1  = (const float*)d_in[8];
    const float* be1 = (const float*)d_in[9];
    const float* g2  = (const float*)d_in[10];
    const float* be2 = (const float*)d_in[11];
    const float* W1  = (const float*)d_in[12];
    const float* b1  = (const float*)d_in[13];
    const float* W2  = (const float*)d_in[14];
    const float* b2  = (const float*)d_in[15];
    float* out = (float*)d_out;

    void *p_ah, *p_al, *p_fh, *p_fl, *p_w1h, *p_w1l, *p_w2h, *p_w2l;
    void *p_qkv, *p_bqkv, *p_ff2, *p_wqh, *p_wql;
    cudaGetSymbolAddress(&p_ah, g_ah);     cudaGetSymbolAddress(&p_al, g_al);
    cudaGetSymbolAddress(&p_fh, g_fh);     cudaGetSymbolAddress(&p_fl, g_fl);
    cudaGetSymbolAddress(&p_w1h, g_w1h);   cudaGetSymbolAddress(&p_w1l, g_w1l);
    cudaGetSymbolAddress(&p_w2h, g_w2h);   cudaGetSymbolAddress(&p_w2l, g_w2l);
    cudaGetSymbolAddress(&p_qkv, g_qkv);   cudaGetSymbolAddress(&p_bqkv, g_bqkv);
    cudaGetSymbolAddress(&p_ff2, g_ff2);
    cudaGetSymbolAddress(&p_wqh, g_wqkvh); cudaGetSymbolAddress(&p_wql, g_wqkvl);

    __nv_bfloat16* ah  = (__nv_bfloat16*)p_ah;
    __nv_bfloat16* al  = (__nv_bfloat16*)p_al;
    __nv_bfloat16* fh  = (__nv_bfloat16*)p_fh;
    __nv_bfloat16* fl  = (__nv_bfloat16*)p_fl;
    __nv_bfloat16* wqh = (__nv_bfloat16*)p_wqh;
    __nv_bfloat16* wql = (__nv_bfloat16*)p_wql;
    __nv_bfloat16* w1h = (__nv_bfloat16*)p_w1h;
    __nv_bfloat16* w1l = (__nv_bfloat16*)p_w1l;
    __nv_bfloat16* w2h = (__nv_bfloat16*)p_w2h;
    __nv_bfloat16* w2l = (__nv_bfloat16*)p_w2l;
    float* qkv  = (float*)p_qkv;
    float* bqkv = (float*)p_bqkv;
    float* ff2  = (float*)p_ff2;

    cudaFuncSetAttribute(attn_mma,
                         cudaFuncAttributeMaxDynamicSharedMemorySize, ATTN_SMEM);
    cudaFuncSetAttribute(gemm_mma,
                         cudaFuncAttributeMaxDynamicSharedMemorySize, GEMM_SMEM);

    dim3 tb(32, 8);

    // weight prep
    prep_bias<<<3, 256>>>(bq, bk, bv);
    transpose_qkv<<<dim3(HID/32, HID/32, 3), tb>>>(Wq, Wk, Wv);
    transpose_split<<<dim3(FF/32,  HID/32), tb>>>(W1, w1h, w1l, HID, FF);
    transpose_split<<<dim3(HID/32, FF/32),  tb>>>(W2, w2h, w2l, FF, HID);

    // split x1
    convert_split<<<2048, 256>>>(x1, ah, al, ROWS * HID / 4);

    // fused QKV GEMM
    gemm_mma<<<dim3(NQKV/128, ROWS/128), 256, GEMM_SMEM>>>(
        ah, al, wqh, wql, bqkv, qkv, nullptr, nullptr, NQKV, HID, 0, 0);

    // tensor-core flash attention with post-softmax mask
    attn_mma<<<dim3(SEQ/QT, NHEAD, BATCH), 256, ATTN_SMEM>>>(wm);

    // x = LN(ctx + q_mixed), fused bf16 split of x into g_ah/g_al
    ln1_kernel<<<ROWS, 256>>>(g1, be1);

    // ff1 = relu(x @ W1 + b1) -> bf16 split into g_fh/g_fl (no aliasing)
    gemm_mma<<<dim3(FF/128, ROWS/128), 256, GEMM_SMEM>>>(
        ah, al, w1h, w1l, b1, nullptr, fh, fl, FF, HID, 1, 1);

    // ff2 = ff1 @ W2 + b2
    gemm_mma<<<dim3(HID/128, ROWS/128), 256, GEMM_SMEM>>>(
        fh, fl, w2h, w2l, b2, ff2, nullptr, nullptr, HID, FF, 0, 0);

    // out = LN(x + ff2)
    ln2_kernel<<<ROWS, 256>>>(g2, be2, out);
}

// round 7
// speedup vs baseline: 2.4199x; 1.0486x over previous
#include <cuda_runtime.h>
#include <cuda_bf16.h>
#include <cstdint>
#include <math.h>

// Problem constants
#define BATCH 8
#define SEQ   1024
#define HID   768
#define NHEAD 12
#define DHEAD 64
#define ROWS  (BATCH*SEQ)          // 8192
#define FF    (2*HID)              // 1536
#define NQKV  (3*HID)              // 2304

// ---------------- scratch (device globals; no allocations allowed) ----------
__device__ float g_qkv[ROWS*NQKV];   // q | k | v  per row
__device__ float g_ctx[ROWS*HID];
__device__ float g_x  [ROWS*HID];
__device__ float g_ff2[ROWS*HID];
__device__ float g_bqkv[NQKV];

__device__ __nv_bfloat16 g_ah[ROWS*HID];     // x1 / x splits (GEMM A inputs)
__device__ __nv_bfloat16 g_al[ROWS*HID];
__device__ __nv_bfloat16 g_fh[ROWS*FF];      // ff1 splits (separate! no aliasing)
__device__ __nv_bfloat16 g_fl[ROWS*FF];
__device__ __nv_bfloat16 g_wqkvh[NQKV*HID];  // W^T split, rows = N, K-major
__device__ __nv_bfloat16 g_wqkvl[NQKV*HID];
__device__ __nv_bfloat16 g_w1h[FF*HID];
__device__ __nv_bfloat16 g_w1l[FF*HID];
__device__ __nv_bfloat16 g_w2h[HID*FF];
__device__ __nv_bfloat16 g_w2l[HID*FF];

// ---------------- PTX helpers (sm_80-era only; no 'a'-features) -------------
__device__ __forceinline__ uint32_t smem_u32(const void* p) {
    uint32_t a;
    asm("{ .reg .u64 t; cvta.to.shared.u64 t, %1; cvt.u32.u64 %0, t; }"
        : "=r"(a) : "l"(p));
    return a;
}

__device__ __forceinline__ void cp16(uint32_t dst, const void* src) {
    asm volatile("cp.async.cg.shared.global [%0], [%1], 16;"
                 :: "r"(dst), "l"(src));
}
#define CP_COMMIT() asm volatile("cp.async.commit_group;" ::: "memory")
#define CP_WAIT(n)  asm volatile("cp.async.wait_group %0;" :: "n"(n) : "memory")

__device__ __forceinline__ void ldsm4(uint32_t& r0, uint32_t& r1,
                                      uint32_t& r2, uint32_t& r3, uint32_t addr) {
    asm volatile("ldmatrix.sync.aligned.m8n8.x4.shared.b16 {%0,%1,%2,%3}, [%4];"
                 : "=r"(r0), "=r"(r1), "=r"(r2), "=r"(r3) : "r"(addr));
}

__device__ __forceinline__ void mma_bf16(float* c, const uint32_t* a, const uint32_t* b) {
    asm volatile("mma.sync.aligned.m16n8k16.row.col.f32.bf16.bf16.f32 "
                 "{%0,%1,%2,%3}, {%4,%5,%6,%7}, {%8,%9}, {%0,%1,%2,%3};"
                 : "+f"(c[0]), "+f"(c[1]), "+f"(c[2]), "+f"(c[3])
                 : "r"(a[0]), "r"(a[1]), "r"(a[2]), "r"(a[3]),
                   "r"(b[0]), "r"(b[1]));
}

// pack two fp32 into bf16x2 hi + residual-lo bf16x2
__device__ __forceinline__ void splitpack(float x, float y, uint32_t& h, uint32_t& l) {
    __nv_bfloat162 hh, ll;
    hh.x = __float2bfloat16(x); hh.y = __float2bfloat16(y);
    ll.x = __float2bfloat16(x - __bfloat162float(hh.x));
    ll.y = __float2bfloat16(y - __bfloat162float(hh.y));
    h = *(uint32_t*)&hh; l = *(uint32_t*)&ll;
}

// ---------------- prep kernels ----------------------------------------------
__global__ void prep_bias(const float* __restrict__ bq, const float* __restrict__ bk,
                          const float* __restrict__ bv) {
    int i = blockIdx.x * blockDim.x + threadIdx.x;
    if (i < HID) {
        g_bqkv[i]         = bq[i];
        g_bqkv[i + HID]   = bk[i];
        g_bqkv[i + 2*HID] = bv[i];
    }
}

// W[K,N] fp32 -> out[N,K] bf16 hi/lo (transpose + split)
__device__ __forceinline__ void tsp_body(const float* __restrict__ W,
                                         __nv_bfloat16* __restrict__ oh,
                                         __nv_bfloat16* __restrict__ ol,
                                         int K, int N) {
    __shared__ float t[32][33];
    const int tx = threadIdx.x, ty = threadIdx.y;
    const int n0 = blockIdx.x * 32, k0 = blockIdx.y * 32;
#pragma unroll
    for (int i = 0; i < 4; i++)
        t[ty + 8*i][tx] = W[(size_t)(k0 + ty + 8*i) * N + n0 + tx];
    __syncthreads();
#pragma unroll
    for (int i = 0; i < 4; i++) {
        float v = t[tx][ty + 8*i];
        __nv_bfloat16 h = __float2bfloat16(v);
        __nv_bfloat16 l = __float2bfloat16(v - __bfloat162float(h));
        size_t idx = (size_t)(n0 + ty + 8*i) * K + k0 + tx;
        oh[idx] = h;
        ol[idx] = l;
    }
}

__global__ void __launch_bounds__(256)
transpose_split(const float* __restrict__ W, __nv_bfloat16* __restrict__ oh,
                __nv_bfloat16* __restrict__ ol, int K, int N) {
    tsp_body(W, oh, ol, K, N);
}

__global__ void __launch_bounds__(256)
transpose_qkv(const float* __restrict__ Wq, const float* __restrict__ Wk,
              const float* __restrict__ Wv) {
    const float* W = (blockIdx.z == 0) ? Wq : (blockIdx.z == 1) ? Wk : Wv;
    tsp_body(W, g_wqkvh + (size_t)blockIdx.z * HID * HID,
                g_wqkvl + (size_t)blockIdx.z * HID * HID, HID, HID);
}

// fp32 -> bf16 hi/lo elementwise split
__global__ void __launch_bounds__(256)
convert_split(const float* __restrict__ in, __nv_bfloat16* __restrict__ oh,
              __nv_bfloat16* __restrict__ ol, int n4) {
    for (int i = blockIdx.x * blockDim.x + threadIdx.x; i < n4;
         i += gridDim.x * blockDim.x) {
        float4 a = ((const float4*)in)[i];
        uint32_t h0, l0, h1, l1;
        splitpack(a.x, a.y, h0, l0);
        splitpack(a.z, a.w, h1, l1);
        ((uint32_t*)oh)[2*i]   = h0;
        ((uint32_t*)oh)[2*i+1] = h1;
        ((uint32_t*)ol)[2*i]   = l0;
        ((uint32_t*)ol)[2*i+1] = l1;
    }
}

// ---------------- fused-pass mma.sync bf16-split GEMM ------------------------
// C = (Ah+Al)(Bh+Bl)^T + bias. 128x128 tile/CTA, K-step 32. All three split
// products (AhBh, AhBl, AlBh) computed per k-block with Ah/Bh fragments
// REUSED in registers; stages hold all 4 tiles (Ah,Al,Bh,Bl).
#define ASTR    40                           // halves per smem row (80 B)
#define TB      (128 * ASTR * 2)             // bytes per tile (10240)
#define GEMM_SMEM (2 * 4 * TB)               // 2 stages x 4 tiles = 81920 B

__global__ void __launch_bounds__(256, 2)
gemm_mma(const __nv_bfloat16* __restrict__ Ah, const __nv_bfloat16* __restrict__ Al,
         const __nv_bfloat16* __restrict__ Bh, const __nv_bfloat16* __restrict__ Bl,
         const float* __restrict__ bias,
         float* __restrict__ Cf,
         __nv_bfloat16* __restrict__ Ch, __nv_bfloat16* __restrict__ Cl,
         int N, int K, int relu, int split_out)
{
    extern __shared__ __align__(16) char dsm[];

    const int tid  = threadIdx.x;
    const int wid  = tid >> 5, lane = tid & 31;
    const int warp_m = wid >> 2;
    const int warp_n = wid & 3;
    const int m0 = blockIdx.y << 7;
    const int n0 = blockIdx.x << 7;

    const uint32_t sb = smem_u32(dsm);

    const int lrow  = tid >> 1;
    const int lcolh = (tid & 1) * 16;

    const int kb = K >> 5;                // 32-wide K blocks

    float c[4][4][4];
#pragma unroll
    for (int i = 0; i < 4; i++)
#pragma unroll
        for (int j = 0; j < 4; j++)
#pragma unroll
            for (int r = 0; r < 4; r++) c[i][j][r] = 0.f;

    const int rowoff = ((lane >> 3) & 1) * 8 + (lane & 7);
    const int coloff = ((lane >> 4) & 1) * 8;
    const uint32_t soff = (lrow * ASTR + lcolh) * 2;

    auto issue = [&](int blk) {
        if (blk < kb) {
            const size_t ao = (size_t)(m0 + lrow) * K + blk * 32 + lcolh;
            const size_t bo = (size_t)(n0 + lrow) * K + blk * 32 + lcolh;
            uint32_t st = sb + (uint32_t)(blk & 1) * (4 * TB) + soff;
            cp16(st,           Ah + ao);
            cp16(st + 16,      Ah + ao + 8);
            cp16(st + TB,      Al + ao);
            cp16(st + TB + 16, Al + ao + 8);
            cp16(st + 2*TB,      Bh + bo);
            cp16(st + 2*TB + 16, Bh + bo + 8);
            cp16(st + 3*TB,      Bl + bo);
            cp16(st + 3*TB + 16, Bl + bo + 8);
        }
        CP_COMMIT();
    };

    issue(0); issue(1);

    for (int blk = 0; blk < kb; blk++) {
        CP_WAIT(1);
        __syncthreads();

        const uint32_t s0 = sb + (uint32_t)(blk & 1) * (4 * TB);
#pragma unroll
        for (int kh = 0; kh < 2; kh++) {
            const uint32_t arow = ((warp_m * 64 + rowoff) * ASTR + kh * 16 + coloff) * 2;
            const uint32_t brow = ((warp_n * 32 + rowoff) * ASTR + kh * 16 + coloff) * 2;

            // Ah fragments (reused across pass 1 and 2)
            uint32_t ah4[4][4];
#pragma unroll
            for (int t = 0; t < 4; t++)
                ldsm4(ah4[t][0], ah4[t][1], ah4[t][2], ah4[t][3],
                      s0 + arow + (uint32_t)(t * 16 * ASTR) * 2);
            // Bh fragments (reused across pass 1 and 3)
            uint32_t bh[4][2];
#pragma unroll
            for (int p = 0; p < 2; p++) {
                uint32_t r0, r1, r2, r3;
                ldsm4(r0, r1, r2, r3,
                      s0 + 2*TB + brow + (uint32_t)(p * 16 * ASTR) * 2);
                bh[2*p][0]   = r0; bh[2*p][1]   = r2;
                bh[2*p+1][0] = r1; bh[2*p+1][1] = r3;
            }
            // pass 1: Ah * Bh
#pragma unroll
            for (int i = 0; i < 4; i++)
#pragma unroll
                for (int j = 0; j < 4; j++)
                    mma_bf16(c[i][j], ah4[i], bh[j]);

            // pass 2: Ah * Bl (load Bl just-in-time)
            {
                uint32_t bl[4][2];
#pragma unroll
                for (int p = 0; p < 2; p++) {
                    uint32_t r0, r1, r2, r3;
                    ldsm4(r0, r1, r2, r3,
                          s0 + 3*TB + brow + (uint32_t)(p * 16 * ASTR) * 2);
                    bl[2*p][0]   = r0; bl[2*p][1]   = r2;
                    bl[2*p+1][0] = r1; bl[2*p+1][1] = r3;
                }
#pragma unroll
                for (int i = 0; i < 4; i++)
#pragma unroll
                    for (int j = 0; j < 4; j++)
                        mma_bf16(c[i][j], ah4[i], bl[j]);
            }
            // pass 3: Al * Bh (load Al just-in-time)
            {
                uint32_t al4[4][4];
#pragma unroll
                for (int t = 0; t < 4; t++)
                    ldsm4(al4[t][0], al4[t][1], al4[t][2], al4[t][3],
                          s0 + TB + arow + (uint32_t)(t * 16 * ASTR) * 2);
#pragma unroll
                for (int i = 0; i < 4; i++)
#pragma unroll
                    for (int j = 0; j < 4; j++)
                        mma_bf16(c[i][j], al4[i], bh[j]);
            }
        }
        __syncthreads();
        issue(blk + 2);
    }

    // epilogue: bias (+relu), then fp32 or bf16-split stores
#pragma unroll
    for (int i = 0; i < 4; i++) {
#pragma unroll
        for (int j = 0; j < 4; j++) {
            int grow = m0 + warp_m * 64 + i * 16 + (lane >> 2);
            int gcol = n0 + warp_n * 32 + j * 8 + (lane & 3) * 2;
            float b0v = bias[gcol], b1v = bias[gcol + 1];
            float v0 = c[i][j][0] + b0v;
            float v1 = c[i][j][1] + b1v;
            float v2 = c[i][j][2] + b0v;
            float v3 = c[i][j][3] + b1v;
            if (relu) {
                v0 = fmaxf(v0, 0.f); v1 = fmaxf(v1, 0.f);
                v2 = fmaxf(v2, 0.f); v3 = fmaxf(v3, 0.f);
            }
            if (split_out) {
                uint32_t h0, l0, h1, l1;
                splitpack(v0, v1, h0, l0);
                splitpack(v2, v3, h1, l1);
                *(uint32_t*)(Ch + (size_t)grow * N + gcol)       = h0;
                *(uint32_t*)(Ch + (size_t)(grow + 8) * N + gcol) = h1;
                *(uint32_t*)(Cl + (size_t)grow * N + gcol)       = l0;
                *(uint32_t*)(Cl + (size_t)(grow + 8) * N + gcol) = l1;
            } else {
                *(float2*)(Cf + (size_t)grow * N + gcol)       = make_float2(v0, v1);
                *(float2*)(Cf + (size_t)(grow + 8) * N + gcol) = make_float2(v2, v3);
            }
        }
    }
}

// ---------------- tensor-core flash attention (split-bf16, post-softmax mask)
#define QT 128
#define KTILE 64
#define SQ 72                                  // smem stride (halves)
#define ATTN_SMEM ((2*QT + 4*KTILE) * SQ * 2)  // 73728 B

__global__ void __launch_bounds__(256)
attn_mma(const float* __restrict__ wm)
{
    extern __shared__ __align__(16) __nv_bfloat16 am_[];
    __nv_bfloat16* qh = am_;
    __nv_bfloat16* ql = qh + QT * SQ;
    __nv_bfloat16* kh = ql + QT * SQ;
    __nv_bfloat16* kl = kh + KTILE * SQ;
    __nv_bfloat16* vh = kl + KTILE * SQ;   // [d][kcol]
    __nv_bfloat16* vl = vh + KTILE * SQ;

    const int tid = threadIdx.x, wid = tid >> 5, lane = tid & 31;
    const int b = blockIdx.z, h = blockIdx.y, q0 = blockIdx.x * QT;

    const uint32_t sqh = smem_u32(qh), sql = smem_u32(ql);
    const uint32_t skh = smem_u32(kh), skl = smem_u32(kl);
    const uint32_t svh = smem_u32(vh), svl = smem_u32(vl);

    // ---- load Q (scaled by 1/8) and split into smem ----
    {
        const int row = tid >> 1, cb = (tid & 1) * 32;
        const float* src = g_qkv + (size_t)(b * SEQ + q0 + row) * NQKV + h * DHEAD + cb;
#pragma unroll
        for (int f = 0; f < 8; f++) {
            float4 v = *(const float4*)(src + 4 * f);
            v.x *= 0.125f; v.y *= 0.125f; v.z *= 0.125f; v.w *= 0.125f;
            uint32_t h0, l0, h1, l1;
            splitpack(v.x, v.y, h0, l0);
            splitpack(v.z, v.w, h1, l1);
            int base = row * SQ + cb + 4 * f;
            *(uint32_t*)(qh + base)     = h0;
            *(uint32_t*)(qh + base + 2) = h1;
            *(uint32_t*)(ql + base)     = l0;
            *(uint32_t*)(ql + base + 2) = l1;
        }
    }

    // ---- K/V prefetch registers ----
    const int krow = tid >> 2, kcb = (tid & 3) * 16;
    float4 rk[4], rv[4];
    {
        const float* kp = g_qkv + (size_t)(b * SEQ + krow) * NQKV + HID + h * DHEAD + kcb;
#pragma unroll
        for (int f = 0; f < 4; f++) {
            rk[f] = *(const float4*)(kp + 4 * f);
            rv[f] = *(const float4*)(kp + HID + 4 * f);
        }
    }

    float m0 = -1e30f, m1 = -1e30f, l0 = 0.f, l1 = 0.f;
    float o[8][4];
#pragma unroll
    for (int j = 0; j < 8; j++)
#pragma unroll
        for (int r = 0; r < 4; r++) o[j][r] = 0.f;

    const int rowoff = ((lane >> 3) & 1) * 8 + (lane & 7);
    const int coloff = (lane >> 4) * 8;
    const int rA = q0 + wid * 16 + (lane >> 2);

    for (int kt = 0; kt < 16; kt++) {
        __syncthreads();
#pragma unroll
        for (int f = 0; f < 4; f++) {
            int c = kcb + 4 * f;
            uint32_t h0, lo0, h1, lo1;
            splitpack(rk[f].x, rk[f].y, h0, lo0);
            splitpack(rk[f].z, rk[f].w, h1, lo1);
            int base = krow * SQ + c;
            *(uint32_t*)(kh + base)     = h0;
            *(uint32_t*)(kh + base + 2) = h1;
            *(uint32_t*)(kl + base)     = lo0;
            *(uint32_t*)(kl + base + 2) = lo1;
            float vv[4] = {rv[f].x, rv[f].y, rv[f].z, rv[f].w};
#pragma unroll
            for (int e = 0; e < 4; e++) {
                __nv_bfloat16 hb = __float2bfloat16(vv[e]);
                __nv_bfloat16 lb = __float2bfloat16(vv[e] - __bfloat162float(hb));
                vh[(c + e) * SQ + krow] = hb;
                vl[(c + e) * SQ + krow] = lb;
            }
        }
        __syncthreads();
        if (kt < 15) {
            const float* kp = g_qkv + (size_t)(b * SEQ + (kt + 1) * KTILE + krow) * NQKV
                              + HID + h * DHEAD + kcb;
#pragma unroll
            for (int f = 0; f < 4; f++) {
                rk[f] = *(const float4*)(kp + 4 * f);
                rv[f] = *(const float4*)(kp + HID + 4 * f);
            }
        }
        float2 mk0[8], mk1[8];
        {
            const float* mr0 = wm + ((size_t)b * SEQ + rA) * SEQ + kt * KTILE + (lane & 3) * 2;
            const float* mr1 = mr0 + 8 * SEQ;
#pragma unroll
            for (int j = 0; j < 8; j++) {
                mk0[j] = *(const float2*)(mr0 + 8 * j);
                mk1[j] = *(const float2*)(mr1 + 8 * j);
            }
        }

        float s[8][4];
#pragma unroll
        for (int j = 0; j < 8; j++)
#pragma unroll
            for (int r = 0; r < 4; r++) s[j][r] = 0.f;

#pragma unroll
        for (int t = 0; t < 4; t++) {
            uint32_t ah[4], al4[4];
            ldsm4(ah[0], ah[1], ah[2], ah[3],
                  sqh + ((wid * 16 + rowoff) * SQ + t * 16 + coloff) * 2);
            ldsm4(al4[0], al4[1], al4[2], al4[3],
                  sql + ((wid * 16 + rowoff) * SQ + t * 16 + coloff) * 2);
#pragma unroll
            for (int p = 0; p < 4; p++) {
                uint32_t h0, h1, h2, h3, g0, g1, g2, g3;
                uint32_t kaddr = ((p * 16 + rowoff) * SQ + t * 16 + coloff) * 2;
                ldsm4(h0, h1, h2, h3, skh + kaddr);
                ldsm4(g0, g1, g2, g3, skl + kaddr);
                uint32_t bh0[2] = {h0, h2}, bh1[2] = {h1, h3};
                uint32_t bl0[2] = {g0, g2}, bl1[2] = {g1, g3};
                mma_bf16(s[2*p],   ah,  bh0);
                mma_bf16(s[2*p],   ah,  bl0);
                mma_bf16(s[2*p],   al4, bh0);
                mma_bf16(s[2*p+1], ah,  bh1);
                mma_bf16(s[2*p+1], ah,  bl1);
                mma_bf16(s[2*p+1], al4, bh1);
            }
        }

        float lm0 = -1e30f, lm1 = -1e30f;
#pragma unroll
        for (int j = 0; j < 8; j++) {
            lm0 = fmaxf(lm0, fmaxf(s[j][0], s[j][1]));
            lm1 = fmaxf(lm1, fmaxf(s[j][2], s[j][3]));
        }
        lm0 = fmaxf(lm0, __shfl_xor_sync(0xffffffffu, lm0, 1));
        lm0 = fmaxf(lm0, __shfl_xor_sync(0xffffffffu, lm0, 2));
        lm1 = fmaxf(lm1, __shfl_xor_sync(0xffffffffu, lm1, 1));
        lm1 = fmaxf(lm1, __shfl_xor_sync(0xffffffffu, lm1, 2));
        float mn0 = fmaxf(m0, lm0), mn1 = fmaxf(m1, lm1);
        float f0 = __expf(m0 - mn0), f1 = __expf(m1 - mn1);
        m0 = mn0; m1 = mn1;
        float ls0 = 0.f, ls1 = 0.f;
#pragma unroll
        for (int j = 0; j < 8; j++) {
            float e0 = __expf(s[j][0] - mn0);
            float e1 = __expf(s[j][1] - mn0);
            float e2 = __expf(s[j][2] - mn1);
            float e3 = __expf(s[j][3] - mn1);
            ls0 += e0 + e1; ls1 += e2 + e3;
            s[j][0] = e0 * mk0[j].x;
            s[j][1] = e1 * mk0[j].y;
            s[j][2] = e2 * mk1[j].x;
            s[j][3] = e3 * mk1[j].y;
        }
        ls0 += __shfl_xor_sync(0xffffffffu, ls0, 1);
        ls0 += __shfl_xor_sync(0xffffffffu, ls0, 2);
        ls1 += __shfl_xor_sync(0xffffffffu, ls1, 1);
        ls1 += __shfl_xor_sync(0xffffffffu, ls1, 2);
        l0 = l0 * f0 + ls0;
        l1 = l1 * f1 + ls1;
#pragma unroll
        for (int j = 0; j < 8; j++) {
            o[j][0] *= f0; o[j][1] *= f0;
            o[j][2] *= f1; o[j][3] *= f1;
        }

#pragma unroll
        for (int u = 0; u < 4; u++) {
            uint32_t pah[4], pal[4];
            splitpack(s[2*u][0],   s[2*u][1],   pah[0], pal[0]);
            splitpack(s[2*u][2],   s[2*u][3],   pah[1], pal[1]);
            splitpack(s[2*u+1][0], s[2*u+1][1], pah[2], pal[2]);
            splitpack(s[2*u+1][2], s[2*u+1][3], pah[3], pal[3]);
#pragma unroll
            for (int p = 0; p < 4; p++) {
                uint32_t h0, h1, h2, h3, g0, g1, g2, g3;
                uint32_t vaddr = ((p * 16 + rowoff) * SQ + u * 16 + coloff) * 2;
                ldsm4(h0, h1, h2, h3, svh + vaddr);
                ldsm4(g0, g1, g2, g3, svl + vaddr);
                uint32_t bh0[2] = {h0, h2}, bh1[2] = {h1, h3};
                uint32_t bl0[2] = {g0, g2}, bl1[2] = {g1, g3};
                mma_bf16(o[2*p],   pah, bh0);
                mma_bf16(o[2*p],   pah, bl0);
                mma_bf16(o[2*p],   pal, bh0);
                mma_bf16(o[2*p+1], pah, bh1);
                mma_bf16(o[2*p+1], pah, bl1);
                mma_bf16(o[2*p+1], pal, bh1);
            }
        }
    }

    float inv0 = 1.0f / l0, inv1 = 1.0f / l1;
    float* c0 = g_ctx + ((size_t)(b * SEQ) + rA) * HID + h * DHEAD + (lane & 3) * 2;
    float* c1 = c0 + 8 * HID;
#pragma unroll
    for (int j = 0; j < 8; j++) {
        *(float2*)(c0 + 8 * j) = make_float2(o[j][0] * inv0, o[j][1] * inv0);
        *(float2*)(c1 + 8 * j) = make_float2(o[j][2] * inv1, o[j][3] * inv1);
    }
}

// ---------------- fused residual-add + LayerNorm (two-pass) -----------------
template<bool SPLIT>
__device__ __forceinline__ void addln_body(const float* __restrict__ A, int sA,
                                           const float* __restrict__ Bv, int sB,
                                           const float* __restrict__ g,
                                           const float* __restrict__ be,
                                           float* __restrict__ out,
                                           __nv_bfloat16* __restrict__ oh,
                                           __nv_bfloat16* __restrict__ ol)
{
    const int row = blockIdx.x;
    const int tid = threadIdx.x;
    __shared__ float red[8];
    __shared__ float s_mu, s_rs;

    float4 v4 = make_float4(0.f, 0.f, 0.f, 0.f);
    float ls = 0.f;
    if (tid < 192) {
        float4 av = ((const float4*)(A  + (size_t)row * sA))[tid];
        float4 bv = ((const float4*)(Bv + (size_t)row * sB))[tid];
        v4 = make_float4(av.x + bv.x, av.y + bv.y, av.z + bv.z, av.w + bv.w);
        ls = v4.x + v4.y + v4.z + v4.w;
    }
    int lane = tid & 31, wid = tid >> 5;
#pragma unroll
    for (int o = 16; o; o >>= 1) ls += __shfl_xor_sync(0xffffffffu, ls, o);
    if (lane == 0) red[wid] = ls;
    __syncthreads();
    if (tid == 0) {
        float t = 0.f;
#pragma unroll
        for (int i = 0; i < 8; i++) t += red[i];
        s_mu = t * (1.0f / HID);
    }
    __syncthreads();
    float mu = s_mu;

    float4 dx = make_float4(v4.x - mu, v4.y - mu, v4.z - mu, v4.w - mu);
    float lv = 0.f;
    if (tid < 192)
        lv = dx.x * dx.x + dx.y * dx.y + dx.z * dx.z + dx.w * dx.w;
#pragma unroll
    for (int o = 16; o; o >>= 1) lv += __shfl_xor_sync(0xffffffffu, lv, o);
    __syncthreads();
    if (lane == 0) red[wid] = lv;
    __syncthreads();
    if (tid == 0) {
        float t = 0.f;
#pragma unroll
        for (int i = 0; i < 8; i++) t += red[i];
        s_rs = rsqrtf(t * (1.0f / HID) + 1e-5f);
    }
    __syncthreads();
    float rs = s_rs;

    if (tid < 192) {
        float4 g4  = ((const float4*)g)[tid];
        float4 be4 = ((const float4*)be)[tid];
        float4 o = make_float4(dx.x * rs * g4.x + be4.x,
                               dx.y * rs * g4.y + be4.y,
                               dx.z * rs * g4.z + be4.z,
                               dx.w * rs * g4.w + be4.w);
        ((float4*)(out + (size_t)row * HID))[tid] = o;
        if (SPLIT) {
            uint32_t h0, l0, h1, l1;
            splitpack(o.x, o.y, h0, l0);
            splitpack(o.z, o.w, h1, l1);
            ((uint32_t*)(oh + (size_t)row * HID))[2*tid]   = h0;
            ((uint32_t*)(oh + (size_t)row * HID))[2*tid+1] = h1;
            ((uint32_t*)(ol + (size_t)row * HID))[2*tid]   = l0;
            ((uint32_t*)(ol + (size_t)row * HID))[2*tid+1] = l1;
        }
    }
}

__global__ void __launch_bounds__(256)
ln1_kernel(const float* __restrict__ g, const float* __restrict__ be)
{
    addln_body<true>(g_ctx, HID, g_qkv, NQKV, g, be, g_x, g_ah, g_al);
}

__global__ void __launch_bounds__(256)
ln2_kernel(const float* __restrict__ g, const float* __restrict__ be,
           float* __restrict__ out)
{
    addln_body<false>(g_x, HID, g_ff2, HID, g, be, out, nullptr, nullptr);
}

// ---------------- launch -----------------------------------------------------
extern "C" void kernel_launch(void* const* d_in, const int* in_sizes, int n_in,
                              void* d_out, int out_size)
{
    const float* x1  = (const float*)d_in[0];
    const float* wm  = (const float*)d_in[1];
    const float* Wq  = (const float*)d_in[2];
    const float* bq  = (const float*)d_in[3];
    const float* Wk  = (const float*)d_in[4];
    const float* bk  = (const float*)d_in[5];
    const float* Wv  = (const float*)d_in[6];
    const float* bv  = (const float*)d_in[7];
    const float* g1  = (const float*)d_in[8];
    const float* be1 = (const float*)d_in[9];
    const float* g2  = (const float*)d_in[10];
    const float* be2 = (const float*)d_in[11];
    const float* W1  = (const float*)d_in[12];
    const float* b1  = (const float*)d_in[13];
    const float* W2  = (const float*)d_in[14];
    const float* b2  = (const float*)d_in[15];
    float* out = (float*)d_out;

    void *p_ah, *p_al, *p_fh, *p_fl, *p_w1h, *p_w1l, *p_w2h, *p_w2l;
    void *p_qkv, *p_bqkv, *p_ff2, *p_wqh, *p_wql;
    cudaGetSymbolAddress(&p_ah, g_ah);     cudaGetSymbolAddress(&p_al, g_al);
    cudaGetSymbolAddress(&p_fh, g_fh);     cudaGetSymbolAddress(&p_fl, g_fl);
    cudaGetSymbolAddress(&p_w1h, g_w1h);   cudaGetSymbolAddress(&p_w1l, g_w1l);
    cudaGetSymbolAddress(&p_w2h, g_w2h);   cudaGetSymbolAddress(&p_w2l, g_w2l);
    cudaGetSymbolAddress(&p_qkv, g_qkv);   cudaGetSymbolAddress(&p_bqkv, g_bqkv);
    cudaGetSymbolAddress(&p_ff2, g_ff2);
    cudaGetSymbolAddress(&p_wqh, g_wqkvh); cudaGetSymbolAddress(&p_wql, g_wqkvl);

    __nv_bfloat16* ah  = (__nv_bfloat16*)p_ah;
    __nv_bfloat16* al  = (__nv_bfloat16*)p_al;
    __nv_bfloat16* fh  = (__nv_bfloat16*)p_fh;
    __nv_bfloat16* fl  = (__nv_bfloat16*)p_fl;
    __nv_bfloat16* wqh = (__nv_bfloat16*)p_wqh;
    __nv_bfloat16* wql = (__nv_bfloat16*)p_wql;
    __nv_bfloat16* w1h = (__nv_bfloat16*)p_w1h;
    __nv_bfloat16* w1l = (__nv_bfloat16*)p_w1l;
    __nv_bfloat16* w2h = (__nv_bfloat16*)p_w2h;
    __nv_bfloat16* w2l = (__nv_bfloat16*)p_w2l;
    float* qkv  = (float*)p_qkv;
    float* bqkv = (float*)p_bqkv;
    float* ff2  = (float*)p_ff2;

    cudaFuncSetAttribute(attn_mma,
                         cudaFuncAttributeMaxDynamicSharedMemorySize, ATTN_SMEM);
    cudaFuncSetAttribute(gemm_mma,
                         cudaFuncAttributeMaxDynamicSharedMemorySize, GEMM_SMEM);

    dim3 tb(32, 8);

    // weight prep
    prep_bias<<<3, 256>>>(bq, bk, bv);
    transpose_qkv<<<dim3(HID/32, HID/32, 3), tb>>>(Wq, Wk, Wv);
    transpose_split<<<dim3(FF/32,  HID/32), tb>>>(W1, w1h, w1l, HID, FF);
    transpose_split<<<dim3(HID/32, FF/32),  tb>>>(W2, w2h, w2l, FF, HID);

    // split x1
    convert_split<<<2048, 256>>>(x1, ah, al, ROWS * HID / 4);

    // fused QKV GEMM
    gemm_mma<<<dim3(NQKV/128, ROWS/128), 256, GEMM_SMEM>>>(
        ah, al, wqh, wql, bqkv, qkv, nullptr, nullptr, NQKV, HID, 0, 0);

    // tensor-core flash attention with post-softmax mask
    attn_mma<<<dim3(SEQ/QT, NHEAD, BATCH), 256, ATTN_SMEM>>>(wm);

    // x = LN(ctx + q_mixed), fused bf16 split of x into g_ah/g_al
    ln1_kernel<<<ROWS, 256>>>(g1, be1);

    // ff1 = relu(x @ W1 + b1) -> bf16 split into g_fh/g_fl (no aliasing)
    gemm_mma<<<dim3(FF/128, ROWS/128), 256, GEMM_SMEM>>>(
        ah, al, w1h, w1l, b1, nullptr, fh, fl, FF, HID, 1, 1);

    // ff2 = ff1 @ W2 + b2
    gemm_mma<<<dim3(HID/128, ROWS/128), 256, GEMM_SMEM>>>(
        fh, fl, w2h, w2l, b2, ff2, nullptr, nullptr, HID, FF, 0, 0);

    // out = LN(x + ff2)
    ln2_kernel<<<ROWS, 256>>>(g2, be2, out);
}

// round 8
// speedup vs baseline: 3.0130x; 1.2451x over previous
#include <cuda_runtime.h>
#include <cuda_bf16.h>
#include <cuda_fp16.h>
#include <cstdint>
#include <math.h>

// Problem constants
#define BATCH 8
#define SEQ   1024
#define HID   768
#define NHEAD 12
#define DHEAD 64
#define ROWS  (BATCH*SEQ)          // 8192
#define FF    (2*HID)              // 1536
#define NQKV  (3*HID)              // 2304

// ---------------- scratch (device globals; no allocations allowed) ----------
__device__ float g_qkv[ROWS*NQKV];   // q | k | v  per row
__device__ float g_ctx[ROWS*HID];
__device__ float g_x  [ROWS*HID];
__device__ float g_ff2[ROWS*HID];
__device__ float g_bqkv[NQKV];

__device__ __half g_ah[ROWS*HID];      // fp16 activations (A inputs; single)
__device__ __half g_fh[ROWS*FF];       // fp16 ff1 output (A for ff2)
__device__ __half g_wqkvh[NQKV*HID];   // W^T fp16 hi, rows = N, K-major
__device__ __half g_wqkvl[NQKV*HID];   // W^T fp16 residual lo
__device__ __half g_w1h[FF*HID];
__device__ __half g_w1l[FF*HID];
__device__ __half g_w2h[HID*FF];
__device__ __half g_w2l[HID*FF];

// ---------------- PTX helpers (sm_80-era only; no 'a'-features) -------------
__device__ __forceinline__ uint32_t smem_u32(const void* p) {
    uint32_t a;
    asm("{ .reg .u64 t; cvta.to.shared.u64 t, %1; cvt.u32.u64 %0, t; }"
        : "=r"(a) : "l"(p));
    return a;
}

__device__ __forceinline__ void cp16(uint32_t dst, const void* src) {
    asm volatile("cp.async.cg.shared.global [%0], [%1], 16;"
                 :: "r"(dst), "l"(src));
}
#define CP_COMMIT() asm volatile("cp.async.commit_group;" ::: "memory")
#define CP_WAIT(n)  asm volatile("cp.async.wait_group %0;" :: "n"(n) : "memory")

__device__ __forceinline__ void ldsm4(uint32_t& r0, uint32_t& r1,
                                      uint32_t& r2, uint32_t& r3, uint32_t addr) {
    asm volatile("ldmatrix.sync.aligned.m8n8.x4.shared.b16 {%0,%1,%2,%3}, [%4];"
                 : "=r"(r0), "=r"(r1), "=r"(r2), "=r"(r3) : "r"(addr));
}

// bf16 mma (attention)
__device__ __forceinline__ void mma_bf16(float* c, const uint32_t* a, const uint32_t* b) {
    asm volatile("mma.sync.aligned.m16n8k16.row.col.f32.bf16.bf16.f32 "
                 "{%0,%1,%2,%3}, {%4,%5,%6,%7}, {%8,%9}, {%0,%1,%2,%3};"
                 : "+f"(c[0]), "+f"(c[1]), "+f"(c[2]), "+f"(c[3])
                 : "r"(a[0]), "r"(a[1]), "r"(a[2]), "r"(a[3]),
                   "r"(b[0]), "r"(b[1]));
}

// fp16 mma (GEMMs)
__device__ __forceinline__ void mma_f16(float* c, const uint32_t* a, const uint32_t* b) {
    asm volatile("mma.sync.aligned.m16n8k16.row.col.f32.f16.f16.f32 "
                 "{%0,%1,%2,%3}, {%4,%5,%6,%7}, {%8,%9}, {%0,%1,%2,%3};"
                 : "+f"(c[0]), "+f"(c[1]), "+f"(c[2]), "+f"(c[3])
                 : "r"(a[0]), "r"(a[1]), "r"(a[2]), "r"(a[3]),
                   "r"(b[0]), "r"(b[1]));
}

// pack two fp32 into bf16x2 hi + residual-lo bf16x2 (attention path)
__device__ __forceinline__ void splitpack(float x, float y, uint32_t& h, uint32_t& l) {
    __nv_bfloat162 hh, ll;
    hh.x = __float2bfloat16(x); hh.y = __float2bfloat16(y);
    ll.x = __float2bfloat16(x - __bfloat162float(hh.x));
    ll.y = __float2bfloat16(y - __bfloat162float(hh.y));
    h = *(uint32_t*)&hh; l = *(uint32_t*)&ll;
}

// ---------------- prep kernels ----------------------------------------------
__global__ void prep_bias(const float* __restrict__ bq, const float* __restrict__ bk,
                          const float* __restrict__ bv) {
    int i = blockIdx.x * blockDim.x + threadIdx.x;
    if (i < HID) {
        g_bqkv[i]         = bq[i];
        g_bqkv[i + HID]   = bk[i];
        g_bqkv[i + 2*HID] = bv[i];
    }
}

// W[K,N] fp32 -> out[N,K] fp16 hi/lo (transpose + split)
__device__ __forceinline__ void tsp_body(const float* __restrict__ W,
                                         __half* __restrict__ oh,
                                         __half* __restrict__ ol,
                                         int K, int N) {
    __shared__ float t[32][33];
    const int tx = threadIdx.x, ty = threadIdx.y;
    const int n0 = blockIdx.x * 32, k0 = blockIdx.y * 32;
#pragma unroll
    for (int i = 0; i < 4; i++)
        t[ty + 8*i][tx] = W[(size_t)(k0 + ty + 8*i) * N + n0 + tx];
    __syncthreads();
#pragma unroll
    for (int i = 0; i < 4; i++) {
        float v = t[tx][ty + 8*i];
        __half h = __float2half_rn(v);
        __half l = __float2half_rn(v - __half2float(h));
        size_t idx = (size_t)(n0 + ty + 8*i) * K + k0 + tx;
        oh[idx] = h;
        ol[idx] = l;
    }
}

__global__ void __launch_bounds__(256)
transpose_split(const float* __restrict__ W, __half* __restrict__ oh,
                __half* __restrict__ ol, int K, int N) {
    tsp_body(W, oh, ol, K, N);
}

__global__ void __launch_bounds__(256)
transpose_qkv(const float* __restrict__ Wq, const float* __restrict__ Wk,
              const float* __restrict__ Wv) {
    const float* W = (blockIdx.z == 0) ? Wq : (blockIdx.z == 1) ? Wk : Wv;
    tsp_body(W, g_wqkvh + (size_t)blockIdx.z * HID * HID,
                g_wqkvl + (size_t)blockIdx.z * HID * HID, HID, HID);
}

// fp32 -> fp16 elementwise
__global__ void __launch_bounds__(256)
convert_half(const float* __restrict__ in, __half* __restrict__ oh, int n4) {
    for (int i = blockIdx.x * blockDim.x + threadIdx.x; i < n4;
         i += gridDim.x * blockDim.x) {
        float4 a = ((const float4*)in)[i];
        __half2 p0 = __floats2half2_rn(a.x, a.y);
        __half2 p1 = __floats2half2_rn(a.z, a.w);
        ((__half2*)oh)[2*i]   = p0;
        ((__half2*)oh)[2*i+1] = p1;
    }
}

// ---------------- fp16 2-pass mma.sync GEMM ----------------------------------
// C = A_h * (Bh + Bl)^T + bias, A in fp16 (single), B split fp16 hi/lo.
// Dropped term (A - fp16(A)) * B ~ 2^-12 relative. 128x128 tile/CTA, K-step 32.
#define ASTR    40                           // halves per smem row (80 B)
#define TB      (128 * ASTR * 2)             // bytes per tile (10240)
#define GEMM_SMEM (2 * 3 * TB)               // 2 stages x 3 tiles = 61440 B

__global__ void __launch_bounds__(256, 2)
gemm_mma(const __half* __restrict__ A,
         const __half* __restrict__ Bh, const __half* __restrict__ Bl,
         const float* __restrict__ bias,
         float* __restrict__ Cf, __half* __restrict__ Ch,
         int N, int K, int relu, int half_out)
{
    extern __shared__ __align__(16) char dsm[];

    const int tid  = threadIdx.x;
    const int wid  = tid >> 5, lane = tid & 31;
    const int warp_m = wid >> 2;
    const int warp_n = wid & 3;
    const int m0 = blockIdx.y << 7;
    const int n0 = blockIdx.x << 7;

    const uint32_t sb = smem_u32(dsm);

    const int lrow  = tid >> 1;
    const int lcolh = (tid & 1) * 16;

    const int kb = K >> 5;                // 32-wide K blocks

    float c[4][4][4];
#pragma unroll
    for (int i = 0; i < 4; i++)
#pragma unroll
        for (int j = 0; j < 4; j++)
#pragma unroll
            for (int r = 0; r < 4; r++) c[i][j][r] = 0.f;

    const int rowoff = ((lane >> 3) & 1) * 8 + (lane & 7);
    const int coloff = ((lane >> 4) & 1) * 8;
    const uint32_t soff = (lrow * ASTR + lcolh) * 2;

    auto issue = [&](int blk) {
        if (blk < kb) {
            const size_t ao = (size_t)(m0 + lrow) * K + blk * 32 + lcolh;
            const size_t bo = (size_t)(n0 + lrow) * K + blk * 32 + lcolh;
            uint32_t st = sb + (uint32_t)(blk & 1) * (3 * TB) + soff;
            cp16(st,             A  + ao);
            cp16(st + 16,        A  + ao + 8);
            cp16(st + TB,        Bh + bo);
            cp16(st + TB + 16,   Bh + bo + 8);
            cp16(st + 2*TB,      Bl + bo);
            cp16(st + 2*TB + 16, Bl + bo + 8);
        }
        CP_COMMIT();
    };

    issue(0); issue(1);

    for (int blk = 0; blk < kb; blk++) {
        CP_WAIT(1);
        __syncthreads();

        const uint32_t s0 = sb + (uint32_t)(blk & 1) * (3 * TB);
#pragma unroll
        for (int kh = 0; kh < 2; kh++) {
            const uint32_t arow = ((warp_m * 64 + rowoff) * ASTR + kh * 16 + coloff) * 2;
            const uint32_t brow = ((warp_n * 32 + rowoff) * ASTR + kh * 16 + coloff) * 2;

            // A fragments (reused across both passes)
            uint32_t af[4][4];
#pragma unroll
            for (int t = 0; t < 4; t++)
                ldsm4(af[t][0], af[t][1], af[t][2], af[t][3],
                      s0 + arow + (uint32_t)(t * 16 * ASTR) * 2);
            // pass 1: A * Bh
            {
                uint32_t bh[4][2];
#pragma unroll
                for (int p = 0; p < 2; p++) {
                    uint32_t r0, r1, r2, r3;
                    ldsm4(r0, r1, r2, r3,
                          s0 + TB + brow + (uint32_t)(p * 16 * ASTR) * 2);
                    bh[2*p][0]   = r0; bh[2*p][1]   = r2;
                    bh[2*p+1][0] = r1; bh[2*p+1][1] = r3;
                }
#pragma unroll
                for (int i = 0; i < 4; i++)
#pragma unroll
                    for (int j = 0; j < 4; j++)
                        mma_f16(c[i][j], af[i], bh[j]);
            }
            // pass 2: A * Bl
            {
                uint32_t bl[4][2];
#pragma unroll
                for (int p = 0; p < 2; p++) {
                    uint32_t r0, r1, r2, r3;
                    ldsm4(r0, r1, r2, r3,
                          s0 + 2*TB + brow + (uint32_t)(p * 16 * ASTR) * 2);
                    bl[2*p][0]   = r0; bl[2*p][1]   = r2;
                    bl[2*p+1][0] = r1; bl[2*p+1][1] = r3;
                }
#pragma unroll
                for (int i = 0; i < 4; i++)
#pragma unroll
                    for (int j = 0; j < 4; j++)
                        mma_f16(c[i][j], af[i], bl[j]);
            }
        }
        __syncthreads();
        issue(blk + 2);
    }

    // epilogue: bias (+relu), fp32 or fp16 stores
#pragma unroll
    for (int i = 0; i < 4; i++) {
#pragma unroll
        for (int j = 0; j < 4; j++) {
            int grow = m0 + warp_m * 64 + i * 16 + (lane >> 2);
            int gcol = n0 + warp_n * 32 + j * 8 + (lane & 3) * 2;
            float b0v = bias[gcol], b1v = bias[gcol + 1];
            float v0 = c[i][j][0] + b0v;
            float v1 = c[i][j][1] + b1v;
            float v2 = c[i][j][2] + b0v;
            float v3 = c[i][j][3] + b1v;
            if (relu) {
                v0 = fmaxf(v0, 0.f); v1 = fmaxf(v1, 0.f);
                v2 = fmaxf(v2, 0.f); v3 = fmaxf(v3, 0.f);
            }
            if (half_out) {
                __half2 p0 = __floats2half2_rn(v0, v1);
                __half2 p1 = __floats2half2_rn(v2, v3);
                *(__half2*)(Ch + (size_t)grow * N + gcol)       = p0;
                *(__half2*)(Ch + (size_t)(grow + 8) * N + gcol) = p1;
            } else {
                *(float2*)(Cf + (size_t)grow * N + gcol)       = make_float2(v0, v1);
                *(float2*)(Cf + (size_t)(grow + 8) * N + gcol) = make_float2(v2, v3);
            }
        }
    }
}

// ---------------- tensor-core flash attention (split-bf16, post-softmax mask)
#define QT 128
#define KTILE 64
#define SQ 72                                  // smem stride (halves)
#define ATTN_SMEM ((2*QT + 4*KTILE) * SQ * 2)  // 73728 B

__global__ void __launch_bounds__(256)
attn_mma(const float* __restrict__ wm)
{
    extern __shared__ __align__(16) __nv_bfloat16 am_[];
    __nv_bfloat16* qh = am_;
    __nv_bfloat16* ql = qh + QT * SQ;
    __nv_bfloat16* kh = ql + QT * SQ;
    __nv_bfloat16* kl = kh + KTILE * SQ;
    __nv_bfloat16* vh = kl + KTILE * SQ;   // [d][kcol]
    __nv_bfloat16* vl = vh + KTILE * SQ;

    const int tid = threadIdx.x, wid = tid >> 5, lane = tid & 31;
    const int b = blockIdx.z, h = blockIdx.y, q0 = blockIdx.x * QT;

    const uint32_t sqh = smem_u32(qh), sql = smem_u32(ql);
    const uint32_t skh = smem_u32(kh), skl = smem_u32(kl);
    const uint32_t svh = smem_u32(vh), svl = smem_u32(vl);

    {
        const int row = tid >> 1, cb = (tid & 1) * 32;
        const float* src = g_qkv + (size_t)(b * SEQ + q0 + row) * NQKV + h * DHEAD + cb;
#pragma unroll
        for (int f = 0; f < 8; f++) {
            float4 v = *(const float4*)(src + 4 * f);
            v.x *= 0.125f; v.y *= 0.125f; v.z *= 0.125f; v.w *= 0.125f;
            uint32_t h0, l0, h1, l1;
            splitpack(v.x, v.y, h0, l0);
            splitpack(v.z, v.w, h1, l1);
            int base = row * SQ + cb + 4 * f;
            *(uint32_t*)(qh + base)     = h0;
            *(uint32_t*)(qh + base + 2) = h1;
            *(uint32_t*)(ql + base)     = l0;
            *(uint32_t*)(ql + base + 2) = l1;
        }
    }

    const int krow = tid >> 2, kcb = (tid & 3) * 16;
    float4 rk[4], rv[4];
    {
        const float* kp = g_qkv + (size_t)(b * SEQ + krow) * NQKV + HID + h * DHEAD + kcb;
#pragma unroll
        for (int f = 0; f < 4; f++) {
            rk[f] = *(const float4*)(kp + 4 * f);
            rv[f] = *(const float4*)(kp + HID + 4 * f);
        }
    }

    float m0 = -1e30f, m1 = -1e30f, l0 = 0.f, l1 = 0.f;
    float o[8][4];
#pragma unroll
    for (int j = 0; j < 8; j++)
#pragma unroll
        for (int r = 0; r < 4; r++) o[j][r] = 0.f;

    const int rowoff = ((lane >> 3) & 1) * 8 + (lane & 7);
    const int coloff = (lane >> 4) * 8;
    const int rA = q0 + wid * 16 + (lane >> 2);

    for (int kt = 0; kt < 16; kt++) {
        __syncthreads();
#pragma unroll
        for (int f = 0; f < 4; f++) {
            int c = kcb + 4 * f;
            uint32_t h0, lo0, h1, lo1;
            splitpack(rk[f].x, rk[f].y, h0, lo0);
            splitpack(rk[f].z, rk[f].w, h1, lo1);
            int base = krow * SQ + c;
            *(uint32_t*)(kh + base)     = h0;
            *(uint32_t*)(kh + base + 2) = h1;
            *(uint32_t*)(kl + base)     = lo0;
            *(uint32_t*)(kl + base + 2) = lo1;
            float vv[4] = {rv[f].x, rv[f].y, rv[f].z, rv[f].w};
#pragma unroll
            for (int e = 0; e < 4; e++) {
                __nv_bfloat16 hb = __float2bfloat16(vv[e]);
                __nv_bfloat16 lb = __float2bfloat16(vv[e] - __bfloat162float(hb));
                vh[(c + e) * SQ + krow] = hb;
                vl[(c + e) * SQ + krow] = lb;
            }
        }
        __syncthreads();
        if (kt < 15) {
            const float* kp = g_qkv + (size_t)(b * SEQ + (kt + 1) * KTILE + krow) * NQKV
                              + HID + h * DHEAD + kcb;
#pragma unroll
            for (int f = 0; f < 4; f++) {
                rk[f] = *(const float4*)(kp + 4 * f);
                rv[f] = *(const float4*)(kp + HID + 4 * f);
            }
        }
        float2 mk0[8], mk1[8];
        {
            const float* mr0 = wm + ((size_t)b * SEQ + rA) * SEQ + kt * KTILE + (lane & 3) * 2;
            const float* mr1 = mr0 + 8 * SEQ;
#pragma unroll
            for (int j = 0; j < 8; j++) {
                mk0[j] = *(const float2*)(mr0 + 8 * j);
                mk1[j] = *(const float2*)(mr1 + 8 * j);
            }
        }

        float s[8][4];
#pragma unroll
        for (int j = 0; j < 8; j++)
#pragma unroll
            for (int r = 0; r < 4; r++) s[j][r] = 0.f;

#pragma unroll
        for (int t = 0; t < 4; t++) {
            uint32_t ah[4], al4[4];
            ldsm4(ah[0], ah[1], ah[2], ah[3],
                  sqh + ((wid * 16 + rowoff) * SQ + t * 16 + coloff) * 2);
            ldsm4(al4[0], al4[1], al4[2], al4[3],
                  sql + ((wid * 16 + rowoff) * SQ + t * 16 + coloff) * 2);
#pragma unroll
            for (int p = 0; p < 4; p++) {
                uint32_t h0, h1, h2, h3, g0, g1, g2, g3;
                uint32_t kaddr = ((p * 16 + rowoff) * SQ + t * 16 + coloff) * 2;
                ldsm4(h0, h1, h2, h3, skh + kaddr);
                ldsm4(g0, g1, g2, g3, skl + kaddr);
                uint32_t bh0[2] = {h0, h2}, bh1[2] = {h1, h3};
                uint32_t bl0[2] = {g0, g2}, bl1[2] = {g1, g3};
                mma_bf16(s[2*p],   ah,  bh0);
                mma_bf16(s[2*p],   ah,  bl0);
                mma_bf16(s[2*p],   al4, bh0);
                mma_bf16(s[2*p+1], ah,  bh1);
                mma_bf16(s[2*p+1], ah,  bl1);
                mma_bf16(s[2*p+1], al4, bh1);
            }
        }

        float lm0 = -1e30f, lm1 = -1e30f;
#pragma unroll
        for (int j = 0; j < 8; j++) {
            lm0 = fmaxf(lm0, fmaxf(s[j][0], s[j][1]));
            lm1 = fmaxf(lm1, fmaxf(s[j][2], s[j][3]));
        }
        lm0 = fmaxf(lm0, __shfl_xor_sync(0xffffffffu, lm0, 1));
        lm0 = fmaxf(lm0, __shfl_xor_sync(0xffffffffu, lm0, 2));
        lm1 = fmaxf(lm1, __shfl_xor_sync(0xffffffffu, lm1, 1));
        lm1 = fmaxf(lm1, __shfl_xor_sync(0xffffffffu, lm1, 2));
        float mn0 = fmaxf(m0, lm0), mn1 = fmaxf(m1, lm1);
        float f0 = __expf(m0 - mn0), f1 = __expf(m1 - mn1);
        m0 = mn0; m1 = mn1;
        float ls0 = 0.f, ls1 = 0.f;
#pragma unroll
        for (int j = 0; j < 8; j++) {
            float e0 = __expf(s[j][0] - mn0);
            float e1 = __expf(s[j][1] - mn0);
            float e2 = __expf(s[j][2] - mn1);
            float e3 = __expf(s[j][3] - mn1);
            ls0 += e0 + e1; ls1 += e2 + e3;
            s[j][0] = e0 * mk0[j].x;
            s[j][1] = e1 * mk0[j].y;
            s[j][2] = e2 * mk1[j].x;
            s[j][3] = e3 * mk1[j].y;
        }
        ls0 += __shfl_xor_sync(0xffffffffu, ls0, 1);
        ls0 += __shfl_xor_sync(0xffffffffu, ls0, 2);
        ls1 += __shfl_xor_sync(0xffffffffu, ls1, 1);
        ls1 += __shfl_xor_sync(0xffffffffu, ls1, 2);
        l0 = l0 * f0 + ls0;
        l1 = l1 * f1 + ls1;
#pragma unroll
        for (int j = 0; j < 8; j++) {
            o[j][0] *= f0; o[j][1] *= f0;
            o[j][2] *= f1; o[j][3] *= f1;
        }

#pragma unroll
        for (int u = 0; u < 4; u++) {
            uint32_t pah[4], pal[4];
            splitpack(s[2*u][0],   s[2*u][1],   pah[0], pal[0]);
            splitpack(s[2*u][2],   s[2*u][3],   pah[1], pal[1]);
            splitpack(s[2*u+1][0], s[2*u+1][1], pah[2], pal[2]);
            splitpack(s[2*u+1][2], s[2*u+1][3], pah[3], pal[3]);
#pragma unroll
            for (int p = 0; p < 4; p++) {
                uint32_t h0, h1, h2, h3, g0, g1, g2, g3;
                uint32_t vaddr = ((p * 16 + rowoff) * SQ + u * 16 + coloff) * 2;
                ldsm4(h0, h1, h2, h3, svh + vaddr);
                ldsm4(g0, g1, g2, g3, svl + vaddr);
                uint32_t bh0[2] = {h0, h2}, bh1[2] = {h1, h3};
                uint32_t bl0[2] = {g0, g2}, bl1[2] = {g1, g3};
                mma_bf16(o[2*p],   pah, bh0);
                mma_bf16(o[2*p],   pah, bl0);
                mma_bf16(o[2*p],   pal, bh0);
                mma_bf16(o[2*p+1], pah, bh1);
                mma_bf16(o[2*p+1], pah, bl1);
                mma_bf16(o[2*p+1], pal, bh1);
            }
        }
    }

    float inv0 = 1.0f / l0, inv1 = 1.0f / l1;
    float* c0 = g_ctx + ((size_t)(b * SEQ) + rA) * HID + h * DHEAD + (lane & 3) * 2;
    float* c1 = c0 + 8 * HID;
#pragma unroll
    for (int j = 0; j < 8; j++) {
        *(float2*)(c0 + 8 * j) = make_float2(o[j][0] * inv0, o[j][1] * inv0);
        *(float2*)(c1 + 8 * j) = make_float2(o[j][2] * inv1, o[j][3] * inv1);
    }
}

// ---------------- fused residual-add + LayerNorm (two-pass) -----------------
// HALF: additionally emit fp16 of the normalized output (A input for ff1).
template<bool HALF>
__device__ __forceinline__ void addln_body(const float* __restrict__ A, int sA,
                                           const float* __restrict__ Bv, int sB,
                                           const float* __restrict__ g,
                                           const float* __restrict__ be,
                                           float* __restrict__ out,
                                           __half* __restrict__ oh)
{
    const int row = blockIdx.x;
    const int tid = threadIdx.x;
    __shared__ float red[8];
    __shared__ float s_mu, s_rs;

    float4 v4 = make_float4(0.f, 0.f, 0.f, 0.f);
    float ls = 0.f;
    if (tid < 192) {
        float4 av = ((const float4*)(A  + (size_t)row * sA))[tid];
        float4 bv = ((const float4*)(Bv + (size_t)row * sB))[tid];
        v4 = make_float4(av.x + bv.x, av.y + bv.y, av.z + bv.z, av.w + bv.w);
        ls = v4.x + v4.y + v4.z + v4.w;
    }
    int lane = tid & 31, wid = tid >> 5;
#pragma unroll
    for (int o = 16; o; o >>= 1) ls += __shfl_xor_sync(0xffffffffu, ls, o);
    if (lane == 0) red[wid] = ls;
    __syncthreads();
    if (tid == 0) {
        float t = 0.f;
#pragma unroll
        for (int i = 0; i < 8; i++) t += red[i];
        s_mu = t * (1.0f / HID);
    }
    __syncthreads();
    float mu = s_mu;

    float4 dx = make_float4(v4.x - mu, v4.y - mu, v4.z - mu, v4.w - mu);
    float lv = 0.f;
    if (tid < 192)
        lv = dx.x * dx.x + dx.y * dx.y + dx.z * dx.z + dx.w * dx.w;
#pragma unroll
    for (int o = 16; o; o >>= 1) lv += __shfl_xor_sync(0xffffffffu, lv, o);
    __syncthreads();
    if (lane == 0) red[wid] = lv;
    __syncthreads();
    if (tid == 0) {
        float t = 0.f;
#pragma unroll
        for (int i = 0; i < 8; i++) t += red[i];
        s_rs = rsqrtf(t * (1.0f / HID) + 1e-5f);
    }
    __syncthreads();
    float rs = s_rs;

    if (tid < 192) {
        float4 g4  = ((const float4*)g)[tid];
        float4 be4 = ((const float4*)be)[tid];
        float4 o = make_float4(dx.x * rs * g4.x + be4.x,
                               dx.y * rs * g4.y + be4.y,
                               dx.z * rs * g4.z + be4.z,
                               dx.w * rs * g4.w + be4.w);
        ((float4*)(out + (size_t)row * HID))[tid] = o;
        if (HALF) {
            __half2 p0 = __floats2half2_rn(o.x, o.y);
            __half2 p1 = __floats2half2_rn(o.z, o.w);
            ((__half2*)(oh + (size_t)row * HID))[2*tid]   = p0;
            ((__half2*)(oh + (size_t)row * HID))[2*tid+1] = p1;
        }
    }
}

__global__ void __launch_bounds__(256)
ln1_kernel(const float* __restrict__ g, const float* __restrict__ be)
{
    addln_body<true>(g_ctx, HID, g_qkv, NQKV, g, be, g_x, g_ah);
}

__global__ void __launch_bounds__(256)
ln2_kernel(const float* __restrict__ g, const float* __restrict__ be,
           float* __restrict__ out)
{
    addln_body<false>(g_x, HID, g_ff2, HID, g, be, out, nullptr);
}

// ---------------- launch -----------------------------------------------------
extern "C" void kernel_launch(void* const* d_in, const int* in_sizes, int n_in,
                              void* d_out, int out_size)
{
    const float* x1  = (const float*)d_in[0];
    const float* wm  = (const float*)d_in[1];
    const float* Wq  = (const float*)d_in[2];
    const float* bq  = (const float*)d_in[3];
    const float* Wk  = (const float*)d_in[4];
    const float* bk  = (const float*)d_in[5];
    const float* Wv  = (const float*)d_in[6];
    const float* bv  = (const float*)d_in[7];
    const float* g1  = (const float*)d_in[8];
    const float* be1 = (const float*)d_in[9];
    const float* g2  = (const float*)d_in[10];
    const float* be2 = (const float*)d_in[11];
    const float* W1  = (const float*)d_in[12];
    const float* b1  = (const float*)d_in[13];
    const float* W2  = (const float*)d_in[14];
    const float* b2  = (const float*)d_in[15];
    float* out = (float*)d_out;

    void *p_ah, *p_fh, *p_w1h, *p_w1l, *p_w2h, *p_w2l;
    void *p_qkv, *p_bqkv, *p_ff2, *p_wqh, *p_wql;
    cudaGetSymbolAddress(&p_ah, g_ah);
    cudaGetSymbolAddress(&p_fh, g_fh);
    cudaGetSymbolAddress(&p_w1h, g_w1h);   cudaGetSymbolAddress(&p_w1l, g_w1l);
    cudaGetSymbolAddress(&p_w2h, g_w2h);   cudaGetSymbolAddress(&p_w2l, g_w2l);
    cudaGetSymbolAddress(&p_qkv, g_qkv);   cudaGetSymbolAddress(&p_bqkv, g_bqkv);
    cudaGetSymbolAddress(&p_ff2, g_ff2);
    cudaGetSymbolAddress(&p_wqh, g_wqkvh); cudaGetSymbolAddress(&p_wql, g_wqkvl);

    __half* ah  = (__half*)p_ah;
    __half* fh  = (__half*)p_fh;
    __half* wqh = (__half*)p_wqh;
    __half* wql = (__half*)p_wql;
    __half* w1h = (__half*)p_w1h;
    __half* w1l = (__half*)p_w1l;
    __half* w2h = (__half*)p_w2h;
    __half* w2l = (__half*)p_w2l;
    float* qkv  = (float*)p_qkv;
    float* bqkv = (float*)p_bqkv;
    float* ff2  = (float*)p_ff2;

    cudaFuncSetAttribute(attn_mma,
                         cudaFuncAttributeMaxDynamicSharedMemorySize, ATTN_SMEM);
    cudaFuncSetAttribute(gemm_mma,
                         cudaFuncAttributeMaxDynamicSharedMemorySize, GEMM_SMEM);

    dim3 tb(32, 8);

    // weight prep
    prep_bias<<<3, 256>>>(bq, bk, bv);
    transpose_qkv<<<dim3(HID/32, HID/32, 3), tb>>>(Wq, Wk, Wv);
    transpose_split<<<dim3(FF/32,  HID/32), tb>>>(W1, w1h, w1l, HID, FF);
    transpose_split<<<dim3(HID/32, FF/32),  tb>>>(W2, w2h, w2l, FF, HID);

    // x1 -> fp16
    convert_half<<<2048, 256>>>(x1, ah, ROWS * HID / 4);

    // fused QKV GEMM (fp16 2-pass)
    gemm_mma<<<dim3(NQKV/128, ROWS/128), 256, GEMM_SMEM>>>(
        ah, wqh, wql, bqkv, qkv, nullptr, NQKV, HID, 0, 0);

    // tensor-core flash attention with post-softmax mask (bf16 3-pass)
    attn_mma<<<dim3(SEQ/QT, NHEAD, BATCH), 256, ATTN_SMEM>>>(wm);

    // x = LN(ctx + q_mixed), fused fp16 emit into g_ah
    ln1_kernel<<<ROWS, 256>>>(g1, be1);

    // ff1 = relu(x @ W1 + b1) -> fp16 into g_fh
    gemm_mma<<<dim3(FF/128, ROWS/128), 256, GEMM_SMEM>>>(
        ah, w1h, w1l, b1, nullptr, fh, FF, HID, 1, 1);

    // ff2 = ff1 @ W2 + b2
    gemm_mma<<<dim3(HID/128, ROWS/128), 256, GEMM_SMEM>>>(
        fh, w2h, w2l, b2, ff2, nullptr, HID, FF, 0, 0);

    // out = LN(x + ff2)
    ln2_kernel<<<ROWS, 256>>>(g2, be2, out);
}

// round 9
// speedup vs baseline: 3.9870x; 1.3233x over previous
#include <cuda_runtime.h>
#include <cuda_bf16.h>
#include <cuda_fp16.h>
#include <cstdint>
#include <math.h>

// Problem constants
#define BATCH 8
#define SEQ   1024
#define HID   768
#define NHEAD 12
#define DHEAD 64
#define ROWS  (BATCH*SEQ)          // 8192
#define FF    (2*HID)              // 1536
#define NQKV  (3*HID)              // 2304

// ---------------- scratch (device globals; no allocations allowed) ----------
__device__ float g_qkv[ROWS*NQKV];   // q | k | v  per row
__device__ float g_ctx[ROWS*HID];
__device__ float g_x  [ROWS*HID];
__device__ float g_ff2[ROWS*HID];
__device__ float g_bqkv[NQKV];

__device__ __half g_ah[ROWS*HID];      // fp16 activations (A inputs)
__device__ __half g_fh[ROWS*FF];       // fp16 ff1 output (A for ff2)
__device__ __half g_wqkvh[NQKV*HID];   // W^T fp16, rows = N, K-major
__device__ __half g_w1h[FF*HID];
__device__ __half g_w2h[HID*FF];

// ---------------- PTX helpers (sm_80-era only; no 'a'-features) -------------
__device__ __forceinline__ uint32_t smem_u32(const void* p) {
    uint32_t a;
    asm("{ .reg .u64 t; cvta.to.shared.u64 t, %1; cvt.u32.u64 %0, t; }"
        : "=r"(a) : "l"(p));
    return a;
}

__device__ __forceinline__ void cp16(uint32_t dst, const void* src) {
    asm volatile("cp.async.cg.shared.global [%0], [%1], 16;"
                 :: "r"(dst), "l"(src));
}
#define CP_COMMIT() asm volatile("cp.async.commit_group;" ::: "memory")
#define CP_WAIT(n)  asm volatile("cp.async.wait_group %0;" :: "n"(n) : "memory")

__device__ __forceinline__ void ldsm4(uint32_t& r0, uint32_t& r1,
                                      uint32_t& r2, uint32_t& r3, uint32_t addr) {
    asm volatile("ldmatrix.sync.aligned.m8n8.x4.shared.b16 {%0,%1,%2,%3}, [%4];"
                 : "=r"(r0), "=r"(r1), "=r"(r2), "=r"(r3) : "r"(addr));
}

// bf16 mma (attention)
__device__ __forceinline__ void mma_bf16(float* c, const uint32_t* a, const uint32_t* b) {
    asm volatile("mma.sync.aligned.m16n8k16.row.col.f32.bf16.bf16.f32 "
                 "{%0,%1,%2,%3}, {%4,%5,%6,%7}, {%8,%9}, {%0,%1,%2,%3};"
                 : "+f"(c[0]), "+f"(c[1]), "+f"(c[2]), "+f"(c[3])
                 : "r"(a[0]), "r"(a[1]), "r"(a[2]), "r"(a[3]),
                   "r"(b[0]), "r"(b[1]));
}

// fp16 mma (GEMMs)
__device__ __forceinline__ void mma_f16(float* c, const uint32_t* a, const uint32_t* b) {
    asm volatile("mma.sync.aligned.m16n8k16.row.col.f32.f16.f16.f32 "
                 "{%0,%1,%2,%3}, {%4,%5,%6,%7}, {%8,%9}, {%0,%1,%2,%3};"
                 : "+f"(c[0]), "+f"(c[1]), "+f"(c[2]), "+f"(c[3])
                 : "r"(a[0]), "r"(a[1]), "r"(a[2]), "r"(a[3]),
                   "r"(b[0]), "r"(b[1]));
}

// pack two fp32 into bf16x2 hi + residual-lo bf16x2 (attention path)
__device__ __forceinline__ void splitpack(float x, float y, uint32_t& h, uint32_t& l) {
    __nv_bfloat162 hh, ll;
    hh.x = __float2bfloat16(x); hh.y = __float2bfloat16(y);
    ll.x = __float2bfloat16(x - __bfloat162float(hh.x));
    ll.y = __float2bfloat16(y - __bfloat162float(hh.y));
    h = *(uint32_t*)&hh; l = *(uint32_t*)&ll;
}

// ---------------- prep kernels ----------------------------------------------
__global__ void prep_bias(const float* __restrict__ bq, const float* __restrict__ bk,
                          const float* __restrict__ bv) {
    int i = blockIdx.x * blockDim.x + threadIdx.x;
    if (i < HID) {
        g_bqkv[i]         = bq[i];
        g_bqkv[i + HID]   = bk[i];
        g_bqkv[i + 2*HID] = bv[i];
    }
}

// W[K,N] fp32 -> out[N,K] fp16 (transpose + convert)
__device__ __forceinline__ void tsp_body(const float* __restrict__ W,
                                         __half* __restrict__ oh,
                                         int K, int N) {
    __shared__ float t[32][33];
    const int tx = threadIdx.x, ty = threadIdx.y;
    const int n0 = blockIdx.x * 32, k0 = blockIdx.y * 32;
#pragma unroll
    for (int i = 0; i < 4; i++)
        t[ty + 8*i][tx] = W[(size_t)(k0 + ty + 8*i) * N + n0 + tx];
    __syncthreads();
#pragma unroll
    for (int i = 0; i < 4; i++) {
        float v = t[tx][ty + 8*i];
        oh[(size_t)(n0 + ty + 8*i) * K + k0 + tx] = __float2half_rn(v);
    }
}

__global__ void __launch_bounds__(256)
transpose_conv(const float* __restrict__ W, __half* __restrict__ oh, int K, int N) {
    tsp_body(W, oh, K, N);
}

__global__ void __launch_bounds__(256)
transpose_qkv(const float* __restrict__ Wq, const float* __restrict__ Wk,
              const float* __restrict__ Wv) {
    const float* W = (blockIdx.z == 0) ? Wq : (blockIdx.z == 1) ? Wk : Wv;
    tsp_body(W, g_wqkvh + (size_t)blockIdx.z * HID * HID, HID, HID);
}

// fp32 -> fp16 elementwise
__global__ void __launch_bounds__(256)
convert_half(const float* __restrict__ in, __half* __restrict__ oh, int n4) {
    for (int i = blockIdx.x * blockDim.x + threadIdx.x; i < n4;
         i += gridDim.x * blockDim.x) {
        float4 a = ((const float4*)in)[i];
        __half2 p0 = __floats2half2_rn(a.x, a.y);
        __half2 p1 = __floats2half2_rn(a.z, a.w);
        ((__half2*)oh)[2*i]   = p0;
        ((__half2*)oh)[2*i+1] = p1;
    }
}

// ---------------- fp16 single-pass mma.sync GEMM (4-stage cp.async ring) -----
// C = A * B^T + bias (both fp16, fp32 accumulate). 128x128 tile/CTA, K-step 32.
#define ASTR    40                           // halves per smem row (80 B)
#define STGB    (128 * ASTR * 2)             // bytes per tile per stage (10240)
#define STAGES  4
#define GEMM_SMEM (STAGES * 2 * STGB)        // 81920 B dynamic

__global__ void __launch_bounds__(256, 2)
gemm_mma(const __half* __restrict__ A, const __half* __restrict__ B,
         const float* __restrict__ bias,
         float* __restrict__ Cf, __half* __restrict__ Ch,
         int N, int K, int relu, int half_out)
{
    extern __shared__ __align__(16) char dsm[];
    __half* smA = (__half*)dsm;
    __half* smB = (__half*)(dsm + STAGES * STGB);

    const int tid  = threadIdx.x;
    const int wid  = tid >> 5, lane = tid & 31;
    const int warp_m = wid >> 2;
    const int warp_n = wid & 3;
    const int m0 = blockIdx.y << 7;
    const int n0 = blockIdx.x << 7;

    const uint32_t sA = smem_u32(smA);
    const uint32_t sB = smem_u32(smB);

    const int lrow  = tid >> 1;
    const int lcolh = (tid & 1) * 16;

    const int kb = K >> 5;                // 32-wide K blocks

    float c[4][4][4];
#pragma unroll
    for (int i = 0; i < 4; i++)
#pragma unroll
        for (int j = 0; j < 4; j++)
#pragma unroll
            for (int r = 0; r < 4; r++) c[i][j][r] = 0.f;

    const int rowoff = ((lane >> 3) & 1) * 8 + (lane & 7);
    const int coloff = ((lane >> 4) & 1) * 8;

    auto issue = [&](int blk) {
        if (blk < kb) {
            const __half* ga = A + (size_t)(m0 + lrow) * K + blk * 32 + lcolh;
            const __half* gb = B + (size_t)(n0 + lrow) * K + blk * 32 + lcolh;
            int st = blk & (STAGES - 1);
            uint32_t da = sA + st * STGB + (lrow * ASTR + lcolh) * 2;
            uint32_t db = sB + st * STGB + (lrow * ASTR + lcolh) * 2;
            cp16(da,      ga);
            cp16(da + 16, ga + 8);
            cp16(db,      gb);
            cp16(db + 16, gb + 8);
        }
        CP_COMMIT();
    };

    issue(0); issue(1); issue(2);

    for (int blk = 0; blk < kb; blk++) {
        CP_WAIT(2);
        __syncthreads();

        const int stage = blk & (STAGES - 1);
        const uint32_t a0 = sA + stage * STGB;
        const uint32_t b0 = sB + stage * STGB;
#pragma unroll
        for (int kh = 0; kh < 2; kh++) {
            uint32_t af[4][4];
#pragma unroll
            for (int t = 0; t < 4; t++)
                ldsm4(af[t][0], af[t][1], af[t][2], af[t][3],
                      a0 + ((warp_m * 64 + t * 16 + rowoff) * ASTR + kh * 16 + coloff) * 2);
            uint32_t bf[4][2];
#pragma unroll
            for (int p = 0; p < 2; p++) {
                uint32_t r0, r1, r2, r3;
                ldsm4(r0, r1, r2, r3,
                      b0 + ((warp_n * 32 + p * 16 + rowoff) * ASTR + kh * 16 + coloff) * 2);
                bf[2*p][0]   = r0; bf[2*p][1]   = r2;
                bf[2*p+1][0] = r1; bf[2*p+1][1] = r3;
            }
#pragma unroll
            for (int i = 0; i < 4; i++)
#pragma unroll
                for (int j = 0; j < 4; j++)
                    mma_f16(c[i][j], af[i], bf[j]);
        }
        issue(blk + 3);
    }

    // epilogue: bias (+relu), fp32 or fp16 stores
#pragma unroll
    for (int i = 0; i < 4; i++) {
#pragma unroll
        for (int j = 0; j < 4; j++) {
            int grow = m0 + warp_m * 64 + i * 16 + (lane >> 2);
            int gcol = n0 + warp_n * 32 + j * 8 + (lane & 3) * 2;
            float b0v = bias[gcol], b1v = bias[gcol + 1];
            float v0 = c[i][j][0] + b0v;
            float v1 = c[i][j][1] + b1v;
            float v2 = c[i][j][2] + b0v;
            float v3 = c[i][j][3] + b1v;
            if (relu) {
                v0 = fmaxf(v0, 0.f); v1 = fmaxf(v1, 0.f);
                v2 = fmaxf(v2, 0.f); v3 = fmaxf(v3, 0.f);
            }
            if (half_out) {
                __half2 p0 = __floats2half2_rn(v0, v1);
                __half2 p1 = __floats2half2_rn(v2, v3);
                *(__half2*)(Ch + (size_t)grow * N + gcol)       = p0;
                *(__half2*)(Ch + (size_t)(grow + 8) * N + gcol) = p1;
            } else {
                *(float2*)(Cf + (size_t)grow * N + gcol)       = make_float2(v0, v1);
                *(float2*)(Cf + (size_t)(grow + 8) * N + gcol) = make_float2(v2, v3);
            }
        }
    }
}

// ---------------- tensor-core flash attention (split-bf16, post-softmax mask)
#define QT 128
#define KTILE 64
#define SQ 72                                  // smem stride (halves)
#define ATTN_SMEM ((2*QT + 4*KTILE) * SQ * 2)  // 73728 B

__global__ void __launch_bounds__(256)
attn_mma(const float* __restrict__ wm)
{
    extern __shared__ __align__(16) __nv_bfloat16 am_[];
    __nv_bfloat16* qh = am_;
    __nv_bfloat16* ql = qh + QT * SQ;
    __nv_bfloat16* kh = ql + QT * SQ;
    __nv_bfloat16* kl = kh + KTILE * SQ;
    __nv_bfloat16* vh = kl + KTILE * SQ;   // [d][kcol]
    __nv_bfloat16* vl = vh + KTILE * SQ;

    const int tid = threadIdx.x, wid = tid >> 5, lane = tid & 31;
    const int b = blockIdx.z, h = blockIdx.y, q0 = blockIdx.x * QT;

    const uint32_t sqh = smem_u32(qh), sql = smem_u32(ql);
    const uint32_t skh = smem_u32(kh), skl = smem_u32(kl);
    const uint32_t svh = smem_u32(vh), svl = smem_u32(vl);

    {
        const int row = tid >> 1, cb = (tid & 1) * 32;
        const float* src = g_qkv + (size_t)(b * SEQ + q0 + row) * NQKV + h * DHEAD + cb;
#pragma unroll
        for (int f = 0; f < 8; f++) {
            float4 v = *(const float4*)(src + 4 * f);
            v.x *= 0.125f; v.y *= 0.125f; v.z *= 0.125f; v.w *= 0.125f;
            uint32_t h0, l0, h1, l1;
            splitpack(v.x, v.y, h0, l0);
            splitpack(v.z, v.w, h1, l1);
            int base = row * SQ + cb + 4 * f;
            *(uint32_t*)(qh + base)     = h0;
            *(uint32_t*)(qh + base + 2) = h1;
            *(uint32_t*)(ql + base)     = l0;
            *(uint32_t*)(ql + base + 2) = l1;
        }
    }

    const int krow = tid >> 2, kcb = (tid & 3) * 16;
    float4 rk[4], rv[4];
    {
        const float* kp = g_qkv + (size_t)(b * SEQ + krow) * NQKV + HID + h * DHEAD + kcb;
#pragma unroll
        for (int f = 0; f < 4; f++) {
            rk[f] = *(const float4*)(kp + 4 * f);
            rv[f] = *(const float4*)(kp + HID + 4 * f);
        }
    }

    float m0 = -1e30f, m1 = -1e30f, l0 = 0.f, l1 = 0.f;
    float o[8][4];
#pragma unroll
    for (int j = 0; j < 8; j++)
#pragma unroll
        for (int r = 0; r < 4; r++) o[j][r] = 0.f;

    const int rowoff = ((lane >> 3) & 1) * 8 + (lane & 7);
    const int coloff = (lane >> 4) * 8;
    const int rA = q0 + wid * 16 + (lane >> 2);

    for (int kt = 0; kt < 16; kt++) {
        __syncthreads();
#pragma unroll
        for (int f = 0; f < 4; f++) {
            int c = kcb + 4 * f;
            uint32_t h0, lo0, h1, lo1;
            splitpack(rk[f].x, rk[f].y, h0, lo0);
            splitpack(rk[f].z, rk[f].w, h1, lo1);
            int base = krow * SQ + c;
            *(uint32_t*)(kh + base)     = h0;
            *(uint32_t*)(kh + base + 2) = h1;
            *(uint32_t*)(kl + base)     = lo0;
            *(uint32_t*)(kl + base + 2) = lo1;
            float vv[4] = {rv[f].x, rv[f].y, rv[f].z, rv[f].w};
#pragma unroll
            for (int e = 0; e < 4; e++) {
                __nv_bfloat16 hb = __float2bfloat16(vv[e]);
                __nv_bfloat16 lb = __float2bfloat16(vv[e] - __bfloat162float(hb));
                vh[(c + e) * SQ + krow] = hb;
                vl[(c + e) * SQ + krow] = lb;
            }
        }
        __syncthreads();
        if (kt < 15) {
            const float* kp = g_qkv + (size_t)(b * SEQ + (kt + 1) * KTILE + krow) * NQKV
                              + HID + h * DHEAD + kcb;
#pragma unroll
            for (int f = 0; f < 4; f++) {
                rk[f] = *(const float4*)(kp + 4 * f);
                rv[f] = *(const float4*)(kp + HID + 4 * f);
            }
        }
        float2 mk0[8], mk1[8];
        {
            const float* mr0 = wm + ((size_t)b * SEQ + rA) * SEQ + kt * KTILE + (lane & 3) * 2;
            const float* mr1 = mr0 + 8 * SEQ;
#pragma unroll
            for (int j = 0; j < 8; j++) {
                mk0[j] = *(const float2*)(mr0 + 8 * j);
                mk1[j] = *(const float2*)(mr1 + 8 * j);
            }
        }

        float s[8][4];
#pragma unroll
        for (int j = 0; j < 8; j++)
#pragma unroll
            for (int r = 0; r < 4; r++) s[j][r] = 0.f;

#pragma unroll
        for (int t = 0; t < 4; t++) {
            uint32_t ah[4], al4[4];
            ldsm4(ah[0], ah[1], ah[2], ah[3],
                  sqh + ((wid * 16 + rowoff) * SQ + t * 16 + coloff) * 2);
            ldsm4(al4[0], al4[1], al4[2], al4[3],
                  sql + ((wid * 16 + rowoff) * SQ + t * 16 + coloff) * 2);
#pragma unroll
            for (int p = 0; p < 4; p++) {
                uint32_t h0, h1, h2, h3, g0, g1, g2, g3;
                uint32_t kaddr = ((p * 16 + rowoff) * SQ + t * 16 + coloff) * 2;
                ldsm4(h0, h1, h2, h3, skh + kaddr);
                ldsm4(g0, g1, g2, g3, skl + kaddr);
                uint32_t bh0[2] = {h0, h2}, bh1[2] = {h1, h3};
                uint32_t bl0[2] = {g0, g2}, bl1[2] = {g1, g3};
                mma_bf16(s[2*p],   ah,  bh0);
                mma_bf16(s[2*p],   ah,  bl0);
                mma_bf16(s[2*p],   al4, bh0);
                mma_bf16(s[2*p+1], ah,  bh1);
                mma_bf16(s[2*p+1], ah,  bl1);
                mma_bf16(s[2*p+1], al4, bh1);
            }
        }

        float lm0 = -1e30f, lm1 = -1e30f;
#pragma unroll
        for (int j = 0; j < 8; j++) {
            lm0 = fmaxf(lm0, fmaxf(s[j][0], s[j][1]));
            lm1 = fmaxf(lm1, fmaxf(s[j][2], s[j][3]));
        }
        lm0 = fmaxf(lm0, __shfl_xor_sync(0xffffffffu, lm0, 1));
        lm0 = fmaxf(lm0, __shfl_xor_sync(0xffffffffu, lm0, 2));
        lm1 = fmaxf(lm1, __shfl_xor_sync(0xffffffffu, lm1, 1));
        lm1 = fmaxf(lm1, __shfl_xor_sync(0xffffffffu, lm1, 2));
        float mn0 = fmaxf(m0, lm0), mn1 = fmaxf(m1, lm1);
        float f0 = __expf(m0 - mn0), f1 = __expf(m1 - mn1);
        m0 = mn0; m1 = mn1;
        float ls0 = 0.f, ls1 = 0.f;
#pragma unroll
        for (int j = 0; j < 8; j++) {
            float e0 = __expf(s[j][0] - mn0);
            float e1 = __expf(s[j][1] - mn0);
            float e2 = __expf(s[j][2] - mn1);
            float e3 = __expf(s[j][3] - mn1);
            ls0 += e0 + e1; ls1 += e2 + e3;
            s[j][0] = e0 * mk0[j].x;
            s[j][1] = e1 * mk0[j].y;
            s[j][2] = e2 * mk1[j].x;
            s[j][3] = e3 * mk1[j].y;
        }
        ls0 += __shfl_xor_sync(0xffffffffu, ls0, 1);
        ls0 += __shfl_xor_sync(0xffffffffu, ls0, 2);
        ls1 += __shfl_xor_sync(0xffffffffu, ls1, 1);
        ls1 += __shfl_xor_sync(0xffffffffu, ls1, 2);
        l0 = l0 * f0 + ls0;
        l1 = l1 * f1 + ls1;
#pragma unroll
        for (int j = 0; j < 8; j++) {
            o[j][0] *= f0; o[j][1] *= f0;
            o[j][2] *= f1; o[j][3] *= f1;
        }

#pragma unroll
        for (int u = 0; u < 4; u++) {
            uint32_t pah[4], pal[4];
            splitpack(s[2*u][0],   s[2*u][1],   pah[0], pal[0]);
            splitpack(s[2*u][2],   s[2*u][3],   pah[1], pal[1]);
            splitpack(s[2*u+1][0], s[2*u+1][1], pah[2], pal[2]);
            splitpack(s[2*u+1][2], s[2*u+1][3], pah[3], pal[3]);
#pragma unroll
            for (int p = 0; p < 4; p++) {
                uint32_t h0, h1, h2, h3, g0, g1, g2, g3;
                uint32_t vaddr = ((p * 16 + rowoff) * SQ + u * 16 + coloff) * 2;
                ldsm4(h0, h1, h2, h3, svh + vaddr);
                ldsm4(g0, g1, g2, g3, svl + vaddr);
                uint32_t bh0[2] = {h0, h2}, bh1[2] = {h1, h3};
                uint32_t bl0[2] = {g0, g2}, bl1[2] = {g1, g3};
                mma_bf16(o[2*p],   pah, bh0);
                mma_bf16(o[2*p],   pah, bl0);
                mma_bf16(o[2*p],   pal, bh0);
                mma_bf16(o[2*p+1], pah, bh1);
                mma_bf16(o[2*p+1], pah, bl1);
                mma_bf16(o[2*p+1], pal, bh1);
            }
        }
    }

    float inv0 = 1.0f / l0, inv1 = 1.0f / l1;
    float* c0 = g_ctx + ((size_t)(b * SEQ) + rA) * HID + h * DHEAD + (lane & 3) * 2;
    float* c1 = c0 + 8 * HID;
#pragma unroll
    for (int j = 0; j < 8; j++) {
        *(float2*)(c0 + 8 * j) = make_float2(o[j][0] * inv0, o[j][1] * inv0);
        *(float2*)(c1 + 8 * j) = make_float2(o[j][2] * inv1, o[j][3] * inv1);
    }
}

// ---------------- fused residual-add + LayerNorm (two-pass) -----------------
template<bool HALF>
__device__ __forceinline__ void addln_body(const float* __restrict__ A, int sA,
                                           const float* __restrict__ Bv, int sB,
                                           const float* __restrict__ g,
                                           const float* __restrict__ be,
                                           float* __restrict__ out,
                                           __half* __restrict__ oh)
{
    const int row = blockIdx.x;
    const int tid = threadIdx.x;
    __shared__ float red[8];
    __shared__ float s_mu, s_rs;

    float4 v4 = make_float4(0.f, 0.f, 0.f, 0.f);
    float ls = 0.f;
    if (tid < 192) {
        float4 av = ((const float4*)(A  + (size_t)row * sA))[tid];
        float4 bv = ((const float4*)(Bv + (size_t)row * sB))[tid];
        v4 = make_float4(av.x + bv.x, av.y + bv.y, av.z + bv.z, av.w + bv.w);
        ls = v4.x + v4.y + v4.z + v4.w;
    }
    int lane = tid & 31, wid = tid >> 5;
#pragma unroll
    for (int o = 16; o; o >>= 1) ls += __shfl_xor_sync(0xffffffffu, ls, o);
    if (lane == 0) red[wid] = ls;
    __syncthreads();
    if (tid == 0) {
        float t = 0.f;
#pragma unroll
        for (int i = 0; i < 8; i++) t += red[i];
        s_mu = t * (1.0f / HID);
    }
    __syncthreads();
    float mu = s_mu;

    float4 dx = make_float4(v4.x - mu, v4.y - mu, v4.z - mu, v4.w - mu);
    float lv = 0.f;
    if (tid < 192)
        lv = dx.x * dx.x + dx.y * dx.y + dx.z * dx.z + dx.w * dx.w;
#pragma unroll
    for (int o = 16; o; o >>= 1) lv += __shfl_xor_sync(0xffffffffu, lv, o);
    __syncthreads();
    if (lane == 0) red[wid] = lv;
    __syncthreads();
    if (tid == 0) {
        float t = 0.f;
#pragma unroll
        for (int i = 0; i < 8; i++) t += red[i];
        s_rs = rsqrtf(t * (1.0f / HID) + 1e-5f);
    }
    __syncthreads();
    float rs = s_rs;

    if (tid < 192) {
        float4 g4  = ((const float4*)g)[tid];
        float4 be4 = ((const float4*)be)[tid];
        float4 o = make_float4(dx.x * rs * g4.x + be4.x,
                               dx.y * rs * g4.y + be4.y,
                               dx.z * rs * g4.z + be4.z,
                               dx.w * rs * g4.w + be4.w);
        ((float4*)(out + (size_t)row * HID))[tid] = o;
        if (HALF) {
            __half2 p0 = __floats2half2_rn(o.x, o.y);
            __half2 p1 = __floats2half2_rn(o.z, o.w);
            ((__half2*)(oh + (size_t)row * HID))[2*tid]   = p0;
            ((__half2*)(oh + (size_t)row * HID))[2*tid+1] = p1;
        }
    }
}

__global__ void __launch_bounds__(256)
ln1_kernel(const float* __restrict__ g, const float* __restrict__ be)
{
    addln_body<true>(g_ctx, HID, g_qkv, NQKV, g, be, g_x, g_ah);
}

__global__ void __launch_bounds__(256)
ln2_kernel(const float* __restrict__ g, const float* __restrict__ be,
           float* __restrict__ out)
{
    addln_body<false>(g_x, HID, g_ff2, HID, g, be, out, nullptr);
}

// ---------------- launch -----------------------------------------------------
extern "C" void kernel_launch(void* const* d_in, const int* in_sizes, int n_in,
                              void* d_out, int out_size)
{
    const float* x1  = (const float*)d_in[0];
    const float* wm  = (const float*)d_in[1];
    const float* Wq  = (const float*)d_in[2];
    const float* bq  = (const float*)d_in[3];
    const float* Wk  = (const float*)d_in[4];
    const float* bk  = (const float*)d_in[5];
    const float* Wv  = (const float*)d_in[6];
    const float* bv  = (const float*)d_in[7];
    const float* g1  = (const float*)d_in[8];
    const float* be1 = (const float*)d_in[9];
    const float* g2  = (const float*)d_in[10];
    const float* be2 = (const float*)d_in[11];
    const float* W1  = (const float*)d_in[12];
    const float* b1  = (const float*)d_in[13];
    const float* W2  = (const float*)d_in[14];
    const float* b2  = (const float*)d_in[15];
    float* out = (float*)d_out;

    void *p_ah, *p_fh, *p_w1h, *p_w2h;
    void *p_qkv, *p_bqkv, *p_ff2, *p_wqh;
    cudaGetSymbolAddress(&p_ah, g_ah);
    cudaGetSymbolAddress(&p_fh, g_fh);
    cudaGetSymbolAddress(&p_w1h, g_w1h);
    cudaGetSymbolAddress(&p_w2h, g_w2h);
    cudaGetSymbolAddress(&p_qkv, g_qkv);   cudaGetSymbolAddress(&p_bqkv, g_bqkv);
    cudaGetSymbolAddress(&p_ff2, g_ff2);
    cudaGetSymbolAddress(&p_wqh, g_wqkvh);

    __half* ah  = (__half*)p_ah;
    __half* fh  = (__half*)p_fh;
    __half* wqh = (__half*)p_wqh;
    __half* w1h = (__half*)p_w1h;
    __half* w2h = (__half*)p_w2h;
    float* qkv  = (float*)p_qkv;
    float* bqkv = (float*)p_bqkv;
    float* ff2  = (float*)p_ff2;

    cudaFuncSetAttribute(attn_mma,
                         cudaFuncAttributeMaxDynamicSharedMemorySize, ATTN_SMEM);
    cudaFuncSetAttribute(gemm_mma,
                         cudaFuncAttributeMaxDynamicSharedMemorySize, GEMM_SMEM);

    dim3 tb(32, 8);

    // weight prep (fp16 convert + transpose)
    prep_bias<<<3, 256>>>(bq, bk, bv);
    transpose_qkv<<<dim3(HID/32, HID/32, 3), tb>>>(Wq, Wk, Wv);
    transpose_conv<<<dim3(FF/32,  HID/32), tb>>>(W1, w1h, HID, FF);
    transpose_conv<<<dim3(HID/32, FF/32),  tb>>>(W2, w2h, FF, HID);

    // x1 -> fp16
    convert_half<<<2048, 256>>>(x1, ah, ROWS * HID / 4);

    // fused QKV GEMM (fp16 single-pass)
    gemm_mma<<<dim3(NQKV/128, ROWS/128), 256, GEMM_SMEM>>>(
        ah, wqh, bqkv, qkv, nullptr, NQKV, HID, 0, 0);

    // tensor-core flash attention with post-softmax mask (bf16 3-pass, exact-ish)
    attn_mma<<<dim3(SEQ/QT, NHEAD, BATCH), 256, ATTN_SMEM>>>(wm);

    // x = LN(ctx + q_mixed), fused fp16 emit into g_ah
    ln1_kernel<<<ROWS, 256>>>(g1, be1);

    // ff1 = relu(x @ W1 + b1) -> fp16 into g_fh
    gemm_mma<<<dim3(FF/128, ROWS/128), 256, GEMM_SMEM>>>(
        ah, w1h, b1, nullptr, fh, FF, HID, 1, 1);

    // ff2 = ff1 @ W2 + b2
    gemm_mma<<<dim3(HID/128, ROWS/128), 256, GEMM_SMEM>>>(
        fh, w2h, b2, ff2, nullptr, HID, FF, 0, 0);

    // out = LN(x + ff2)
    ln2_kernel<<<ROWS, 256>>>(g2, be2, out);
}

// round 10
// speedup vs baseline: 5.8954x; 1.4786x over previous
#include <cuda_runtime.h>
#include <cuda_bf16.h>
#include <cuda_fp16.h>
#include <cstdint>
#include <math.h>

// Problem constants
#define BATCH 8
#define SEQ   1024
#define HID   768
#define NHEAD 12
#define DHEAD 64
#define ROWS  (BATCH*SEQ)          // 8192
#define FF    (2*HID)              // 1536
#define NQKV  (3*HID)              // 2304

// ---------------- scratch (device globals; no allocations allowed) ----------
__device__ float g_ctx[ROWS*HID];
__device__ float g_x  [ROWS*HID];
__device__ float g_ff2[ROWS*HID];
__device__ float g_bqkv[NQKV];
__device__ float g_qf32[ROWS*HID];     // q_mixed fp32 (LN1 residual)

__device__ __half g_qkv16[ROWS*NQKV];  // q(pre-scaled 1/8) | k | v, fp16
__device__ __half g_ah[ROWS*HID];      // fp16 activations (A inputs)
__device__ __half g_fh[ROWS*FF];       // fp16 ff1 output (A for ff2)
__device__ __half g_wqkvh[NQKV*HID];   // W^T fp16, rows = N, K-major
__device__ __half g_w1h[FF*HID];
__device__ __half g_w2h[HID*FF];

// ---------------- PTX helpers (sm_80-era only; no 'a'-features) -------------
__device__ __forceinline__ uint32_t smem_u32(const void* p) {
    uint32_t a;
    asm("{ .reg .u64 t; cvta.to.shared.u64 t, %1; cvt.u32.u64 %0, t; }"
        : "=r"(a) : "l"(p));
    return a;
}

__device__ __forceinline__ void cp16(uint32_t dst, const void* src) {
    asm volatile("cp.async.cg.shared.global [%0], [%1], 16;"
                 :: "r"(dst), "l"(src));
}
#define CP_COMMIT() asm volatile("cp.async.commit_group;" ::: "memory")
#define CP_WAIT(n)  asm volatile("cp.async.wait_group %0;" :: "n"(n) : "memory")

__device__ __forceinline__ void ldsm4(uint32_t& r0, uint32_t& r1,
                                      uint32_t& r2, uint32_t& r3, uint32_t addr) {
    asm volatile("ldmatrix.sync.aligned.m8n8.x4.shared.b16 {%0,%1,%2,%3}, [%4];"
                 : "=r"(r0), "=r"(r1), "=r"(r2), "=r"(r3) : "r"(addr));
}

// fp16 mma
__device__ __forceinline__ void mma_f16(float* c, const uint32_t* a, const uint32_t* b) {
    asm volatile("mma.sync.aligned.m16n8k16.row.col.f32.f16.f16.f32 "
                 "{%0,%1,%2,%3}, {%4,%5,%6,%7}, {%8,%9}, {%0,%1,%2,%3};"
                 : "+f"(c[0]), "+f"(c[1]), "+f"(c[2]), "+f"(c[3])
                 : "r"(a[0]), "r"(a[1]), "r"(a[2]), "r"(a[3]),
                   "r"(b[0]), "r"(b[1]));
}

__device__ __forceinline__ uint32_t packh(float x, float y) {
    __half2 p = __floats2half2_rn(x, y);
    return *(uint32_t*)&p;
}

// ---------------- prep kernels ----------------------------------------------
__global__ void prep_bias(const float* __restrict__ bq, const float* __restrict__ bk,
                          const float* __restrict__ bv) {
    int i = blockIdx.x * blockDim.x + threadIdx.x;
    if (i < HID) {
        g_bqkv[i]         = bq[i];
        g_bqkv[i + HID]   = bk[i];
        g_bqkv[i + 2*HID] = bv[i];
    }
}

// W[K,N] fp32 -> out[N,K] fp16 (transpose + convert)
__device__ __forceinline__ void tsp_body(const float* __restrict__ W,
                                         __half* __restrict__ oh,
                                         int K, int N) {
    __shared__ float t[32][33];
    const int tx = threadIdx.x, ty = threadIdx.y;
    const int n0 = blockIdx.x * 32, k0 = blockIdx.y * 32;
#pragma unroll
    for (int i = 0; i < 4; i++)
        t[ty + 8*i][tx] = W[(size_t)(k0 + ty + 8*i) * N + n0 + tx];
    __syncthreads();
#pragma unroll
    for (int i = 0; i < 4; i++) {
        float v = t[tx][ty + 8*i];
        oh[(size_t)(n0 + ty + 8*i) * K + k0 + tx] = __float2half_rn(v);
    }
}

__global__ void __launch_bounds__(256)
transpose_conv(const float* __restrict__ W, __half* __restrict__ oh, int K, int N) {
    tsp_body(W, oh, K, N);
}

__global__ void __launch_bounds__(256)
transpose_qkv(const float* __restrict__ Wq, const float* __restrict__ Wk,
              const float* __restrict__ Wv) {
    const float* W = (blockIdx.z == 0) ? Wq : (blockIdx.z == 1) ? Wk : Wv;
    tsp_body(W, g_wqkvh + (size_t)blockIdx.z * HID * HID, HID, HID);
}

// fp32 -> fp16 elementwise
__global__ void __launch_bounds__(256)
convert_half(const float* __restrict__ in, __half* __restrict__ oh, int n4) {
    for (int i = blockIdx.x * blockDim.x + threadIdx.x; i < n4;
         i += gridDim.x * blockDim.x) {
        float4 a = ((const float4*)in)[i];
        ((__half2*)oh)[2*i]   = __floats2half2_rn(a.x, a.y);
        ((__half2*)oh)[2*i+1] = __floats2half2_rn(a.z, a.w);
    }
}

// ---------------- fp16 single-pass mma.sync GEMM (4-stage cp.async ring) -----
// C = A * B^T + bias. 128x128 tile/CTA, K-step 32.
// mode 0: fp32 out (Cf, stride N). mode 1: fp16 out (Ch, stride N).
// mode 2 (QKV): fp16 out to Ch stride N (q cols scaled 1/8) + fp32 q to Cf stride HID.
#define ASTR    40
#define STGB    (128 * ASTR * 2)
#define STAGES  4
#define GEMM_SMEM (STAGES * 2 * STGB)        // 81920 B

__global__ void __launch_bounds__(256, 2)
gemm_mma(const __half* __restrict__ A, const __half* __restrict__ B,
         const float* __restrict__ bias,
         float* __restrict__ Cf, __half* __restrict__ Ch,
         int N, int K, int relu, int mode)
{
    extern __shared__ __align__(16) char dsm[];
    __half* smA = (__half*)dsm;
    __half* smB = (__half*)(dsm + STAGES * STGB);

    const int tid  = threadIdx.x;
    const int wid  = tid >> 5, lane = tid & 31;
    const int warp_m = wid >> 2;
    const int warp_n = wid & 3;
    const int m0 = blockIdx.y << 7;
    const int n0 = blockIdx.x << 7;

    const uint32_t sA = smem_u32(smA);
    const uint32_t sB = smem_u32(smB);

    const int lrow  = tid >> 1;
    const int lcolh = (tid & 1) * 16;

    const int kb = K >> 5;

    float c[4][4][4];
#pragma unroll
    for (int i = 0; i < 4; i++)
#pragma unroll
        for (int j = 0; j < 4; j++)
#pragma unroll
            for (int r = 0; r < 4; r++) c[i][j][r] = 0.f;

    const int rowoff = ((lane >> 3) & 1) * 8 + (lane & 7);
    const int coloff = ((lane >> 4) & 1) * 8;

    auto issue = [&](int blk) {
        if (blk < kb) {
            const __half* ga = A + (size_t)(m0 + lrow) * K + blk * 32 + lcolh;
            const __half* gb = B + (size_t)(n0 + lrow) * K + blk * 32 + lcolh;
            int st = blk & (STAGES - 1);
            uint32_t da = sA + st * STGB + (lrow * ASTR + lcolh) * 2;
            uint32_t db = sB + st * STGB + (lrow * ASTR + lcolh) * 2;
            cp16(da,      ga);
            cp16(da + 16, ga + 8);
            cp16(db,      gb);
            cp16(db + 16, gb + 8);
        }
        CP_COMMIT();
    };

    issue(0); issue(1); issue(2);

    for (int blk = 0; blk < kb; blk++) {
        CP_WAIT(2);
        __syncthreads();

        const int stage = blk & (STAGES - 1);
        const uint32_t a0 = sA + stage * STGB;
        const uint32_t b0 = sB + stage * STGB;
#pragma unroll
        for (int kh = 0; kh < 2; kh++) {
            uint32_t af[4][4];
#pragma unroll
            for (int t = 0; t < 4; t++)
                ldsm4(af[t][0], af[t][1], af[t][2], af[t][3],
                      a0 + ((warp_m * 64 + t * 16 + rowoff) * ASTR + kh * 16 + coloff) * 2);
            uint32_t bf[4][2];
#pragma unroll
            for (int p = 0; p < 2; p++) {
                uint32_t r0, r1, r2, r3;
                ldsm4(r0, r1, r2, r3,
                      b0 + ((warp_n * 32 + p * 16 + rowoff) * ASTR + kh * 16 + coloff) * 2);
                bf[2*p][0]   = r0; bf[2*p][1]   = r2;
                bf[2*p+1][0] = r1; bf[2*p+1][1] = r3;
            }
#pragma unroll
            for (int i = 0; i < 4; i++)
#pragma unroll
                for (int j = 0; j < 4; j++)
                    mma_f16(c[i][j], af[i], bf[j]);
        }
        issue(blk + 3);
    }

    const float qsc = (mode == 2 && n0 < HID) ? 0.125f : 1.0f;
    const int   qf  = (mode == 2 && n0 < HID);

#pragma unroll
    for (int i = 0; i < 4; i++) {
#pragma unroll
        for (int j = 0; j < 4; j++) {
            int grow = m0 + warp_m * 64 + i * 16 + (lane >> 2);
            int gcol = n0 + warp_n * 32 + j * 8 + (lane & 3) * 2;
            float b0v = bias[gcol], b1v = bias[gcol + 1];
            float v0 = c[i][j][0] + b0v;
            float v1 = c[i][j][1] + b1v;
            float v2 = c[i][j][2] + b0v;
            float v3 = c[i][j][3] + b1v;
            if (relu) {
                v0 = fmaxf(v0, 0.f); v1 = fmaxf(v1, 0.f);
                v2 = fmaxf(v2, 0.f); v3 = fmaxf(v3, 0.f);
            }
            if (mode == 0) {
                *(float2*)(Cf + (size_t)grow * N + gcol)       = make_float2(v0, v1);
                *(float2*)(Cf + (size_t)(grow + 8) * N + gcol) = make_float2(v2, v3);
            } else {
                __half2 p0 = __floats2half2_rn(v0 * qsc, v1 * qsc);
                __half2 p1 = __floats2half2_rn(v2 * qsc, v3 * qsc);
                *(__half2*)(Ch + (size_t)grow * N + gcol)       = p0;
                *(__half2*)(Ch + (size_t)(grow + 8) * N + gcol) = p1;
                if (qf) {
                    *(float2*)(Cf + (size_t)grow * HID + gcol)       = make_float2(v0, v1);
                    *(float2*)(Cf + (size_t)(grow + 8) * HID + gcol) = make_float2(v2, v3);
                }
            }
        }
    }
}

// ---------------- tensor-core flash attention (fp16 single-pass) -------------
// Q pre-scaled fp16; K fp16 row-major; V fp16 stored transposed in smem.
// softmax in fp32; P packed fp16 (values in [0,1]).
#define QT 128
#define KTILE 64
#define SQ 72
#define ATTN_SMEM ((QT + 2*KTILE) * SQ * 2)    // 36864 B

__global__ void __launch_bounds__(256, 2)
attn_mma(const float* __restrict__ wm)
{
    extern __shared__ __align__(16) __half am_[];
    __half* qs = am_;                 // [row][d]
    __half* ks = qs + QT * SQ;        // [k][d]
    __half* vt = ks + KTILE * SQ;     // [d][k]

    const int tid = threadIdx.x, wid = tid >> 5, lane = tid & 31;
    const int b = blockIdx.z, h = blockIdx.y, q0 = blockIdx.x * QT;

    const uint32_t sqs = smem_u32(qs);
    const uint32_t sks = smem_u32(ks);
    const uint32_t svt = smem_u32(vt);

    // ---- stage Q (already scaled, fp16 direct copy) ----
    {
        const int row = tid >> 1, cb = (tid & 1) * 32;   // 32 halves
        const __half* src = g_qkv16 + (size_t)(b * SEQ + q0 + row) * NQKV + h * DHEAD + cb;
#pragma unroll
        for (int f = 0; f < 4; f++)
            *(uint4*)(qs + row * SQ + cb + 8 * f) = *(const uint4*)(src + 8 * f);
    }

    // ---- K/V register prefetch (fp16) ----
    const int krow = tid >> 2, kcb = (tid & 3) * 16;     // 16 halves each
    uint4 rk[2], rv[2];
    {
        const __half* kp = g_qkv16 + (size_t)(b * SEQ + krow) * NQKV + HID + h * DHEAD + kcb;
        rk[0] = *(const uint4*)kp;      rk[1] = *(const uint4*)(kp + 8);
        rv[0] = *(const uint4*)(kp + HID);  rv[1] = *(const uint4*)(kp + HID + 8);
    }

    float m0 = -1e30f, m1 = -1e30f, l0 = 0.f, l1 = 0.f;
    float o[8][4];
#pragma unroll
    for (int j = 0; j < 8; j++)
#pragma unroll
        for (int r = 0; r < 4; r++) o[j][r] = 0.f;

    const int rowoff = ((lane >> 3) & 1) * 8 + (lane & 7);
    const int coloff = (lane >> 4) * 8;
    const int rA = q0 + wid * 16 + (lane >> 2);

    for (int kt = 0; kt < 16; kt++) {
        __syncthreads();
        // K direct copy; V transposed store
        *(uint4*)(ks + krow * SQ + kcb)     = rk[0];
        *(uint4*)(ks + krow * SQ + kcb + 8) = rk[1];
        {
            __half vv[16];
            *(uint4*)vv       = rv[0];
            *(uint4*)(vv + 8) = rv[1];
#pragma unroll
            for (int e = 0; e < 16; e++)
                vt[(kcb + e) * SQ + krow] = vv[e];
        }
        __syncthreads();
        if (kt < 15) {
            const __half* kp = g_qkv16 + (size_t)(b * SEQ + (kt + 1) * KTILE + krow) * NQKV
                               + HID + h * DHEAD + kcb;
            rk[0] = *(const uint4*)kp;      rk[1] = *(const uint4*)(kp + 8);
            rv[0] = *(const uint4*)(kp + HID);  rv[1] = *(const uint4*)(kp + HID + 8);
        }
        float2 mk0[8], mk1[8];
        {
            const float* mr0 = wm + ((size_t)b * SEQ + rA) * SEQ + kt * KTILE + (lane & 3) * 2;
            const float* mr1 = mr0 + 8 * SEQ;
#pragma unroll
            for (int j = 0; j < 8; j++) {
                mk0[j] = *(const float2*)(mr0 + 8 * j);
                mk1[j] = *(const float2*)(mr1 + 8 * j);
            }
        }

        // ---- QK^T (single-pass fp16) ----
        float s[8][4];
#pragma unroll
        for (int j = 0; j < 8; j++)
#pragma unroll
            for (int r = 0; r < 4; r++) s[j][r] = 0.f;

#pragma unroll
        for (int t = 0; t < 4; t++) {
            uint32_t af[4];
            ldsm4(af[0], af[1], af[2], af[3],
                  sqs + ((wid * 16 + rowoff) * SQ + t * 16 + coloff) * 2);
#pragma unroll
            for (int p = 0; p < 4; p++) {
                uint32_t r0, r1, r2, r3;
                ldsm4(r0, r1, r2, r3,
                      sks + ((p * 16 + rowoff) * SQ + t * 16 + coloff) * 2);
                uint32_t b0[2] = {r0, r2}, b1[2] = {r1, r3};
                mma_f16(s[2*p],   af, b0);
                mma_f16(s[2*p+1], af, b1);
            }
        }

        // ---- online softmax (denominator UNmasked), then mask ----
        float lm0 = -1e30f, lm1 = -1e30f;
#pragma unroll
        for (int j = 0; j < 8; j++) {
            lm0 = fmaxf(lm0, fmaxf(s[j][0], s[j][1]));
            lm1 = fmaxf(lm1, fmaxf(s[j][2], s[j][3]));
        }
        lm0 = fmaxf(lm0, __shfl_xor_sync(0xffffffffu, lm0, 1));
        lm0 = fmaxf(lm0, __shfl_xor_sync(0xffffffffu, lm0, 2));
        lm1 = fmaxf(lm1, __shfl_xor_sync(0xffffffffu, lm1, 1));
        lm1 = fmaxf(lm1, __shfl_xor_sync(0xffffffffu, lm1, 2));
        float mn0 = fmaxf(m0, lm0), mn1 = fmaxf(m1, lm1);
        float f0 = __expf(m0 - mn0), f1 = __expf(m1 - mn1);
        m0 = mn0; m1 = mn1;
        float ls0 = 0.f, ls1 = 0.f;
#pragma unroll
        for (int j = 0; j < 8; j++) {
            float e0 = __expf(s[j][0] - mn0);
            float e1 = __expf(s[j][1] - mn0);
            float e2 = __expf(s[j][2] - mn1);
            float e3 = __expf(s[j][3] - mn1);
            ls0 += e0 + e1; ls1 += e2 + e3;
            s[j][0] = e0 * mk0[j].x;
            s[j][1] = e1 * mk0[j].y;
            s[j][2] = e2 * mk1[j].x;
            s[j][3] = e3 * mk1[j].y;
        }
        ls0 += __shfl_xor_sync(0xffffffffu, ls0, 1);
        ls0 += __shfl_xor_sync(0xffffffffu, ls0, 2);
        ls1 += __shfl_xor_sync(0xffffffffu, ls1, 1);
        ls1 += __shfl_xor_sync(0xffffffffu, ls1, 2);
        l0 = l0 * f0 + ls0;
        l1 = l1 * f1 + ls1;
#pragma unroll
        for (int j = 0; j < 8; j++) {
            o[j][0] *= f0; o[j][1] *= f0;
            o[j][2] *= f1; o[j][3] *= f1;
        }

        // ---- PV (single-pass fp16) ----
#pragma unroll
        for (int u = 0; u < 4; u++) {
            uint32_t pa[4];
            pa[0] = packh(s[2*u][0],   s[2*u][1]);
            pa[1] = packh(s[2*u][2],   s[2*u][3]);
            pa[2] = packh(s[2*u+1][0], s[2*u+1][1]);
            pa[3] = packh(s[2*u+1][2], s[2*u+1][3]);
#pragma unroll
            for (int p = 0; p < 4; p++) {
                uint32_t r0, r1, r2, r3;
                ldsm4(r0, r1, r2, r3,
                      svt + ((p * 16 + rowoff) * SQ + u * 16 + coloff) * 2);
                uint32_t b0[2] = {r0, r2}, b1[2] = {r1, r3};
                mma_f16(o[2*p],   pa, b0);
                mma_f16(o[2*p+1], pa, b1);
            }
        }
    }

    float inv0 = 1.0f / l0, inv1 = 1.0f / l1;
    float* c0 = g_ctx + ((size_t)(b * SEQ) + rA) * HID + h * DHEAD + (lane & 3) * 2;
    float* c1 = c0 + 8 * HID;
#pragma unroll
    for (int j = 0; j < 8; j++) {
        *(float2*)(c0 + 8 * j) = make_float2(o[j][0] * inv0, o[j][1] * inv0);
        *(float2*)(c1 + 8 * j) = make_float2(o[j][2] * inv1, o[j][3] * inv1);
    }
}

// ---------------- fused residual-add + LayerNorm (two-pass) -----------------
template<bool HALF>
__device__ __forceinline__ void addln_body(const float* __restrict__ A, int sA,
                                           const float* __restrict__ Bv, int sB,
                                           const float* __restrict__ g,
                                           const float* __restrict__ be,
                                           float* __restrict__ out,
                                           __half* __restrict__ oh)
{
    const int row = blockIdx.x;
    const int tid = threadIdx.x;
    __shared__ float red[8];
    __shared__ float s_mu, s_rs;

    float4 v4 = make_float4(0.f, 0.f, 0.f, 0.f);
    float ls = 0.f;
    if (tid < 192) {
        float4 av = ((const float4*)(A  + (size_t)row * sA))[tid];
        float4 bv = ((const float4*)(Bv + (size_t)row * sB))[tid];
        v4 = make_float4(av.x + bv.x, av.y + bv.y, av.z + bv.z, av.w + bv.w);
        ls = v4.x + v4.y + v4.z + v4.w;
    }
    int lane = tid & 31, wid = tid >> 5;
#pragma unroll
    for (int o = 16; o; o >>= 1) ls += __shfl_xor_sync(0xffffffffu, ls, o);
    if (lane == 0) red[wid] = ls;
    __syncthreads();
    if (tid == 0) {
        float t = 0.f;
#pragma unroll
        for (int i = 0; i < 8; i++) t += red[i];
        s_mu = t * (1.0f / HID);
    }
    __syncthreads();
    float mu = s_mu;

    float4 dx = make_float4(v4.x - mu, v4.y - mu, v4.z - mu, v4.w - mu);
    float lv = 0.f;
    if (tid < 192)
        lv = dx.x * dx.x + dx.y * dx.y + dx.z * dx.z + dx.w * dx.w;
#pragma unroll
    for (int o = 16; o; o >>= 1) lv += __shfl_xor_sync(0xffffffffu, lv, o);
    __syncthreads();
    if (lane == 0) red[wid] = lv;
    __syncthreads();
    if (tid == 0) {
        float t = 0.f;
#pragma unroll
        for (int i = 0; i < 8; i++) t += red[i];
        s_rs = rsqrtf(t * (1.0f / HID) + 1e-5f);
    }
    __syncthreads();
    float rs = s_rs;

    if (tid < 192) {
        float4 g4  = ((const float4*)g)[tid];
        float4 be4 = ((const float4*)be)[tid];
        float4 o = make_float4(dx.x * rs * g4.x + be4.x,
                               dx.y * rs * g4.y + be4.y,
                               dx.z * rs * g4.z + be4.z,
                               dx.w * rs * g4.w + be4.w);
        ((float4*)(out + (size_t)row * HID))[tid] = o;
        if (HALF) {
            ((__half2*)(oh + (size_t)row * HID))[2*tid]   = __floats2half2_rn(o.x, o.y);
            ((__half2*)(oh + (size_t)row * HID))[2*tid+1] = __floats2half2_rn(o.z, o.w);
        }
    }
}

__global__ void __launch_bounds__(256)
ln1_kernel(const float* __restrict__ g, const float* __restrict__ be)
{
    addln_body<true>(g_ctx, HID, g_qf32, HID, g, be, g_x, g_ah);
}

__global__ void __launch_bounds__(256)
ln2_kernel(const float* __restrict__ g, const float* __restrict__ be,
           float* __restrict__ out)
{
    addln_body<false>(g_x, HID, g_ff2, HID, g, be, out, nullptr);
}

// ---------------- launch -----------------------------------------------------
extern "C" void kernel_launch(void* const* d_in, const int* in_sizes, int n_in,
                              void* d_out, int out_size)
{
    const float* x1  = (const float*)d_in[0];
    const float* wm  = (const float*)d_in[1];
    const float* Wq  = (const float*)d_in[2];
    const float* bq  = (const float*)d_in[3];
    const float* Wk  = (const float*)d_in[4];
    const float* bk  = (const float*)d_in[5];
    const float* Wv  = (const float*)d_in[6];
    const float* bv  = (const float*)d_in[7];
    const float* g1  = (const float*)d_in[8];
    const float* be1 = (const float*)d_in[9];
    const float* g2  = (const float*)d_in[10];
    const float* be2 = (const float*)d_in[11];
    const float* W1  = (const float*)d_in[12];
    const float* b1  = (const float*)d_in[13];
    const float* W2  = (const float*)d_in[14];
    const float* b2  = (const float*)d_in[15];
    float* out = (float*)d_out;

    void *p_ah, *p_fh, *p_w1h, *p_w2h;
    void *p_qkv16, *p_qf32, *p_bqkv, *p_ff2, *p_wqh;
    cudaGetSymbolAddress(&p_ah, g_ah);
    cudaGetSymbolAddress(&p_fh, g_fh);
    cudaGetSymbolAddress(&p_w1h, g_w1h);
    cudaGetSymbolAddress(&p_w2h, g_w2h);
    cudaGetSymbolAddress(&p_qkv16, g_qkv16);
    cudaGetSymbolAddress(&p_qf32, g_qf32);
    cudaGetSymbolAddress(&p_bqkv, g_bqkv);
    cudaGetSymbolAddress(&p_ff2, g_ff2);
    cudaGetSymbolAddress(&p_wqh, g_wqkvh);

    __half* ah    = (__half*)p_ah;
    __half* fh    = (__half*)p_fh;
    __half* wqh   = (__half*)p_wqh;
    __half* w1h   = (__half*)p_w1h;
    __half* w2h   = (__half*)p_w2h;
    __half* qkv16 = (__half*)p_qkv16;
    float* qf32   = (float*)p_qf32;
    float* bqkv   = (float*)p_bqkv;
    float* ff2    = (float*)p_ff2;

    cudaFuncSetAttribute(attn_mma,
                         cudaFuncAttributeMaxDynamicSharedMemorySize, ATTN_SMEM);
    cudaFuncSetAttribute(gemm_mma,
                         cudaFuncAttributeMaxDynamicSharedMemorySize, GEMM_SMEM);

    dim3 tb(32, 8);

    // weight prep
    prep_bias<<<3, 256>>>(bq, bk, bv);
    transpose_qkv<<<dim3(HID/32, HID/32, 3), tb>>>(Wq, Wk, Wv);
    transpose_conv<<<dim3(FF/32,  HID/32), tb>>>(W1, w1h, HID, FF);
    transpose_conv<<<dim3(HID/32, FF/32),  tb>>>(W2, w2h, FF, HID);

    // x1 -> fp16
    convert_half<<<2048, 256>>>(x1, ah, ROWS * HID / 4);

    // fused QKV GEMM: fp16 out (q pre-scaled) + fp32 q for residual
    gemm_mma<<<dim3(NQKV/128, ROWS/128), 256, GEMM_SMEM>>>(
        ah, wqh, bqkv, qf32, qkv16, NQKV, HID, 0, 2);

    // fp16 flash attention with post-softmax mask
    attn_mma<<<dim3(SEQ/QT, NHEAD, BATCH), 256, ATTN_SMEM>>>(wm);

    // x = LN(ctx + q_mixed), fused fp16 emit into g_ah
    ln1_kernel<<<ROWS, 256>>>(g1, be1);

    // ff1 = relu(x @ W1 + b1) -> fp16
    gemm_mma<<<dim3(FF/128, ROWS/128), 256, GEMM_SMEM>>>(
        ah, w1h, b1, nullptr, fh, FF, HID, 1, 1);

    // ff2 = ff1 @ W2 + b2 -> fp32
    gemm_mma<<<dim3(HID/128, ROWS/128), 256, GEMM_SMEM>>>(
        fh, w2h, b2, ff2, nullptr, HID, FF, 0, 0);

    // out = LN(x + ff2)
    ln2_kernel<<<ROWS, 256>>>(g2, be2, out);
}